// round 3
// baseline (speedup 1.0000x reference)
#include <cuda_runtime.h>
#include <cuda_bf16.h>
#include <cstdint>

// Problem constants
#define BB   4
#define CC   256
#define CQ   32
#define HH   128
#define WW   128
#define NH   4
#define HW   (HH*WW)          // 16384
#define P    HW
#define MROWS 384             // fused rows: 32 q + 32 k + 256 v + 64 pad

// ---------------- scratch (device globals; no allocation) ----------------
__device__ __align__(16) float g_q [BB*CQ*HW];
__device__ __align__(16) float g_k [BB*CQ*HW];
__device__ __align__(16) float g_v [BB*CC*HW];
__device__ __align__(16) float g_qT[BB*CQ*HW];
__device__ __align__(16) float g_kT[BB*CQ*HW];
__device__ __align__(16) float g_vT[BB*CC*HW];
__device__ __align__(16) float g_oh[BB*CC*HW];
__device__ __align__(16) __nv_bfloat16 g_Whi[MROWS*CC];
__device__ __align__(16) __nv_bfloat16 g_Wlo[MROWS*CC];
__device__ float g_ball[MROWS];

// ---------------- mma.sync helper (HMMA, supported on compute_103) ----------------
__device__ __forceinline__ void mma_bf16(float d[4], const uint32_t a[4], const uint32_t b[2]) {
    asm volatile(
        "mma.sync.aligned.m16n8k16.row.col.f32.bf16.bf16.f32 "
        "{%0,%1,%2,%3}, {%4,%5,%6,%7}, {%8,%9}, {%0,%1,%2,%3};"
        : "+f"(d[0]), "+f"(d[1]), "+f"(d[2]), "+f"(d[3])
        : "r"(a[0]), "r"(a[1]), "r"(a[2]), "r"(a[3]), "r"(b[0]), "r"(b[1]));
}

// split two floats into packed bf16 hi pair (returned) and lo pair (out param)
__device__ __forceinline__ uint32_t pack_hilo(float f0, float f1, uint32_t& lo) {
    __nv_bfloat16 h0 = __float2bfloat16(f0), h1 = __float2bfloat16(f1);
    float l0f = f0 - __bfloat162float(h0);
    float l1f = f1 - __bfloat162float(h1);
    __nv_bfloat16 l0 = __float2bfloat16(l0f), l1 = __float2bfloat16(l1f);
    lo = (uint32_t)__bfloat16_as_ushort(l0) | ((uint32_t)__bfloat16_as_ushort(l1) << 16);
    return (uint32_t)__bfloat16_as_ushort(h0) | ((uint32_t)__bfloat16_as_ushort(h1) << 16);
}

// ---------------- weight prep: fuse [Wq;Wk;Wv] -> bf16 hi/lo + fused bias ----------------
__global__ void prep_kernel(const float* __restrict__ Wq, const float* __restrict__ bq,
                            const float* __restrict__ Wk, const float* __restrict__ bk,
                            const float* __restrict__ Wv, const float* __restrict__ bv)
{
    int i = blockIdx.x * blockDim.x + threadIdx.x;
    if (i >= MROWS * CC) return;
    int m = i >> 8, c = i & 255;
    float w = 0.f, b = 0.f;
    if      (m < 32)  { w = Wq[m * CC + c];        b = bq[m];      }
    else if (m < 64)  { w = Wk[(m - 32) * CC + c]; b = bk[m - 32]; }
    else if (m < 320) { w = Wv[(m - 64) * CC + c]; b = bv[m - 64]; }
    __nv_bfloat16 hi = __float2bfloat16(w);
    float lo = w - __bfloat162float(hi);
    g_Whi[i] = hi;
    g_Wlo[i] = __float2bfloat16(lo);
    if (c == 0) g_ball[m] = b;
}

// ---------------- fused QKV projection on HMMA ----------------
// Y[m,p] = sum_k W[m,k] X[k,p] + bias[m].  CTA tile M=128, N=128, K chunks of 64.
#define ASTR 34                         // u32 stride (32 k-pairs + 2 pad)
#define PROJ_SMEM (4*128*ASTR*4)        // 69632 B

__device__ __forceinline__ void store_proj(int b, int mg, int p, float v0, float v1) {
    if (mg >= 320) return;
    float bv = g_ball[mg];
    float2 val = make_float2(v0 + bv, v1 + bv);
    float* dst;
    if (mg < 32)       dst = g_q + (size_t)(b*CQ + mg) * HW;
    else if (mg < 64)  dst = g_k + (size_t)(b*CQ + mg - 32) * HW;
    else               dst = g_v + (size_t)(b*CC + mg - 64) * HW;
    *(float2*)&dst[p] = val;
}

__global__ __launch_bounds__(256)
void qkv_mma_kernel(const float* __restrict__ X)
{
    extern __shared__ uint32_t sm32[];
    uint32_t* sAhi = sm32;
    uint32_t* sAlo = sm32 + 128*ASTR;
    uint32_t* sBhi = sm32 + 2*128*ASTR;
    uint32_t* sBlo = sm32 + 3*128*ASTR;

    int tid = threadIdx.x, lane = tid & 31, wid = tid >> 5;
    int wm = wid >> 2, wn = wid & 3;          // warp grid 2(m) x 4(n)
    int r = lane >> 2, tg = lane & 3;
    int p0 = blockIdx.x * 128, m0 = blockIdx.y * 128, b = blockIdx.z;
    const float* Xb = X + (size_t)b * CC * P;

    float acc[4][4][4];
#pragma unroll
    for (int mf=0; mf<4; mf++)
#pragma unroll
        for (int nf=0; nf<4; nf++)
#pragma unroll
            for (int j=0; j<4; j++) acc[mf][nf][j] = 0.f;

    for (int ck = 0; ck < 4; ck++) {
        int k0 = ck * 64;
        // W chunk (bf16 hi/lo already)
        for (int i = tid; i < 4096; i += 256) {
            int m = i >> 5, kp = i & 31;
            size_t gi = (size_t)(m0 + m) * CC + k0 + 2*kp;
            sAhi[m*ASTR + kp] = *(const uint32_t*)&g_Whi[gi];
            sAlo[m*ASTR + kp] = *(const uint32_t*)&g_Wlo[gi];
        }
        // X chunk: fp32 -> bf16 hi/lo, stored transposed [p][k]
        for (int i = tid; i < 4096; i += 256) {
            int kp = i >> 7, p = i & 127;
            float f0 = Xb[(size_t)(k0 + 2*kp    ) * P + p0 + p];
            float f1 = Xb[(size_t)(k0 + 2*kp + 1) * P + p0 + p];
            uint32_t lo, hi = pack_hilo(f0, f1, lo);
            sBhi[p*ASTR + kp] = hi;
            sBlo[p*ASTR + kp] = lo;
        }
        __syncthreads();
#pragma unroll
        for (int s = 0; s < 4; s++) {
            uint32_t ah[4][4], al[4][4], bh[4][2], bl[4][2];
#pragma unroll
            for (int mf = 0; mf < 4; mf++) {
                int row = wm*64 + mf*16 + r;
                int i0 = row*ASTR + s*8 + tg;
                int i1 = i0 + 8*ASTR;
                ah[mf][0]=sAhi[i0]; ah[mf][1]=sAhi[i1]; ah[mf][2]=sAhi[i0+4]; ah[mf][3]=sAhi[i1+4];
                al[mf][0]=sAlo[i0]; al[mf][1]=sAlo[i1]; al[mf][2]=sAlo[i0+4]; al[mf][3]=sAlo[i1+4];
            }
#pragma unroll
            for (int nf = 0; nf < 4; nf++) {
                int prow = wn*32 + nf*8 + r;
                int j = prow*ASTR + s*8 + tg;
                bh[nf][0]=sBhi[j]; bh[nf][1]=sBhi[j+4];
                bl[nf][0]=sBlo[j]; bl[nf][1]=sBlo[j+4];
            }
#pragma unroll
            for (int mf=0; mf<4; mf++)
#pragma unroll
                for (int nf=0; nf<4; nf++) {
                    mma_bf16(acc[mf][nf], ah[mf], bh[nf]);
                    mma_bf16(acc[mf][nf], ah[mf], bl[nf]);
                    mma_bf16(acc[mf][nf], al[mf], bh[nf]);
                }
        }
        __syncthreads();
    }
    // epilogue: direct float2 stores with bias + routing
#pragma unroll
    for (int mf = 0; mf < 4; mf++) {
        int mg = m0 + wm*64 + mf*16 + r;
#pragma unroll
        for (int nf = 0; nf < 4; nf++) {
            int col = p0 + wn*32 + nf*8 + 2*tg;
            store_proj(b, mg,     col, acc[mf][nf][0], acc[mf][nf][1]);
            store_proj(b, mg + 8, col, acc[mf][nf][2], acc[mf][nf][3]);
        }
    }
}

// ---------------- per-plane 128x128 transpose ----------------
__global__ __launch_bounds__(256)
void transpose_kernel(const float* __restrict__ src, float* __restrict__ dst)
{
    __shared__ float t[32][33];
    int p  = blockIdx.z;
    int i0 = blockIdx.y*32, j0 = blockIdx.x*32;
    const float* S = src + (size_t)p*HW;
    float*       D = dst + (size_t)p*HW;
    int tx = threadIdx.x & 31;
    int ty = threadIdx.x >> 5;
#pragma unroll
    for (int r=0;r<32;r+=8) t[ty+r][tx] = S[(size_t)(i0+ty+r)*WW + j0+tx];
    __syncthreads();
#pragma unroll
    for (int r=0;r<32;r+=8) D[(size_t)(j0+ty+r)*WW + i0+tx] = t[tx][ty+r];
}

// ---------------- attention over one line (phase3 on HMMA) ----------------
// smem layout (bytes):
//  qs 0..4096 | ks 4096..8192 | ss 8192..8704 | VH 8704..25600 | VL 25600..42496
//  PH 42496..76288 | PL 76288..110080 | Et 110080..177664
#define ATT_SMEM 177664

__global__ __launch_bounds__(256)
void attn_kernel(const float* __restrict__ q, const float* __restrict__ k,
                 const float* __restrict__ v, const float* __restrict__ scr,
                 const float* __restrict__ x, const float* __restrict__ gamma,
                 float* __restrict__ outp, int mode)
{
    extern __shared__ char smc[];
    float*    qs = (float*)smc;
    float*    ks = (float*)(smc + 4096);
    float*    ss = (float*)(smc + 8192);
    uint32_t* VH = (uint32_t*)(smc + 8704);
    uint32_t* VL = (uint32_t*)(smc + 25600);
    uint32_t* PH = (uint32_t*)(smc + 42496);
    uint32_t* PL = (uint32_t*)(smc + 76288);
    float*    Et = (float*)(smc + 110080);

    int tid = threadIdx.x;
    int row = blockIdx.x;
    int bh  = blockIdx.y;
    int b   = bh >> 2, hd = bh & 3;

    const float* qb = q + ((size_t)(b*CQ + hd*8 ))*HW + (size_t)row*WW;
    const float* kb = k + ((size_t)(b*CQ + hd*8 ))*HW + (size_t)row*WW;
    const float* vb = v + ((size_t)(b*CC + hd*64))*HW + (size_t)row*WW;

    // ---- load q,k (fp32) and v (bf16 hi/lo [c][kv], u32-pair stride 66) ----
    for (int i = tid; i < 1024; i += 256) {
        int c = i >> 7, j = i & 127;
        qs[i] = qb[(size_t)c*HW + j];
        ks[i] = kb[(size_t)c*HW + j];
    }
    for (int i = tid; i < 2048; i += 256) {
        int c = i >> 5, q4 = i & 31;
        float4 vv = *(const float4*)&vb[(size_t)c*HW + q4*4];
        uint32_t lo0, hi0 = pack_hilo(vv.x, vv.y, lo0);
        uint32_t lo1, hi1 = pack_hilo(vv.z, vv.w, lo1);
        *(uint2*)&VH[c*66 + q4*2] = make_uint2(hi0, hi1);
        *(uint2*)&VL[c*66 + q4*2] = make_uint2(lo0, lo1);
    }
    __syncthreads();

    // ---- phase 1: Et[kv][w] = sum_c qs[c][w]*ks[c][kv]  (fp32 SIMT, exact) ----
    {
        int w0 = (tid >> 4) * 8;
        int v0 = (tid & 15) * 8;
        float a[8][8];
#pragma unroll
        for (int j=0;j<8;j++)
#pragma unroll
            for (int i=0;i<8;i++) a[j][i] = 0.f;
#pragma unroll
        for (int c = 0; c < 8; c++) {
            float4 qa = *(const float4*)&qs[c*128 + w0];
            float4 qbv= *(const float4*)&qs[c*128 + w0 + 4];
            float4 ka = *(const float4*)&ks[c*128 + v0];
            float4 kbv= *(const float4*)&ks[c*128 + v0 + 4];
            float qv[8] = {qa.x,qa.y,qa.z,qa.w,qbv.x,qbv.y,qbv.z,qbv.w};
            float kv[8] = {ka.x,ka.y,ka.z,ka.w,kbv.x,kbv.y,kbv.z,kbv.w};
#pragma unroll
            for (int j=0;j<8;j++)
#pragma unroll
                for (int i=0;i<8;i++) a[j][i] += kv[j]*qv[i];
        }
#pragma unroll
        for (int j=0;j<8;j++)
#pragma unroll
            for (int i=0;i<8;i++) Et[(v0+j)*132 + w0+i] = a[j][i];
    }
    __syncthreads();

    // ---- phase 2: softmax per query w; emit transposed bf16 hi/lo P[w][kv] ----
    if (tid < 128) {
        int w = tid;
        float mx = -1e30f;
#pragma unroll 4
        for (int kv=0; kv<128; kv++) mx = fmaxf(mx, Et[kv*132 + w]);
        float s = 0.f;
#pragma unroll 2
        for (int kp=0; kp<64; kp++) {
            float e0 = __expf(Et[(2*kp  )*132 + w] - mx);
            float e1 = __expf(Et[(2*kp+1)*132 + w] - mx);
            s += e0 + e1;
            uint32_t lo, hi = pack_hilo(e0, e1, lo);
            PH[w*66 + kp] = hi;
            PL[w*66 + kp] = lo;
        }
        ss[w] = 1.0f / s;
    }
    __syncthreads();

    // ---- phase 3: O[c][w] = (sum_kv P[kv->w] * v[c][kv]) * ss[w]  via HMMA ----
    {
        int lane = tid & 31, wid = tid >> 5;
        int wm = wid >> 2, wn = wid & 3;      // 2(m=c) x 4(n=w)
        int r = lane >> 2, tg = lane & 3;

        float acc[2][4][4];
#pragma unroll
        for (int mf=0; mf<2; mf++)
#pragma unroll
            for (int nf=0; nf<4; nf++)
#pragma unroll
                for (int j=0; j<4; j++) acc[mf][nf][j] = 0.f;

#pragma unroll
        for (int s = 0; s < 8; s++) {
            uint32_t ah[2][4], al[2][4], bh[4][2], bl[4][2];
#pragma unroll
            for (int mf = 0; mf < 2; mf++) {
                int c0 = wm*32 + mf*16 + r;
                int i0 = c0*66 + 8*s + tg;
                int i1 = i0 + 8*66;
                ah[mf][0]=VH[i0]; ah[mf][1]=VH[i1]; ah[mf][2]=VH[i0+4]; ah[mf][3]=VH[i1+4];
                al[mf][0]=VL[i0]; al[mf][1]=VL[i1]; al[mf][2]=VL[i0+4]; al[mf][3]=VL[i1+4];
            }
#pragma unroll
            for (int nf = 0; nf < 4; nf++) {
                int wr = wn*32 + nf*8 + r;
                int j = wr*66 + 8*s + tg;
                bh[nf][0]=PH[j]; bh[nf][1]=PH[j+4];
                bl[nf][0]=PL[j]; bl[nf][1]=PL[j+4];
            }
#pragma unroll
            for (int mf=0; mf<2; mf++)
#pragma unroll
                for (int nf=0; nf<4; nf++) {
                    mma_bf16(acc[mf][nf], ah[mf], bh[nf]);
                    mma_bf16(acc[mf][nf], ah[mf], bl[nf]);
                    mma_bf16(acc[mf][nf], al[mf], bh[nf]);
                }
        }

        float g = gamma[0];
#pragma unroll
        for (int mf = 0; mf < 2; mf++) {
            int ch = wm*32 + mf*16 + r;
#pragma unroll
            for (int nf = 0; nf < 4; nf++) {
                int wcol = wn*32 + nf*8 + 2*tg;
                float s0 = ss[wcol], s1 = ss[wcol+1];
                const float* a = acc[mf][nf];
                size_t base0 = ((size_t)(b*CC + hd*64 + ch    )*HH + row)*WW + wcol;
                size_t base1 = ((size_t)(b*CC + hd*64 + ch + 8)*HH + row)*WW + wcol;
                if (mode == 0) {
                    *(float2*)&outp[base0] = make_float2(a[0]*s0, a[1]*s1);
                    *(float2*)&outp[base1] = make_float2(a[2]*s0, a[3]*s1);
                } else {
                    float2 sc0 = *(const float2*)&scr[base0];
                    float2 x0  = *(const float2*)&x[base0];
                    float2 sc1 = *(const float2*)&scr[base1];
                    float2 x1  = *(const float2*)&x[base1];
                    *(float2*)&outp[base0] = make_float2(g*(a[0]*s0 + sc0.x) + x0.x,
                                                         g*(a[1]*s1 + sc0.y) + x0.y);
                    *(float2*)&outp[base1] = make_float2(g*(a[2]*s0 + sc1.x) + x1.x,
                                                         g*(a[3]*s1 + sc1.y) + x1.y);
                }
            }
        }
    }
}

// ---------------- host ----------------
extern "C" void kernel_launch(void* const* d_in, const int* in_sizes, int n_in,
                              void* d_out, int out_size)
{
    const float* x     = (const float*)d_in[0];
    const float* Wq    = (const float*)d_in[1];
    const float* bq    = (const float*)d_in[2];
    const float* Wk    = (const float*)d_in[3];
    const float* bk    = (const float*)d_in[4];
    const float* Wv    = (const float*)d_in[5];
    const float* bv    = (const float*)d_in[6];
    const float* gamma = (const float*)d_in[7];
    float* out = (float*)d_out;

    float *pq, *pk, *pv, *pqT, *pkT, *pvT, *poh;
    cudaGetSymbolAddress((void**)&pq,  g_q);
    cudaGetSymbolAddress((void**)&pk,  g_k);
    cudaGetSymbolAddress((void**)&pv,  g_v);
    cudaGetSymbolAddress((void**)&pqT, g_qT);
    cudaGetSymbolAddress((void**)&pkT, g_kT);
    cudaGetSymbolAddress((void**)&pvT, g_vT);
    cudaGetSymbolAddress((void**)&poh, g_oh);

    prep_kernel<<<(MROWS*CC + 255)/256, 256>>>(Wq, bq, Wk, bk, Wv, bv);

    cudaFuncSetAttribute(qkv_mma_kernel, cudaFuncAttributeMaxDynamicSharedMemorySize, PROJ_SMEM);
    qkv_mma_kernel<<<dim3(P/128, MROWS/128, BB), 256, PROJ_SMEM>>>(x);

    transpose_kernel<<<dim3(4,4,BB*CQ), 256>>>(pq, pqT);
    transpose_kernel<<<dim3(4,4,BB*CQ), 256>>>(pk, pkT);
    transpose_kernel<<<dim3(4,4,BB*CC), 256>>>(pv, pvT);

    cudaFuncSetAttribute(attn_kernel, cudaFuncAttributeMaxDynamicSharedMemorySize, ATT_SMEM);
    attn_kernel<<<dim3(HH, BB*NH), 256, ATT_SMEM>>>(pq, pk, pv, nullptr, nullptr, gamma, poh, 0);
    attn_kernel<<<dim3(WW, BB*NH), 256, ATT_SMEM>>>(pqT, pkT, pvT, poh, x, gamma, out, 1);
}

// round 5
// speedup vs baseline: 2.5662x; 2.5662x over previous
#include <cuda_runtime.h>
#include <cuda_bf16.h>
#include <cstdint>

// Problem constants
#define BB   4
#define CC   256
#define CQ   32
#define HH   128
#define WW   128
#define NH   4
#define HW   (HH*WW)          // 16384
#define P    HW
#define MROWS 384             // fused rows: 32 q + 32 k + 256 v + 64 pad

// ---------------- scratch (device globals; no allocation) ----------------
__device__ __align__(16) float g_q [BB*CQ*HW];
__device__ __align__(16) float g_k [BB*CQ*HW];
__device__ __align__(16) float g_v [BB*CC*HW];
__device__ __align__(16) float g_qT[BB*CQ*HW];
__device__ __align__(16) float g_kT[BB*CQ*HW];
__device__ __align__(16) float g_vT[BB*CC*HW];
__device__ __align__(16) float g_oh[BB*CC*HW];
__device__ __align__(16) __nv_bfloat16 g_Whi[MROWS*CC];
__device__ __align__(16) __nv_bfloat16 g_Wlo[MROWS*CC];
__device__ float g_ball[MROWS];

// ---------------- PTX helpers (baseline PTX, compute_103-safe) ----------------
__device__ __forceinline__ uint32_t smem_u32(const void* p) {
    uint32_t a;
    asm("{ .reg .u64 t; cvta.to.shared.u64 t, %1; cvt.u32.u64 %0, t; }" : "=r"(a) : "l"(p));
    return a;
}
__device__ __forceinline__ void mma_bf16(float d[4], const uint32_t a[4], const uint32_t b[2]) {
    asm volatile(
        "mma.sync.aligned.m16n8k16.row.col.f32.bf16.bf16.f32 "
        "{%0,%1,%2,%3}, {%4,%5,%6,%7}, {%8,%9}, {%0,%1,%2,%3};"
        : "+f"(d[0]), "+f"(d[1]), "+f"(d[2]), "+f"(d[3])
        : "r"(a[0]), "r"(a[1]), "r"(a[2]), "r"(a[3]), "r"(b[0]), "r"(b[1]));
}
__device__ __forceinline__ void ldsm4(uint32_t r[4], uint32_t addr) {
    asm volatile("ldmatrix.sync.aligned.m8n8.x4.shared.b16 {%0,%1,%2,%3}, [%4];"
        : "=r"(r[0]), "=r"(r[1]), "=r"(r[2]), "=r"(r[3]) : "r"(addr));
}
__device__ __forceinline__ void ldsm2(uint32_t r[2], uint32_t addr) {
    asm volatile("ldmatrix.sync.aligned.m8n8.x2.shared.b16 {%0,%1}, [%2];"
        : "=r"(r[0]), "=r"(r[1]) : "r"(addr));
}
// split two floats into packed bf16 hi pair (returned) and lo pair (out param)
__device__ __forceinline__ uint32_t pack_hilo(float f0, float f1, uint32_t& lo) {
    __nv_bfloat16 h0 = __float2bfloat16(f0), h1 = __float2bfloat16(f1);
    float l0f = f0 - __bfloat162float(h0);
    float l1f = f1 - __bfloat162float(h1);
    __nv_bfloat16 l0 = __float2bfloat16(l0f), l1 = __float2bfloat16(l1f);
    lo = (uint32_t)__bfloat16_as_ushort(l0) | ((uint32_t)__bfloat16_as_ushort(l1) << 16);
    return (uint32_t)__bfloat16_as_ushort(h0) | ((uint32_t)__bfloat16_as_ushort(h1) << 16);
}

// ---------------- weight prep ----------------
__global__ void prep_kernel(const float* __restrict__ Wq, const float* __restrict__ bq,
                            const float* __restrict__ Wk, const float* __restrict__ bk,
                            const float* __restrict__ Wv, const float* __restrict__ bv)
{
    int i = blockIdx.x * blockDim.x + threadIdx.x;
    if (i >= MROWS * CC) return;
    int m = i >> 8, c = i & 255;
    float w = 0.f, b = 0.f;
    if      (m < 32)  { w = Wq[m * CC + c];        b = bq[m];      }
    else if (m < 64)  { w = Wk[(m - 32) * CC + c]; b = bk[m - 32]; }
    else if (m < 320) { w = Wv[(m - 64) * CC + c]; b = bv[m - 64]; }
    __nv_bfloat16 hi = __float2bfloat16(w);
    float lo = w - __bfloat162float(hi);
    g_Whi[i] = hi;
    g_Wlo[i] = __float2bfloat16(lo);
    if (c == 0) g_ball[m] = b;
}

// ---------------- fused QKV projection on HMMA + ldmatrix ----------------
// Y[m,p] = sum_k W[m,k] X[k,p] + bias[m].  CTA tile M=128, N=128, K chunks of 64.
#define ASTR 36                         // u32 row stride (144B: 16B-mult, 4-bank shift)
#define PROJ_SMEM (4*128*ASTR*4)        // 73728 B

__device__ __forceinline__ void store_proj(int b, int mg, int p, float v0, float v1) {
    if (mg >= 320) return;
    float bv = g_ball[mg];
    float2 val = make_float2(v0 + bv, v1 + bv);
    float* dst;
    if (mg < 32)       dst = g_q + (size_t)(b*CQ + mg) * HW;
    else if (mg < 64)  dst = g_k + (size_t)(b*CQ + mg - 32) * HW;
    else               dst = g_v + (size_t)(b*CC + mg - 64) * HW;
    *(float2*)&dst[p] = val;
}

__global__ __launch_bounds__(256, 2)
void qkv_mma_kernel(const float* __restrict__ X)
{
    extern __shared__ uint32_t sm32[];
    uint32_t* sAhi = sm32;
    uint32_t* sAlo = sm32 + 128*ASTR;
    uint32_t* sBhi = sm32 + 2*128*ASTR;
    uint32_t* sBlo = sm32 + 3*128*ASTR;
    uint32_t sb    = smem_u32(sm32);
    const uint32_t OA = 0, OAL = 128*ASTR*4, OB = 2*128*ASTR*4, OBL = 3*128*ASTR*4;

    int tid = threadIdx.x, lane = tid & 31, wid = tid >> 5;
    int wm = wid >> 2, wn = wid & 3;          // warp grid 2(m) x 4(n)
    int r = lane >> 2, tg = lane & 3;
    int lr = lane & 7, grp = lane >> 3;
    int p0 = blockIdx.x * 128, m0 = blockIdx.y * 128, b = blockIdx.z;
    const float* Xb = X + (size_t)b * CC * P;

    float acc[4][4][4];
#pragma unroll
    for (int mf=0; mf<4; mf++)
#pragma unroll
        for (int nf=0; nf<4; nf++)
#pragma unroll
            for (int j=0; j<4; j++) acc[mf][nf][j] = 0.f;

    for (int ck = 0; ck < 4; ck++) {
        int k0 = ck * 64;
        // W chunk (bf16 hi/lo already); lanes sweep kp -> conflict-free + coalesced
        for (int i = tid; i < 4096; i += 256) {
            int m = i >> 5, kp = i & 31;
            size_t gi = (size_t)(m0 + m) * CC + k0 + 2*kp;
            sAhi[m*ASTR + kp] = *(const uint32_t*)&g_Whi[gi];
            sAlo[m*ASTR + kp] = *(const uint32_t*)&g_Wlo[gi];
        }
        // X chunk: fp32 -> bf16 hi/lo, stored transposed [p][k]
        for (int i = tid; i < 4096; i += 256) {
            int kp = i >> 7, p = i & 127;
            float f0 = Xb[(size_t)(k0 + 2*kp    ) * P + p0 + p];
            float f1 = Xb[(size_t)(k0 + 2*kp + 1) * P + p0 + p];
            uint32_t lo, hi = pack_hilo(f0, f1, lo);
            sBhi[p*ASTR + kp] = hi;
            sBlo[p*ASTR + kp] = lo;
        }
        __syncthreads();
#pragma unroll
        for (int s = 0; s < 4; s++) {
            uint32_t bh[4][2], bl[4][2];
#pragma unroll
            for (int nf = 0; nf < 4; nf++) {
                uint32_t ab = sb + OB + (uint32_t)(((wn*32 + nf*8) + lr)*ASTR + s*8 + ((lane>>3)&1)*4)*4;
                ldsm2(bh[nf], ab);
                ldsm2(bl[nf], ab + (OBL - OB));
            }
#pragma unroll
            for (int mf = 0; mf < 4; mf++) {
                uint32_t aa = sb + OA + (uint32_t)((wm*64 + mf*16 + lr + (grp&1)*8)*ASTR + s*8 + (grp>>1)*4)*4;
                uint32_t ah[4], al[4];
                ldsm4(ah, aa);
                ldsm4(al, aa + OAL);
#pragma unroll
                for (int nf=0; nf<4; nf++) {
                    mma_bf16(acc[mf][nf], ah, bh[nf]);
                    mma_bf16(acc[mf][nf], ah, bl[nf]);
                    mma_bf16(acc[mf][nf], al, bh[nf]);
                }
            }
        }
        __syncthreads();
    }
#pragma unroll
    for (int mf = 0; mf < 4; mf++) {
        int mg = m0 + wm*64 + mf*16 + r;
#pragma unroll
        for (int nf = 0; nf < 4; nf++) {
            int col = p0 + wn*32 + nf*8 + 2*tg;
            store_proj(b, mg,     col, acc[mf][nf][0], acc[mf][nf][1]);
            store_proj(b, mg + 8, col, acc[mf][nf][2], acc[mf][nf][3]);
        }
    }
}

// ---------------- per-plane 128x128 transpose ----------------
__global__ __launch_bounds__(256)
void transpose_kernel(const float* __restrict__ src, float* __restrict__ dst)
{
    __shared__ float t[32][33];
    int p  = blockIdx.z;
    int i0 = blockIdx.y*32, j0 = blockIdx.x*32;
    const float* S = src + (size_t)p*HW;
    float*       D = dst + (size_t)p*HW;
    int tx = threadIdx.x & 31;
    int ty = threadIdx.x >> 5;
#pragma unroll
    for (int r=0;r<32;r+=8) t[ty+r][tx] = S[(size_t)(i0+ty+r)*WW + j0+tx];
    __syncthreads();
#pragma unroll
    for (int r=0;r<32;r+=8) D[(size_t)(j0+ty+r)*WW + i0+tx] = t[tx][ty+r];
}

// ---------------- attention over one line ----------------
// smem (bytes): qs 0..4096 | ks 4096..8192 | ss 8192..8704
//               VH 8704..26112 | VL 26112..43520 | E 43520..111104
// V:  bf16 hi/lo, [c][kv], u32 row stride 68 (272B)
// E:  fp32 [w][kv], float row stride 132 (528B). After softmax, row w holds
//     packed bf16 probs: hi pairs at u32 [0..63], lo pairs at u32 [68..131].
#define VSTR 68
#define ESTR 132
#define ATT_SMEM 111104

__global__ __launch_bounds__(256, 2)
void attn_kernel(const float* __restrict__ q, const float* __restrict__ k,
                 const float* __restrict__ v, const float* __restrict__ scr,
                 const float* __restrict__ x, const float* __restrict__ gamma,
                 float* __restrict__ outp, int mode)
{
    extern __shared__ char smc[];
    float*    qs = (float*)smc;
    float*    ks = (float*)(smc + 4096);
    float*    ss = (float*)(smc + 8192);
    uint32_t* VH = (uint32_t*)(smc + 8704);
    float*    E  = (float*)(smc + 43520);
    uint32_t sb  = smem_u32(smc);
    const uint32_t OVH = 8704, OVL = 26112, OE = 43520;

    int tid = threadIdx.x;
    int row = blockIdx.x;
    int bh  = blockIdx.y;
    int b   = bh >> 2, hd = bh & 3;

    const float* qb = q + ((size_t)(b*CQ + hd*8 ))*HW + (size_t)row*WW;
    const float* kb = k + ((size_t)(b*CQ + hd*8 ))*HW + (size_t)row*WW;
    const float* vb = v + ((size_t)(b*CC + hd*64))*HW + (size_t)row*WW;

    // ---- load q,k (fp32) and v (bf16 hi/lo) ----
    for (int i = tid; i < 1024; i += 256) {
        int c = i >> 7, j = i & 127;
        qs[i] = qb[(size_t)c*HW + j];
        ks[i] = kb[(size_t)c*HW + j];
    }
    {
        uint32_t* VL = (uint32_t*)(smc + OVL);
        for (int i = tid; i < 2048; i += 256) {
            int c = i >> 5, q4 = i & 31;
            float4 vv = *(const float4*)&vb[(size_t)c*HW + q4*4];
            uint32_t lo0, hi0 = pack_hilo(vv.x, vv.y, lo0);
            uint32_t lo1, hi1 = pack_hilo(vv.z, vv.w, lo1);
            *(uint2*)&VH[c*VSTR + q4*2] = make_uint2(hi0, hi1);
            *(uint2*)&VL[c*VSTR + q4*2] = make_uint2(lo0, lo1);
        }
    }
    __syncthreads();

    // ---- phase 1: E[w][kv] = sum_c qs[c][w]*ks[c][kv]  (fp32 SIMT, exact) ----
    {
        int w0 = (tid >> 4) * 8;
        int v0 = (tid & 15) * 8;
        float a[8][8];                   // [w_local][kv_local]
#pragma unroll
        for (int i=0;i<8;i++)
#pragma unroll
            for (int j=0;j<8;j++) a[i][j] = 0.f;
#pragma unroll
        for (int c = 0; c < 8; c++) {
            float4 qa = *(const float4*)&qs[c*128 + w0];
            float4 qbv= *(const float4*)&qs[c*128 + w0 + 4];
            float4 ka = *(const float4*)&ks[c*128 + v0];
            float4 kbv= *(const float4*)&ks[c*128 + v0 + 4];
            float qv[8] = {qa.x,qa.y,qa.z,qa.w,qbv.x,qbv.y,qbv.z,qbv.w};
            float kv[8] = {ka.x,ka.y,ka.z,ka.w,kbv.x,kbv.y,kbv.z,kbv.w};
#pragma unroll
            for (int i=0;i<8;i++)
#pragma unroll
                for (int j=0;j<8;j++) a[i][j] += qv[i]*kv[j];
        }
#pragma unroll
        for (int i=0;i<8;i++) {
            *(float4*)&E[(w0+i)*ESTR + v0]     = make_float4(a[i][0],a[i][1],a[i][2],a[i][3]);
            *(float4*)&E[(w0+i)*ESTR + v0 + 4] = make_float4(a[i][4],a[i][5],a[i][6],a[i][7]);
        }
    }
    __syncthreads();

    // ---- phase 2: softmax along kv; in-place pack to bf16 hi/lo ----
    if (tid < 128) {
        float*    rf = &E[tid * ESTR];
        uint32_t* ru = (uint32_t*)rf;
        float mx = -1e30f;
#pragma unroll 8
        for (int kv = 0; kv < 128; kv += 4) {
            float4 e4 = *(const float4*)&rf[kv];
            mx = fmaxf(mx, fmaxf(fmaxf(e4.x, e4.y), fmaxf(e4.z, e4.w)));
        }
        float s = 0.f;
        uint32_t stg[32];
        // first half ascending: hi -> slot kp (safe), lo staged in regs
#pragma unroll
        for (int kp = 0; kp < 32; kp++) {
            float e0 = __expf(rf[2*kp]   - mx);
            float e1 = __expf(rf[2*kp+1] - mx);
            s += e0 + e1;
            uint32_t lo, hi = pack_hilo(e0, e1, lo);
            ru[kp] = hi;
            stg[kp] = lo;
        }
        // second half descending: hi -> slot kp (already read), lo -> 68+kp (already read)
#pragma unroll
        for (int kp = 63; kp >= 32; kp--) {
            float e0 = __expf(rf[2*kp]   - mx);
            float e1 = __expf(rf[2*kp+1] - mx);
            s += e0 + e1;
            uint32_t lo, hi = pack_hilo(e0, e1, lo);
            ru[kp] = hi;
            ru[68 + kp] = lo;
        }
        // flush staged first-half lo (floats 68..99 consumed by descending pass)
#pragma unroll
        for (int kp = 0; kp < 32; kp++) ru[68 + kp] = stg[kp];
        ss[tid] = 1.0f / s;
    }
    __syncthreads();

    // ---- phase 3: O[c][w] = (sum_kv V[c][kv] P[w][kv]) * ss[w]  via HMMA+ldmatrix ----
    {
        int lane = tid & 31, wid = tid >> 5;
        int wm = wid >> 2, wn = wid & 3;      // 2(m=c) x 4(n=w)
        int r = lane >> 2, tg = lane & 3;
        int lr = lane & 7, grp = lane >> 3;

        float acc[2][4][4];
#pragma unroll
        for (int mf=0; mf<2; mf++)
#pragma unroll
            for (int nf=0; nf<4; nf++)
#pragma unroll
                for (int j=0; j<4; j++) acc[mf][nf][j] = 0.f;

#pragma unroll
        for (int s = 0; s < 8; s++) {
            uint32_t bh[4][2], bl[4][2];
#pragma unroll
            for (int nf = 0; nf < 4; nf++) {
                uint32_t ab = sb + OE + (uint32_t)(((wn*32 + nf*8) + lr)*ESTR + s*8 + ((lane>>3)&1)*4)*4;
                ldsm2(bh[nf], ab);
                ldsm2(bl[nf], ab + 68*4);
            }
#pragma unroll
            for (int mf = 0; mf < 2; mf++) {
                uint32_t aa = sb + OVH + (uint32_t)((wm*32 + mf*16 + lr + (grp&1)*8)*VSTR + s*8 + (grp>>1)*4)*4;
                uint32_t ah[4], al[4];
                ldsm4(ah, aa);
                ldsm4(al, aa + (OVL - OVH));
#pragma unroll
                for (int nf=0; nf<4; nf++) {
                    mma_bf16(acc[mf][nf], ah, bh[nf]);
                    mma_bf16(acc[mf][nf], ah, bl[nf]);
                    mma_bf16(acc[mf][nf], al, bh[nf]);
                }
            }
        }

        float g = gamma[0];
#pragma unroll
        for (int mf = 0; mf < 2; mf++) {
            int ch = wm*32 + mf*16 + r;
#pragma unroll
            for (int nf = 0; nf < 4; nf++) {
                int wcol = wn*32 + nf*8 + 2*tg;
                float s0 = ss[wcol], s1 = ss[wcol+1];
                const float* a = acc[mf][nf];
                size_t base0 = ((size_t)(b*CC + hd*64 + ch    )*HH + row)*WW + wcol;
                size_t base1 = ((size_t)(b*CC + hd*64 + ch + 8)*HH + row)*WW + wcol;
                if (mode == 0) {
                    *(float2*)&outp[base0] = make_float2(a[0]*s0, a[1]*s1);
                    *(float2*)&outp[base1] = make_float2(a[2]*s0, a[3]*s1);
                } else {
                    float2 sc0 = *(const float2*)&scr[base0];
                    float2 x0  = *(const float2*)&x[base0];
                    float2 sc1 = *(const float2*)&scr[base1];
                    float2 x1  = *(const float2*)&x[base1];
                    *(float2*)&outp[base0] = make_float2(g*(a[0]*s0 + sc0.x) + x0.x,
                                                         g*(a[1]*s1 + sc0.y) + x0.y);
                    *(float2*)&outp[base1] = make_float2(g*(a[2]*s0 + sc1.x) + x1.x,
                                                         g*(a[3]*s1 + sc1.y) + x1.y);
                }
            }
        }
    }
}

// ---------------- host ----------------
extern "C" void kernel_launch(void* const* d_in, const int* in_sizes, int n_in,
                              void* d_out, int out_size)
{
    const float* x     = (const float*)d_in[0];
    const float* Wq    = (const float*)d_in[1];
    const float* bq    = (const float*)d_in[2];
    const float* Wk    = (const float*)d_in[3];
    const float* bk    = (const float*)d_in[4];
    const float* Wv    = (const float*)d_in[5];
    const float* bv    = (const float*)d_in[6];
    const float* gamma = (const float*)d_in[7];
    float* out = (float*)d_out;

    float *pq, *pk, *pv, *pqT, *pkT, *pvT, *poh;
    cudaGetSymbolAddress((void**)&pq,  g_q);
    cudaGetSymbolAddress((void**)&pk,  g_k);
    cudaGetSymbolAddress((void**)&pv,  g_v);
    cudaGetSymbolAddress((void**)&pqT, g_qT);
    cudaGetSymbolAddress((void**)&pkT, g_kT);
    cudaGetSymbolAddress((void**)&pvT, g_vT);
    cudaGetSymbolAddress((void**)&poh, g_oh);

    prep_kernel<<<(MROWS*CC + 255)/256, 256>>>(Wq, bq, Wk, bk, Wv, bv);

    cudaFuncSetAttribute(qkv_mma_kernel, cudaFuncAttributeMaxDynamicSharedMemorySize, PROJ_SMEM);
    qkv_mma_kernel<<<dim3(P/128, MROWS/128, BB), 256, PROJ_SMEM>>>(x);

    transpose_kernel<<<dim3(4,4,BB*CQ), 256>>>(pq, pqT);
    transpose_kernel<<<dim3(4,4,BB*CQ), 256>>>(pk, pkT);
    transpose_kernel<<<dim3(4,4,BB*CC), 256>>>(pv, pvT);

    cudaFuncSetAttribute(attn_kernel, cudaFuncAttributeMaxDynamicSharedMemorySize, ATT_SMEM);
    attn_kernel<<<dim3(HH, BB*NH), 256, ATT_SMEM>>>(pq, pk, pv, nullptr, nullptr, gamma, poh, 0);
    attn_kernel<<<dim3(WW, BB*NH), 256, ATT_SMEM>>>(pqT, pkT, pvT, poh, x, gamma, out, 1);
}

// round 6
// speedup vs baseline: 2.7610x; 1.0759x over previous
#include <cuda_runtime.h>
#include <cuda_bf16.h>
#include <cstdint>

// Problem constants
#define BB   4
#define CC   256
#define CQ   32
#define HH   128
#define WW   128
#define NH   4
#define HW   (HH*WW)          // 16384
#define P    HW
#define MROWS 384             // fused rows: 32 q + 32 k + 256 v + 64 pad

// ---------------- scratch (device globals; no allocation) ----------------
__device__ __align__(16) float g_q [BB*CQ*HW];
__device__ __align__(16) float g_k [BB*CQ*HW];
__device__ __align__(16) float g_v [BB*CC*HW];
__device__ __align__(16) float g_qT[BB*CQ*HW];
__device__ __align__(16) float g_kT[BB*CQ*HW];
__device__ __align__(16) float g_vT[BB*CC*HW];
__device__ __align__(16) float g_oh[BB*CC*HW];
__device__ __align__(16) __nv_bfloat16 g_Whi[MROWS*CC];
__device__ __align__(16) __nv_bfloat16 g_Wlo[MROWS*CC];
__device__ __align__(16) __nv_bfloat16 g_Xhi[BB*CC*HW];
__device__ __align__(16) __nv_bfloat16 g_Xlo[BB*CC*HW];
__device__ float g_ball[MROWS];

// ---------------- PTX helpers (baseline PTX, compute_103-safe) ----------------
__device__ __forceinline__ uint32_t smem_u32(const void* p) {
    uint32_t a;
    asm("{ .reg .u64 t; cvta.to.shared.u64 t, %1; cvt.u32.u64 %0, t; }" : "=r"(a) : "l"(p));
    return a;
}
__device__ __forceinline__ void mma_bf16(float d[4], const uint32_t a[4], const uint32_t b[2]) {
    asm volatile(
        "mma.sync.aligned.m16n8k16.row.col.f32.bf16.bf16.f32 "
        "{%0,%1,%2,%3}, {%4,%5,%6,%7}, {%8,%9}, {%0,%1,%2,%3};"
        : "+f"(d[0]), "+f"(d[1]), "+f"(d[2]), "+f"(d[3])
        : "r"(a[0]), "r"(a[1]), "r"(a[2]), "r"(a[3]), "r"(b[0]), "r"(b[1]));
}
__device__ __forceinline__ void ldsm4(uint32_t r[4], uint32_t addr) {
    asm volatile("ldmatrix.sync.aligned.m8n8.x4.shared.b16 {%0,%1,%2,%3}, [%4];"
        : "=r"(r[0]), "=r"(r[1]), "=r"(r[2]), "=r"(r[3]) : "r"(addr));
}
__device__ __forceinline__ void ldsm4t(uint32_t r[4], uint32_t addr) {
    asm volatile("ldmatrix.sync.aligned.m8n8.x4.trans.shared.b16 {%0,%1,%2,%3}, [%4];"
        : "=r"(r[0]), "=r"(r[1]), "=r"(r[2]), "=r"(r[3]) : "r"(addr));
}
__device__ __forceinline__ void ldsm2(uint32_t r[2], uint32_t addr) {
    asm volatile("ldmatrix.sync.aligned.m8n8.x2.shared.b16 {%0,%1}, [%2];"
        : "=r"(r[0]), "=r"(r[1]) : "r"(addr));
}
#define CP_ASYNC16(dst, src) asm volatile("cp.async.cg.shared.global [%0], [%1], 16;" :: "r"(dst), "l"(src))
#define CP_COMMIT()          asm volatile("cp.async.commit_group;")
#define CP_WAIT1()           asm volatile("cp.async.wait_group 1;")

// split two floats into packed bf16 hi pair (returned) and lo pair (out param)
__device__ __forceinline__ uint32_t pack_hilo(float f0, float f1, uint32_t& lo) {
    __nv_bfloat16 h0 = __float2bfloat16(f0), h1 = __float2bfloat16(f1);
    float l0f = f0 - __bfloat162float(h0);
    float l1f = f1 - __bfloat162float(h1);
    __nv_bfloat16 l0 = __float2bfloat16(l0f), l1 = __float2bfloat16(l1f);
    lo = (uint32_t)__bfloat16_as_ushort(l0) | ((uint32_t)__bfloat16_as_ushort(l1) << 16);
    return (uint32_t)__bfloat16_as_ushort(h0) | ((uint32_t)__bfloat16_as_ushort(h1) << 16);
}

// ---------------- weight prep ----------------
__global__ void prep_kernel(const float* __restrict__ Wq, const float* __restrict__ bq,
                            const float* __restrict__ Wk, const float* __restrict__ bk,
                            const float* __restrict__ Wv, const float* __restrict__ bv)
{
    int i = blockIdx.x * blockDim.x + threadIdx.x;
    if (i >= MROWS * CC) return;
    int m = i >> 8, c = i & 255;
    float w = 0.f, b = 0.f;
    if      (m < 32)  { w = Wq[m * CC + c];        b = bq[m];      }
    else if (m < 64)  { w = Wk[(m - 32) * CC + c]; b = bk[m - 32]; }
    else if (m < 320) { w = Wv[(m - 64) * CC + c]; b = bv[m - 64]; }
    __nv_bfloat16 hi = __float2bfloat16(w);
    float lo = w - __bfloat162float(hi);
    g_Whi[i] = hi;
    g_Wlo[i] = __float2bfloat16(lo);
    if (c == 0) g_ball[m] = b;
}

// ---------------- X pre-convert: fp32 -> bf16 hi/lo planar ----------------
__global__ __launch_bounds__(256)
void xconv_kernel(const float* __restrict__ X)
{
    size_t i = ((size_t)blockIdx.x * 256 + threadIdx.x) * 4;
    float4 v = *(const float4*)&X[i];
    uint32_t lo0, hi0 = pack_hilo(v.x, v.y, lo0);
    uint32_t lo1, hi1 = pack_hilo(v.z, v.w, lo1);
    *(uint2*)&g_Xhi[i] = make_uint2(hi0, hi1);
    *(uint2*)&g_Xlo[i] = make_uint2(lo0, lo1);
}

// ---------------- fused QKV projection: cp.async double-buffered HMMA ----------------
// Y[m,p] = sum_k W[m,k] X[k,p] + bias[m].  CTA tile M=128, N=128, K chunks of 32 (x8).
// Buffer layout (bytes): A hi [128][80] | A lo [128][80] | B hi [32][272] | B lo [32][272]
#define OAH 0
#define OAL 10240
#define OBH 20480
#define OBL 29184
#define BUFSZ 37888
#define PROJ_SMEM (2*BUFSZ)   // 75776

__device__ __forceinline__ void store_proj(int b, int mg, int p, float v0, float v1) {
    if (mg >= 320) return;
    float bv = g_ball[mg];
    float2 val = make_float2(v0 + bv, v1 + bv);
    float* dst;
    if (mg < 32)       dst = g_q + (size_t)(b*CQ + mg) * HW;
    else if (mg < 64)  dst = g_k + (size_t)(b*CQ + mg - 32) * HW;
    else               dst = g_v + (size_t)(b*CC + mg - 64) * HW;
    *(float2*)&dst[p] = val;
}

__global__ __launch_bounds__(256, 2)
void qkv_mma_kernel()
{
    extern __shared__ char smem[];
    uint32_t sbase = smem_u32(smem);

    int tid = threadIdx.x, lane = tid & 31, wid = tid >> 5;
    int wm = wid >> 2, wn = wid & 3;          // warp grid 2(m) x 4(n)
    int r = lane >> 2, tg = lane & 3;
    int p0 = blockIdx.x * 128, m0 = blockIdx.y * 128, bb = blockIdx.z;

    float acc[4][4][4];
#pragma unroll
    for (int mf=0; mf<4; mf++)
#pragma unroll
        for (int nf=0; nf<4; nf++)
#pragma unroll
            for (int j=0; j<4; j++) acc[mf][nf][j] = 0.f;

    // --- async chunk loader ---
    auto load_chunk = [&](int ck, int buf) {
        uint32_t base = sbase + buf*BUFSZ;
#pragma unroll
        for (int t = 0; t < 4; t++) {            // A: 1024 granules (hi+lo)
            int item = t*256 + tid;
            int half = item >> 9, m = (item >> 2) & 127, g = item & 3;
            uint32_t dst = base + (half ? OAL : OAH) + m*80 + g*16;
            const __nv_bfloat16* src = (half ? g_Wlo : g_Whi)
                                     + (size_t)(m0 + m)*CC + ck*32 + g*8;
            CP_ASYNC16(dst, src);
        }
#pragma unroll
        for (int t = 0; t < 4; t++) {            // B: 1024 granules (hi+lo)
            int item = t*256 + tid;
            int half = item >> 9, k = (item >> 4) & 31, g = item & 15;
            uint32_t dst = base + (half ? OBL : OBH) + k*272 + g*16;
            const __nv_bfloat16* src = (half ? g_Xlo : g_Xhi)
                                     + ((size_t)(bb*CC + ck*32 + k))*P + p0 + g*8;
            CP_ASYNC16(dst, src);
        }
    };

    load_chunk(0, 0);
    CP_COMMIT();

    for (int ck = 0; ck < 8; ck++) {
        if (ck < 7) load_chunk(ck + 1, (ck + 1) & 1);
        CP_COMMIT();
        CP_WAIT1();
        __syncthreads();

        uint32_t base = sbase + (ck & 1)*BUFSZ;
#pragma unroll
        for (int s = 0; s < 2; s++) {
            // B frags via trans ldmatrix on [k][p] storage
            uint32_t bh[4][2], bl[4][2];
#pragma unroll
            for (int pr = 0; pr < 2; pr++) {
                uint32_t ab = base + OBH + (uint32_t)((s*16 + (lane & 15))*272
                             + (wn*32 + pr*16 + (lane >> 4)*8)*2);
                uint32_t t4h[4], t4l[4];
                ldsm4t(t4h, ab);
                ldsm4t(t4l, ab + (OBL - OBH));
                bh[2*pr][0]=t4h[0]; bh[2*pr][1]=t4h[1]; bh[2*pr+1][0]=t4h[2]; bh[2*pr+1][1]=t4h[3];
                bl[2*pr][0]=t4l[0]; bl[2*pr][1]=t4l[1]; bl[2*pr+1][0]=t4l[2]; bl[2*pr+1][1]=t4l[3];
            }
#pragma unroll
            for (int mf = 0; mf < 4; mf++) {
                uint32_t aa = base + OAH + (uint32_t)((wm*64 + mf*16 + (lane & 15))*80
                             + s*32 + (lane >> 4)*16);
                uint32_t ah[4], al[4];
                ldsm4(ah, aa);
                ldsm4(al, aa + (OAL - OAH));
#pragma unroll
                for (int nf = 0; nf < 4; nf++) {
                    mma_bf16(acc[mf][nf], ah, bh[nf]);
                    mma_bf16(acc[mf][nf], ah, bl[nf]);
                    mma_bf16(acc[mf][nf], al, bh[nf]);
                }
            }
        }
        __syncthreads();
    }

#pragma unroll
    for (int mf = 0; mf < 4; mf++) {
        int mg = m0 + wm*64 + mf*16 + r;
#pragma unroll
        for (int nf = 0; nf < 4; nf++) {
            int col = p0 + wn*32 + nf*8 + 2*tg;
            store_proj(bb, mg,     col, acc[mf][nf][0], acc[mf][nf][1]);
            store_proj(bb, mg + 8, col, acc[mf][nf][2], acc[mf][nf][3]);
        }
    }
}

// ---------------- per-plane 128x128 transpose ----------------
__global__ __launch_bounds__(256)
void transpose_kernel(const float* __restrict__ src, float* __restrict__ dst)
{
    __shared__ float t[32][33];
    int p  = blockIdx.z;
    int i0 = blockIdx.y*32, j0 = blockIdx.x*32;
    const float* S = src + (size_t)p*HW;
    float*       D = dst + (size_t)p*HW;
    int tx = threadIdx.x & 31;
    int ty = threadIdx.x >> 5;
#pragma unroll
    for (int r=0;r<32;r+=8) t[ty+r][tx] = S[(size_t)(i0+ty+r)*WW + j0+tx];
    __syncthreads();
#pragma unroll
    for (int r=0;r<32;r+=8) D[(size_t)(j0+ty+r)*WW + i0+tx] = t[tx][ty+r];
}

// ---------------- attention over one line (all-HMMA, register softmax) ----------------
// smem (bytes): VH [64][272] 0..17408 | VL 17408..34816 | PH [128][272] 34816..69632
//               PL 69632..104448 | ss 104448..104960
// q/k bf16 staging (overlaid on PH region, consumed before PH written):
//   QH 34816 | QL 40960 | KH 47104 | KL 53248, each [128 rows][48B] (16 cols, 8 zero-pad)
#define ATT_SMEM 104960

__global__ __launch_bounds__(256, 2)
void attn_kernel(const float* __restrict__ q, const float* __restrict__ k,
                 const float* __restrict__ v, const float* __restrict__ scr,
                 const float* __restrict__ x, const float* __restrict__ gamma,
                 float* __restrict__ outp, int mode)
{
    extern __shared__ char smc[];
    const uint32_t OVH = 0, OVL = 17408, OPH = 34816, OPL = 69632, OSS = 104448;
    const uint32_t OQH = 34816, OQL = 40960, OKH = 47104, OKL = 53248;
    uint32_t sb = smem_u32(smc);
    uint32_t* VH = (uint32_t*)(smc + OVH);
    uint32_t* VL = (uint32_t*)(smc + OVL);
    uint32_t* PH = (uint32_t*)(smc + OPH);
    uint32_t* PL = (uint32_t*)(smc + OPL);
    float*    ss = (float*)(smc + OSS);

    int tid = threadIdx.x;
    int row = blockIdx.x;
    int bh  = blockIdx.y;
    int b   = bh >> 2, hd = bh & 3;
    int lane = tid & 31, wid = tid >> 5;

    const float* qb = q + ((size_t)(b*CQ + hd*8 ))*HW + (size_t)row*WW;
    const float* kb = k + ((size_t)(b*CQ + hd*8 ))*HW + (size_t)row*WW;
    const float* vb = v + ((size_t)(b*CC + hd*64))*HW + (size_t)row*WW;

    // ---- v: fp32 -> bf16 hi/lo [c][kv], u32 stride 68 ----
    for (int i = tid; i < 2048; i += 256) {
        int c = i >> 5, q4 = i & 31;
        float4 vv = *(const float4*)&vb[(size_t)c*HW + q4*4];
        uint32_t lo0, hi0 = pack_hilo(vv.x, vv.y, lo0);
        uint32_t lo1, hi1 = pack_hilo(vv.z, vv.w, lo1);
        *(uint2*)&VH[c*68 + q4*2] = make_uint2(hi0, hi1);
        *(uint2*)&VL[c*68 + q4*2] = make_uint2(lo0, lo1);
    }
    // ---- q,k: fp32 [c][w] -> bf16 hi/lo staged [w][c] (row 48B, cols 8..15 zero) ----
    for (int i = tid; i < 2048; i += 256) {
        int half = i >> 10, j = i & 1023, c = j >> 7, w = j & 127;
        const float* src = half ? kb : qb;
        float f = src[(size_t)c*HW + w];
        __nv_bfloat16 h = __float2bfloat16(f);
        float l = f - __bfloat162float(h);
        __nv_bfloat16 lb = __float2bfloat16(l);
        uint32_t off = (half ? OKH : OQH) + (uint32_t)(w*48 + c*2);
        *(uint16_t*)(smc + off)        = __bfloat16_as_ushort(h);
        *(uint16_t*)(smc + off + 6144) = __bfloat16_as_ushort(lb);
    }
    for (int i = tid; i < 2048; i += 256) {      // zero pad cols 8..15 (u32 4..7)
        int mat = i >> 9, w = (i >> 2) & 127, u = i & 3;
        *(uint32_t*)(smc + OQH + mat*6144 + w*48 + 16 + u*4) = 0;
    }
    __syncthreads();

    // ---- phase 1: E[w][kv] = q^T k via HMMA (K padded to 16) ----
    int w0 = wid * 16;
    float e[16][4];
#pragma unroll
    for (int nf=0; nf<16; nf++)
#pragma unroll
        for (int j=0; j<4; j++) e[nf][j] = 0.f;
    {
        uint32_t aqh[4], aql[4];
        uint32_t aa = sb + OQH + (uint32_t)((w0 + (lane & 15))*48 + (lane >> 4)*16);
        ldsm4(aqh, aa);
        ldsm4(aql, aa + (OQL - OQH));
#pragma unroll
        for (int t = 0; t < 8; t++) {
            uint32_t ba = sb + OKH + (uint32_t)((t*16 + (lane & 15))*48 + (lane >> 4)*16);
            uint32_t bh4[4], bl4[4];
            ldsm4(bh4, ba);
            ldsm4(bl4, ba + (OKL - OKH));
            uint32_t B0h[2] = {bh4[0], bh4[2]}, B1h[2] = {bh4[1], bh4[3]};
            uint32_t B0l[2] = {bl4[0], bl4[2]}, B1l[2] = {bl4[1], bl4[3]};
            mma_bf16(e[2*t],   aqh, B0h);
            mma_bf16(e[2*t],   aqh, B0l);
            mma_bf16(e[2*t],   aql, B0h);
            mma_bf16(e[2*t+1], aqh, B1h);
            mma_bf16(e[2*t+1], aqh, B1l);
            mma_bf16(e[2*t+1], aql, B1h);
        }
    }
    __syncthreads();   // staging reads complete before P region overwritten

    // ---- phase 2: softmax entirely in registers; pack straight to P hi/lo ----
    {
        int r = lane >> 2, tg = lane & 3;
        float mx0 = -1e30f, mx1 = -1e30f;
#pragma unroll
        for (int nf = 0; nf < 16; nf++) {
            mx0 = fmaxf(mx0, fmaxf(e[nf][0], e[nf][1]));
            mx1 = fmaxf(mx1, fmaxf(e[nf][2], e[nf][3]));
        }
        mx0 = fmaxf(mx0, __shfl_xor_sync(0xFFFFFFFF, mx0, 1));
        mx0 = fmaxf(mx0, __shfl_xor_sync(0xFFFFFFFF, mx0, 2));
        mx1 = fmaxf(mx1, __shfl_xor_sync(0xFFFFFFFF, mx1, 1));
        mx1 = fmaxf(mx1, __shfl_xor_sync(0xFFFFFFFF, mx1, 2));
        float s0 = 0.f, s1 = 0.f;
#pragma unroll
        for (int nf = 0; nf < 16; nf++) {
            e[nf][0] = __expf(e[nf][0] - mx0);
            e[nf][1] = __expf(e[nf][1] - mx0);
            e[nf][2] = __expf(e[nf][2] - mx1);
            e[nf][3] = __expf(e[nf][3] - mx1);
            s0 += e[nf][0] + e[nf][1];
            s1 += e[nf][2] + e[nf][3];
        }
        s0 += __shfl_xor_sync(0xFFFFFFFF, s0, 1);
        s0 += __shfl_xor_sync(0xFFFFFFFF, s0, 2);
        s1 += __shfl_xor_sync(0xFFFFFFFF, s1, 1);
        s1 += __shfl_xor_sync(0xFFFFFFFF, s1, 2);
        if (tg == 0) {
            ss[w0 + r]     = 1.0f / s0;
            ss[w0 + r + 8] = 1.0f / s1;
        }
#pragma unroll
        for (int nf = 0; nf < 16; nf++) {
            uint32_t lo0, hi0 = pack_hilo(e[nf][0], e[nf][1], lo0);
            uint32_t lo1, hi1 = pack_hilo(e[nf][2], e[nf][3], lo1);
            PH[(w0 + r)*68     + nf*4 + tg] = hi0;
            PL[(w0 + r)*68     + nf*4 + tg] = lo0;
            PH[(w0 + r + 8)*68 + nf*4 + tg] = hi1;
            PL[(w0 + r + 8)*68 + nf*4 + tg] = lo1;
        }
    }
    __syncthreads();

    // ---- phase 3: O[c][w] = (V P^T) * ss[w] via HMMA + ldmatrix ----
    {
        int wm = wid >> 2, wn = wid & 3;      // 2(m=c) x 4(n=w)
        int r = lane >> 2, tg = lane & 3;
        int lr = lane & 7, grp = lane >> 3;

        float acc[2][4][4];
#pragma unroll
        for (int mf=0; mf<2; mf++)
#pragma unroll
            for (int nf=0; nf<4; nf++)
#pragma unroll
                for (int j=0; j<4; j++) acc[mf][nf][j] = 0.f;

#pragma unroll
        for (int s = 0; s < 8; s++) {
            uint32_t bh2[4][2], bl2[4][2];
#pragma unroll
            for (int nf = 0; nf < 4; nf++) {
                uint32_t ab = sb + OPH + (uint32_t)(((wn*32 + nf*8) + lr)*68 + s*8 + ((lane>>3)&1)*4)*4;
                ldsm2(bh2[nf], ab);
                ldsm2(bl2[nf], ab + (OPL - OPH));
            }
#pragma unroll
            for (int mf = 0; mf < 2; mf++) {
                uint32_t aa = sb + OVH + (uint32_t)((wm*32 + mf*16 + lr + (grp&1)*8)*68 + s*8 + (grp>>1)*4)*4;
                uint32_t ah[4], al[4];
                ldsm4(ah, aa);
                ldsm4(al, aa + (OVL - OVH));
#pragma unroll
                for (int nf=0; nf<4; nf++) {
                    mma_bf16(acc[mf][nf], ah, bh2[nf]);
                    mma_bf16(acc[mf][nf], ah, bl2[nf]);
                    mma_bf16(acc[mf][nf], al, bh2[nf]);
                }
            }
        }

        float g = gamma[0];
#pragma unroll
        for (int mf = 0; mf < 2; mf++) {
            int ch = wm*32 + mf*16 + r;
#pragma unroll
            for (int nf = 0; nf < 4; nf++) {
                int wcol = wn*32 + nf*8 + 2*tg;
                float s0 = ss[wcol], s1 = ss[wcol+1];
                const float* a = acc[mf][nf];
                size_t base0 = ((size_t)(b*CC + hd*64 + ch    )*HH + row)*WW + wcol;
                size_t base1 = ((size_t)(b*CC + hd*64 + ch + 8)*HH + row)*WW + wcol;
                if (mode == 0) {
                    *(float2*)&outp[base0] = make_float2(a[0]*s0, a[1]*s1);
                    *(float2*)&outp[base1] = make_float2(a[2]*s0, a[3]*s1);
                } else {
                    float2 sc0 = *(const float2*)&scr[base0];
                    float2 x0  = *(const float2*)&x[base0];
                    float2 sc1 = *(const float2*)&scr[base1];
                    float2 x1  = *(const float2*)&x[base1];
                    *(float2*)&outp[base0] = make_float2(g*(a[0]*s0 + sc0.x) + x0.x,
                                                         g*(a[1]*s1 + sc0.y) + x0.y);
                    *(float2*)&outp[base1] = make_float2(g*(a[2]*s0 + sc1.x) + x1.x,
                                                         g*(a[3]*s1 + sc1.y) + x1.y);
                }
            }
        }
    }
}

// ---------------- host ----------------
extern "C" void kernel_launch(void* const* d_in, const int* in_sizes, int n_in,
                              void* d_out, int out_size)
{
    const float* x     = (const float*)d_in[0];
    const float* Wq    = (const float*)d_in[1];
    const float* bq    = (const float*)d_in[2];
    const float* Wk    = (const float*)d_in[3];
    const float* bk    = (const float*)d_in[4];
    const float* Wv    = (const float*)d_in[5];
    const float* bv    = (const float*)d_in[6];
    const float* gamma = (const float*)d_in[7];
    float* out = (float*)d_out;

    float *pq, *pk, *pv, *pqT, *pkT, *pvT, *poh;
    cudaGetSymbolAddress((void**)&pq,  g_q);
    cudaGetSymbolAddress((void**)&pk,  g_k);
    cudaGetSymbolAddress((void**)&pv,  g_v);
    cudaGetSymbolAddress((void**)&pqT, g_qT);
    cudaGetSymbolAddress((void**)&pkT, g_kT);
    cudaGetSymbolAddress((void**)&pvT, g_vT);
    cudaGetSymbolAddress((void**)&poh, g_oh);

    prep_kernel<<<(MROWS*CC + 255)/256, 256>>>(Wq, bq, Wk, bk, Wv, bv);
    xconv_kernel<<<(BB*CC*HW)/(256*4), 256>>>(x);

    cudaFuncSetAttribute(qkv_mma_kernel, cudaFuncAttributeMaxDynamicSharedMemorySize, PROJ_SMEM);
    qkv_mma_kernel<<<dim3(P/128, MROWS/128, BB), 256, PROJ_SMEM>>>();

    transpose_kernel<<<dim3(4,4,BB*CQ), 256>>>(pq, pqT);
    transpose_kernel<<<dim3(4,4,BB*CQ), 256>>>(pk, pkT);
    transpose_kernel<<<dim3(4,4,BB*CC), 256>>>(pv, pvT);

    cudaFuncSetAttribute(attn_kernel, cudaFuncAttributeMaxDynamicSharedMemorySize, ATT_SMEM);
    attn_kernel<<<dim3(HH, BB*NH), 256, ATT_SMEM>>>(pq, pk, pv, nullptr, nullptr, gamma, poh, 0);
    attn_kernel<<<dim3(WW, BB*NH), 256, ATT_SMEM>>>(pqT, pkT, pvT, poh, x, gamma, out, 1);
}

// round 8
// speedup vs baseline: 3.4147x; 1.2368x over previous
#include <cuda_runtime.h>
#include <cuda_bf16.h>
#include <cstdint>

// Problem constants
#define BB   4
#define CC   256
#define CQ   32
#define HH   128
#define WW   128
#define NH   4
#define HW   (HH*WW)          // 16384
#define P    HW
#define MROWS 384             // fused rows: 32 q + 32 k + 256 v + 64 pad

// ---------------- scratch (device globals; no allocation) ----------------
__device__ __align__(16) float g_oh[BB*CC*HW];                 // o_h scratch (fp32)
__device__ __align__(16) __nv_bfloat16 g_Whi[MROWS*CC];
__device__ __align__(16) __nv_bfloat16 g_Wlo[MROWS*CC];
__device__ __align__(16) __nv_bfloat16 g_Xhi[BB*CC*HW];
__device__ __align__(16) __nv_bfloat16 g_Xlo[BB*CC*HW];
// projections, bf16 hi/lo planar
__device__ __align__(16) __nv_bfloat16 g_qhi [BB*CQ*HW], g_qlo [BB*CQ*HW];
__device__ __align__(16) __nv_bfloat16 g_khi [BB*CQ*HW], g_klo [BB*CQ*HW];
__device__ __align__(16) __nv_bfloat16 g_vhi [BB*CC*HW], g_vlo [BB*CC*HW];
__device__ __align__(16) __nv_bfloat16 g_qThi[BB*CQ*HW], g_qTlo[BB*CQ*HW];
__device__ __align__(16) __nv_bfloat16 g_kThi[BB*CQ*HW], g_kTlo[BB*CQ*HW];
__device__ __align__(16) __nv_bfloat16 g_vThi[BB*CC*HW], g_vTlo[BB*CC*HW];
__device__ float g_ball[MROWS];

// ---------------- PTX helpers (baseline PTX, compute_103-safe) ----------------
__device__ __forceinline__ uint32_t smem_u32(const void* p) {
    uint32_t a;
    asm("{ .reg .u64 t; cvta.to.shared.u64 t, %1; cvt.u32.u64 %0, t; }" : "=r"(a) : "l"(p));
    return a;
}
__device__ __forceinline__ void mma_bf16(float d[4], const uint32_t a[4], const uint32_t b[2]) {
    asm volatile(
        "mma.sync.aligned.m16n8k16.row.col.f32.bf16.bf16.f32 "
        "{%0,%1,%2,%3}, {%4,%5,%6,%7}, {%8,%9}, {%0,%1,%2,%3};"
        : "+f"(d[0]), "+f"(d[1]), "+f"(d[2]), "+f"(d[3])
        : "r"(a[0]), "r"(a[1]), "r"(a[2]), "r"(a[3]), "r"(b[0]), "r"(b[1]));
}
__device__ __forceinline__ void ldsm4(uint32_t r[4], uint32_t addr) {
    asm volatile("ldmatrix.sync.aligned.m8n8.x4.shared.b16 {%0,%1,%2,%3}, [%4];"
        : "=r"(r[0]), "=r"(r[1]), "=r"(r[2]), "=r"(r[3]) : "r"(addr));
}
__device__ __forceinline__ void ldsm4t(uint32_t r[4], uint32_t addr) {
    asm volatile("ldmatrix.sync.aligned.m8n8.x4.trans.shared.b16 {%0,%1,%2,%3}, [%4];"
        : "=r"(r[0]), "=r"(r[1]), "=r"(r[2]), "=r"(r[3]) : "r"(addr));
}
__device__ __forceinline__ void ldsm2(uint32_t r[2], uint32_t addr) {
    asm volatile("ldmatrix.sync.aligned.m8n8.x2.shared.b16 {%0,%1}, [%2];"
        : "=r"(r[0]), "=r"(r[1]) : "r"(addr));
}
#define CP_ASYNC16(dst, src) asm volatile("cp.async.cg.shared.global [%0], [%1], 16;" :: "r"(dst), "l"(src))
#define CP_COMMIT()          asm volatile("cp.async.commit_group;")
#define CP_WAIT1()           asm volatile("cp.async.wait_group 1;")
#define CP_WAIT0()           asm volatile("cp.async.wait_group 0;")

// split two floats into packed bf16 hi pair (returned) and lo pair (out param)
__device__ __forceinline__ uint32_t pack_hilo(float f0, float f1, uint32_t& lo) {
    __nv_bfloat16 h0 = __float2bfloat16(f0), h1 = __float2bfloat16(f1);
    float l0f = f0 - __bfloat162float(h0);
    float l1f = f1 - __bfloat162float(h1);
    __nv_bfloat16 l0 = __float2bfloat16(l0f), l1 = __float2bfloat16(l1f);
    lo = (uint32_t)__bfloat16_as_ushort(l0) | ((uint32_t)__bfloat16_as_ushort(l1) << 16);
    return (uint32_t)__bfloat16_as_ushort(h0) | ((uint32_t)__bfloat16_as_ushort(h1) << 16);
}

// ---------------- weight prep ----------------
__global__ void prep_kernel(const float* __restrict__ Wq, const float* __restrict__ bq,
                            const float* __restrict__ Wk, const float* __restrict__ bk,
                            const float* __restrict__ Wv, const float* __restrict__ bv)
{
    int i = blockIdx.x * blockDim.x + threadIdx.x;
    if (i >= MROWS * CC) return;
    int m = i >> 8, c = i & 255;
    float w = 0.f, b = 0.f;
    if      (m < 32)  { w = Wq[m * CC + c];        b = bq[m];      }
    else if (m < 64)  { w = Wk[(m - 32) * CC + c]; b = bk[m - 32]; }
    else if (m < 320) { w = Wv[(m - 64) * CC + c]; b = bv[m - 64]; }
    __nv_bfloat16 hi = __float2bfloat16(w);
    float lo = w - __bfloat162float(hi);
    g_Whi[i] = hi;
    g_Wlo[i] = __float2bfloat16(lo);
    if (c == 0) g_ball[m] = b;
}

// ---------------- X pre-convert: fp32 -> bf16 hi/lo planar ----------------
__global__ __launch_bounds__(256)
void xconv_kernel(const float* __restrict__ X)
{
    size_t i = ((size_t)blockIdx.x * 256 + threadIdx.x) * 4;
    float4 v = *(const float4*)&X[i];
    uint32_t lo0, hi0 = pack_hilo(v.x, v.y, lo0);
    uint32_t lo1, hi1 = pack_hilo(v.z, v.w, lo1);
    *(uint2*)&g_Xhi[i] = make_uint2(hi0, hi1);
    *(uint2*)&g_Xlo[i] = make_uint2(lo0, lo1);
}

// ---------------- fused QKV projection: cp.async double-buffered HMMA ----------------
#define OAH 0
#define OAL 10240
#define OBH 20480
#define OBL 29184
#define BUFSZ 37888
#define PROJ_SMEM (2*BUFSZ)   // 75776

__device__ __forceinline__ void store_proj(int b, int mg, int p, float v0, float v1) {
    if (mg >= 320) return;
    float bv = g_ball[mg];
    uint32_t lo;
    uint32_t hi = pack_hilo(v0 + bv, v1 + bv, lo);
    __nv_bfloat16 *dh, *dl;
    size_t idx;
    if (mg < 32)      { dh = g_qhi; dl = g_qlo; idx = (size_t)(b*CQ + mg) * HW + p; }
    else if (mg < 64) { dh = g_khi; dl = g_klo; idx = (size_t)(b*CQ + mg - 32) * HW + p; }
    else              { dh = g_vhi; dl = g_vlo; idx = (size_t)(b*CC + mg - 64) * HW + p; }
    *(uint32_t*)&dh[idx] = hi;
    *(uint32_t*)&dl[idx] = lo;
}

__global__ __launch_bounds__(256, 2)
void qkv_mma_kernel()
{
    extern __shared__ char smem[];
    uint32_t sbase = smem_u32(smem);

    int tid = threadIdx.x, lane = tid & 31, wid = tid >> 5;
    int wm = wid >> 2, wn = wid & 3;          // warp grid 2(m) x 4(n)
    int r = lane >> 2, tg = lane & 3;
    // m fastest in grid.x so 3 CTAs sharing an X tile are adjacent (L2 reuse)
    int m0 = blockIdx.x * 128, p0 = blockIdx.y * 128, bb = blockIdx.z;

    float acc[4][4][4];
#pragma unroll
    for (int mf=0; mf<4; mf++)
#pragma unroll
        for (int nf=0; nf<4; nf++)
#pragma unroll
            for (int j=0; j<4; j++) acc[mf][nf][j] = 0.f;

    auto load_chunk = [&](int ck, int buf) {
        uint32_t base = sbase + buf*BUFSZ;
#pragma unroll
        for (int t = 0; t < 4; t++) {            // A: 1024 granules (hi+lo)
            int item = t*256 + tid;
            int half = item >> 9, m = (item >> 2) & 127, g = item & 3;
            uint32_t dst = base + (half ? OAL : OAH) + m*80 + g*16;
            const __nv_bfloat16* src = (half ? g_Wlo : g_Whi)
                                     + (size_t)(m0 + m)*CC + ck*32 + g*8;
            CP_ASYNC16(dst, src);
        }
#pragma unroll
        for (int t = 0; t < 4; t++) {            // B: 1024 granules (hi+lo)
            int item = t*256 + tid;
            int half = item >> 9, k = (item >> 4) & 31, g = item & 15;
            uint32_t dst = base + (half ? OBL : OBH) + k*272 + g*16;
            const __nv_bfloat16* src = (half ? g_Xlo : g_Xhi)
                                     + ((size_t)(bb*CC + ck*32 + k))*P + p0 + g*8;
            CP_ASYNC16(dst, src);
        }
    };

    load_chunk(0, 0);
    CP_COMMIT();

    for (int ck = 0; ck < 8; ck++) {
        if (ck < 7) load_chunk(ck + 1, (ck + 1) & 1);
        CP_COMMIT();
        CP_WAIT1();
        __syncthreads();

        uint32_t base = sbase + (ck & 1)*BUFSZ;
#pragma unroll
        for (int s = 0; s < 2; s++) {
            uint32_t bh[4][2], bl[4][2];
#pragma unroll
            for (int pr = 0; pr < 2; pr++) {
                uint32_t ab = base + OBH + (uint32_t)((s*16 + (lane & 15))*272
                             + (wn*32 + pr*16 + (lane >> 4)*8)*2);
                uint32_t t4h[4], t4l[4];
                ldsm4t(t4h, ab);
                ldsm4t(t4l, ab + (OBL - OBH));
                bh[2*pr][0]=t4h[0]; bh[2*pr][1]=t4h[1]; bh[2*pr+1][0]=t4h[2]; bh[2*pr+1][1]=t4h[3];
                bl[2*pr][0]=t4l[0]; bl[2*pr][1]=t4l[1]; bl[2*pr+1][0]=t4l[2]; bl[2*pr+1][1]=t4l[3];
            }
#pragma unroll
            for (int mf = 0; mf < 4; mf++) {
                uint32_t aa = base + OAH + (uint32_t)((wm*64 + mf*16 + (lane & 15))*80
                             + s*32 + (lane >> 4)*16);
                uint32_t ah[4], al[4];
                ldsm4(ah, aa);
                ldsm4(al, aa + (OAL - OAH));
#pragma unroll
                for (int nf = 0; nf < 4; nf++) {
                    mma_bf16(acc[mf][nf], ah, bh[nf]);
                    mma_bf16(acc[mf][nf], ah, bl[nf]);
                    mma_bf16(acc[mf][nf], al, bh[nf]);
                }
            }
        }
        __syncthreads();
    }

#pragma unroll
    for (int mf = 0; mf < 4; mf++) {
        int mg = m0 + wm*64 + mf*16 + r;
#pragma unroll
        for (int nf = 0; nf < 4; nf++) {
            int col = p0 + wn*32 + nf*8 + 2*tg;
            store_proj(bb, mg,     col, acc[mf][nf][0], acc[mf][nf][1]);
            store_proj(bb, mg + 8, col, acc[mf][nf][2], acc[mf][nf][3]);
        }
    }
}

// ---------------- bf16 plane transpose: [plane][h][w] -> [plane][w][h] ----------------
__global__ __launch_bounds__(256)
void tranb_kernel(const __nv_bfloat16* __restrict__ shi, const __nv_bfloat16* __restrict__ slo,
                  __nv_bfloat16* __restrict__ dhi, __nv_bfloat16* __restrict__ dlo)
{
    __shared__ uint32_t t[128*67];
    const __nv_bfloat16* src = (blockIdx.y ? slo : shi) + (size_t)blockIdx.z * HW;
    __nv_bfloat16*       dst = (blockIdx.y ? dlo : dhi) + (size_t)blockIdx.z * HW;
    const uint32_t* s32 = (const uint32_t*)src;
    uint32_t*       d32 = (uint32_t*)dst;
    int tid = threadIdx.x;
#pragma unroll
    for (int i = tid; i < 8192; i += 256) {
        int h = i >> 6, wq = i & 63;
        t[h*67 + wq] = s32[i];
    }
    __syncthreads();
#pragma unroll
    for (int i = tid; i < 8192; i += 256) {
        int w = i >> 6, hq = i & 63;
        uint32_t a = t[(2*hq)*67 + (w >> 1)];
        uint32_t b = t[(2*hq+1)*67 + (w >> 1)];
        d32[i] = __byte_perm(a, b, (w & 1) ? 0x7632 : 0x5410);
    }
}

// ---------------- attention over one line (all-HMMA, cp.async staging) ----------------
// smem (bytes): VH [64][272] 0..17408 | VL 17408..34816
//               P region 34816.. : PH [128][272] 34816..69632 | PL 69632..104448 | ss 104448
// q/k staging overlaid on PH start (consumed in phase1 before PH written):
//   QH 34816 | QL 39168 | KH 43520 | KL 47872, each [16][272B] rows 8..15 zero
#define ATT_SMEM 104960

__global__ __launch_bounds__(256, 2)
void attn_kernel(const __nv_bfloat16* __restrict__ qhi, const __nv_bfloat16* __restrict__ qlo,
                 const __nv_bfloat16* __restrict__ khi, const __nv_bfloat16* __restrict__ klo,
                 const __nv_bfloat16* __restrict__ vhi, const __nv_bfloat16* __restrict__ vlo,
                 const float* __restrict__ scr, const float* __restrict__ x,
                 const float* __restrict__ gamma, float* __restrict__ outp, int mode)
{
    extern __shared__ char smc[];
    const uint32_t OVH = 0, OVL = 17408, OPH = 34816, OPL = 69632, OSS = 104448;
    const uint32_t OQK = 34816;                 // 4 mats x 4352B
    uint32_t sb = smem_u32(smc);
    uint32_t* PH = (uint32_t*)(smc + OPH);
    uint32_t* PL = (uint32_t*)(smc + OPL);
    float*    ss = (float*)(smc + OSS);

    int tid = threadIdx.x;
    int row = blockIdx.x;
    int bh  = blockIdx.y;
    int b   = bh >> 2, hd = bh & 3;
    int lane = tid & 31, wid = tid >> 5;

    size_t qoff = ((size_t)(b*CQ + hd*8 ))*HW + (size_t)row*WW;
    size_t voff = ((size_t)(b*CC + hd*64))*HW + (size_t)row*WW;

    // ---- group 0: q,k hi/lo (4 mats x 8 rows x 256B) ----
    {
        const __nv_bfloat16* srcs[4] = {qhi, qlo, khi, klo};
#pragma unroll
        for (int i = tid; i < 512; i += 256) {
            int mat = i >> 7, rem = i & 127, c = rem >> 4, g = rem & 15;
            uint32_t dst = sb + OQK + mat*4352 + c*272 + g*16;
            CP_ASYNC16(dst, srcs[mat] + qoff + (size_t)c*HW + g*8);
        }
    }
    CP_COMMIT();
    // ---- group 1: v hi/lo (64 rows x 256B each) ----
#pragma unroll
    for (int i = tid; i < 2048; i += 256) {
        int half = i >> 10, rem = i & 1023, c = rem >> 4, g = rem & 15;
        uint32_t dst = sb + (half ? OVL : OVH) + c*272 + g*16;
        CP_ASYNC16(dst, (half ? vlo : vhi) + voff + (size_t)c*HW + g*8);
    }
    CP_COMMIT();
    // ---- zero rows 8..15 of the 4 q/k mats (K padded 8 -> 16) ----
#pragma unroll
    for (int i = tid; i < 2048; i += 256) {
        int mat = i >> 9, rem = i & 511, r8 = rem >> 6, u = rem & 63;
        *(uint32_t*)(smc + OQK + mat*4352 + (8 + r8)*272 + u*4) = 0;
    }
    CP_WAIT1();          // q,k landed (v may still be in flight)
    __syncthreads();

    // ---- phase 1: E[w][kv] = q^T k via HMMA, frags via ldmatrix.trans ----
    int w0 = wid * 16;
    float e[16][4];
#pragma unroll
    for (int nf=0; nf<16; nf++)
#pragma unroll
        for (int j=0; j<4; j++) e[nf][j] = 0.f;
    {
        int l7 = lane & 7, g = lane >> 3;
        // A (q): tiles a0..a3 = (m-half g&1, k-half g>>1)
        uint32_t aa = sb + OQK + (uint32_t)(((g >> 1)*8 + l7)*272 + (w0 + (g & 1)*8)*2);
        uint32_t aqh[4], aql[4];
        ldsm4t(aqh, aa);
        ldsm4t(aql, aa + 4352);
#pragma unroll
        for (int t = 0; t < 8; t++) {
            // B (k): r0=(k0-7,n0-7) r1=(k8-15,n0-7) r2=(k0-7,n8-15) r3=(k8-15,n8-15)
            uint32_t ba = sb + OQK + 2*4352
                        + (uint32_t)(((g & 1)*8 + l7)*272 + (t*16 + (g >> 1)*8)*2);
            uint32_t bh4[4], bl4[4];
            ldsm4t(bh4, ba);
            ldsm4t(bl4, ba + 4352);
            uint32_t B0h[2] = {bh4[0], bh4[1]}, B1h[2] = {bh4[2], bh4[3]};
            uint32_t B0l[2] = {bl4[0], bl4[1]}, B1l[2] = {bl4[2], bl4[3]};
            mma_bf16(e[2*t],   aqh, B0h);
            mma_bf16(e[2*t],   aqh, B0l);
            mma_bf16(e[2*t],   aql, B0h);
            mma_bf16(e[2*t+1], aqh, B1h);
            mma_bf16(e[2*t+1], aqh, B1l);
            mma_bf16(e[2*t+1], aql, B1h);
        }
    }
    __syncthreads();   // q/k staging reads complete before P region overwritten

    // ---- phase 2: softmax in registers; pack straight to P hi/lo ----
    {
        int r = lane >> 2, tg = lane & 3;
        float mx0 = -1e30f, mx1 = -1e30f;
#pragma unroll
        for (int nf = 0; nf < 16; nf++) {
            mx0 = fmaxf(mx0, fmaxf(e[nf][0], e[nf][1]));
            mx1 = fmaxf(mx1, fmaxf(e[nf][2], e[nf][3]));
        }
        mx0 = fmaxf(mx0, __shfl_xor_sync(0xFFFFFFFF, mx0, 1));
        mx0 = fmaxf(mx0, __shfl_xor_sync(0xFFFFFFFF, mx0, 2));
        mx1 = fmaxf(mx1, __shfl_xor_sync(0xFFFFFFFF, mx1, 1));
        mx1 = fmaxf(mx1, __shfl_xor_sync(0xFFFFFFFF, mx1, 2));
        float s0 = 0.f, s1 = 0.f;
#pragma unroll
        for (int nf = 0; nf < 16; nf++) {
            e[nf][0] = __expf(e[nf][0] - mx0);
            e[nf][1] = __expf(e[nf][1] - mx0);
            e[nf][2] = __expf(e[nf][2] - mx1);
            e[nf][3] = __expf(e[nf][3] - mx1);
            s0 += e[nf][0] + e[nf][1];
            s1 += e[nf][2] + e[nf][3];
        }
        s0 += __shfl_xor_sync(0xFFFFFFFF, s0, 1);
        s0 += __shfl_xor_sync(0xFFFFFFFF, s0, 2);
        s1 += __shfl_xor_sync(0xFFFFFFFF, s1, 1);
        s1 += __shfl_xor_sync(0xFFFFFFFF, s1, 2);
        if (tg == 0) {
            ss[w0 + r]     = 1.0f / s0;
            ss[w0 + r + 8] = 1.0f / s1;
        }
#pragma unroll
        for (int nf = 0; nf < 16; nf++) {
            uint32_t lo0, hi0 = pack_hilo(e[nf][0], e[nf][1], lo0);
            uint32_t lo1, hi1 = pack_hilo(e[nf][2], e[nf][3], lo1);
            PH[(w0 + r)*68     + nf*4 + tg] = hi0;
            PL[(w0 + r)*68     + nf*4 + tg] = lo0;
            PH[(w0 + r + 8)*68 + nf*4 + tg] = hi1;
            PL[(w0 + r + 8)*68 + nf*4 + tg] = lo1;
        }
    }
    CP_WAIT0();          // v landed
    __syncthreads();

    // ---- phase 3: O[c][w] = (V P^T) * ss[w] via HMMA + ldmatrix ----
    {
        int wm = wid >> 2, wn = wid & 3;      // 2(m=c) x 4(n=w)
        int r = lane >> 2, tg = lane & 3;
        int lr = lane & 7, grp = lane >> 3;

        float acc[2][4][4];
#pragma unroll
        for (int mf=0; mf<2; mf++)
#pragma unroll
            for (int nf=0; nf<4; nf++)
#pragma unroll
                for (int j=0; j<4; j++) acc[mf][nf][j] = 0.f;

#pragma unroll
        for (int s = 0; s < 8; s++) {
            uint32_t bh2[4][2], bl2[4][2];
#pragma unroll
            for (int nf = 0; nf < 4; nf++) {
                uint32_t ab = sb + OPH + (uint32_t)(((wn*32 + nf*8) + lr)*68 + s*8 + ((lane>>3)&1)*4)*4;
                ldsm2(bh2[nf], ab);
                ldsm2(bl2[nf], ab + (OPL - OPH));
            }
#pragma unroll
            for (int mf = 0; mf < 2; mf++) {
                uint32_t aa = sb + OVH + (uint32_t)((wm*32 + mf*16 + lr + (grp&1)*8)*68 + s*8 + (grp>>1)*4)*4;
                uint32_t ah[4], al[4];
                ldsm4(ah, aa);
                ldsm4(al, aa + (OVL - OVH));
#pragma unroll
                for (int nf=0; nf<4; nf++) {
                    mma_bf16(acc[mf][nf], ah, bh2[nf]);
                    mma_bf16(acc[mf][nf], ah, bl2[nf]);
                    mma_bf16(acc[mf][nf], al, bh2[nf]);
                }
            }
        }

        float g = gamma[0];
#pragma unroll
        for (int mf = 0; mf < 2; mf++) {
            int ch = wm*32 + mf*16 + r;
#pragma unroll
            for (int nf = 0; nf < 4; nf++) {
                int wcol = wn*32 + nf*8 + 2*tg;
                float s0 = ss[wcol], s1 = ss[wcol+1];
                const float* a = acc[mf][nf];
                size_t base0 = ((size_t)(b*CC + hd*64 + ch    )*HH + row)*WW + wcol;
                size_t base1 = ((size_t)(b*CC + hd*64 + ch + 8)*HH + row)*WW + wcol;
                if (mode == 0) {
                    *(float2*)&outp[base0] = make_float2(a[0]*s0, a[1]*s1);
                    *(float2*)&outp[base1] = make_float2(a[2]*s0, a[3]*s1);
                } else {
                    float2 sc0 = *(const float2*)&scr[base0];
                    float2 x0  = *(const float2*)&x[base0];
                    float2 sc1 = *(const float2*)&scr[base1];
                    float2 x1  = *(const float2*)&x[base1];
                    *(float2*)&outp[base0] = make_float2(g*(a[0]*s0 + sc0.x) + x0.x,
                                                         g*(a[1]*s1 + sc0.y) + x0.y);
                    *(float2*)&outp[base1] = make_float2(g*(a[2]*s0 + sc1.x) + x1.x,
                                                         g*(a[3]*s1 + sc1.y) + x1.y);
                }
            }
        }
    }
}

// ---------------- host ----------------
extern "C" void kernel_launch(void* const* d_in, const int* in_sizes, int n_in,
                              void* d_out, int out_size)
{
    const float* x     = (const float*)d_in[0];
    const float* Wq    = (const float*)d_in[1];
    const float* bq    = (const float*)d_in[2];
    const float* Wk    = (const float*)d_in[3];
    const float* bk    = (const float*)d_in[4];
    const float* Wv    = (const float*)d_in[5];
    const float* bv    = (const float*)d_in[6];
    const float* gamma = (const float*)d_in[7];
    float* out = (float*)d_out;

    float* poh;
    cudaGetSymbolAddress((void**)&poh, g_oh);
    __nv_bfloat16 *pqh,*pql,*pkh,*pkl,*pvh,*pvl,*pqTh,*pqTl,*pkTh,*pkTl,*pvTh,*pvTl;
    cudaGetSymbolAddress((void**)&pqh,  g_qhi);  cudaGetSymbolAddress((void**)&pql,  g_qlo);
    cudaGetSymbolAddress((void**)&pkh,  g_khi);  cudaGetSymbolAddress((void**)&pkl,  g_klo);
    cudaGetSymbolAddress((void**)&pvh,  g_vhi);  cudaGetSymbolAddress((void**)&pvl,  g_vlo);
    cudaGetSymbolAddress((void**)&pqTh, g_qThi); cudaGetSymbolAddress((void**)&pqTl, g_qTlo);
    cudaGetSymbolAddress((void**)&pkTh, g_kThi); cudaGetSymbolAddress((void**)&pkTl, g_kTlo);
    cudaGetSymbolAddress((void**)&pvTh, g_vThi); cudaGetSymbolAddress((void**)&pvTl, g_vTlo);

    prep_kernel<<<(MROWS*CC + 255)/256, 256>>>(Wq, bq, Wk, bk, Wv, bv);
    xconv_kernel<<<(BB*CC*HW)/(256*4), 256>>>(x);

    cudaFuncSetAttribute(qkv_mma_kernel, cudaFuncAttributeMaxDynamicSharedMemorySize, PROJ_SMEM);
    qkv_mma_kernel<<<dim3(MROWS/128, P/128, BB), 256, PROJ_SMEM>>>();

    tranb_kernel<<<dim3(1, 2, BB*CQ), 256>>>(pqh, pql, pqTh, pqTl);
    tranb_kernel<<<dim3(1, 2, BB*CQ), 256>>>(pkh, pkl, pkTh, pkTl);
    tranb_kernel<<<dim3(1, 2, BB*CC), 256>>>(pvh, pvl, pvTh, pvTl);

    cudaFuncSetAttribute(attn_kernel, cudaFuncAttributeMaxDynamicSharedMemorySize, ATT_SMEM);
    attn_kernel<<<dim3(HH, BB*NH), 256, ATT_SMEM>>>(pqh, pql, pkh, pkl, pvh, pvl,
                                                    nullptr, nullptr, gamma, poh, 0);
    attn_kernel<<<dim3(WW, BB*NH), 256, ATT_SMEM>>>(pqTh, pqTl, pkTh, pkTl, pvTh, pvTl,
                                                    poh, x, gamma, out, 1);
}

// round 9
// speedup vs baseline: 4.7878x; 1.4021x over previous
#include <cuda_runtime.h>
#include <cuda_fp16.h>
#include <cstdint>

// Problem constants
#define BB   4
#define CC   256
#define CQ   32
#define HH   128
#define WW   128
#define NH   4
#define HW   (HH*WW)          // 16384
#define P    HW
#define MROWS 384             // fused rows: 32 q + 32 k + 256 v + 64 pad

// ---------------- scratch (device globals; no allocation) ----------------
__device__ __align__(16) float g_oh[BB*CC*HW];                 // o_h scratch (fp32)
__device__ __align__(16) __half g_Whi[MROWS*CC];
__device__ __align__(16) __half g_Wlo[MROWS*CC];
__device__ __align__(16) __half g_Xhi[BB*CC*HW];
__device__ __align__(16) __half g_Xlo[BB*CC*HW];
// projections, fp16 planar. q,k have hi/lo (energy path), v single.
__device__ __align__(16) __half g_qhi [BB*CQ*HW], g_qlo [BB*CQ*HW];
__device__ __align__(16) __half g_khi [BB*CQ*HW], g_klo [BB*CQ*HW];
__device__ __align__(16) __half g_vhi [BB*CC*HW];
__device__ __align__(16) __half g_qThi[BB*CQ*HW], g_qTlo[BB*CQ*HW];
__device__ __align__(16) __half g_kThi[BB*CQ*HW], g_kTlo[BB*CQ*HW];
__device__ __align__(16) __half g_vThi[BB*CC*HW];
__device__ float g_ball[MROWS];

// ---------------- PTX helpers (baseline PTX, compute_103-safe) ----------------
__device__ __forceinline__ uint32_t smem_u32(const void* p) {
    uint32_t a;
    asm("{ .reg .u64 t; cvta.to.shared.u64 t, %1; cvt.u32.u64 %0, t; }" : "=r"(a) : "l"(p));
    return a;
}
__device__ __forceinline__ void mma_f16(float d[4], const uint32_t a[4], const uint32_t b[2]) {
    asm volatile(
        "mma.sync.aligned.m16n8k16.row.col.f32.f16.f16.f32 "
        "{%0,%1,%2,%3}, {%4,%5,%6,%7}, {%8,%9}, {%0,%1,%2,%3};"
        : "+f"(d[0]), "+f"(d[1]), "+f"(d[2]), "+f"(d[3])
        : "r"(a[0]), "r"(a[1]), "r"(a[2]), "r"(a[3]), "r"(b[0]), "r"(b[1]));
}
__device__ __forceinline__ void ldsm4(uint32_t r[4], uint32_t addr) {
    asm volatile("ldmatrix.sync.aligned.m8n8.x4.shared.b16 {%0,%1,%2,%3}, [%4];"
        : "=r"(r[0]), "=r"(r[1]), "=r"(r[2]), "=r"(r[3]) : "r"(addr));
}
__device__ __forceinline__ void ldsm4t(uint32_t r[4], uint32_t addr) {
    asm volatile("ldmatrix.sync.aligned.m8n8.x4.trans.shared.b16 {%0,%1,%2,%3}, [%4];"
        : "=r"(r[0]), "=r"(r[1]), "=r"(r[2]), "=r"(r[3]) : "r"(addr));
}
__device__ __forceinline__ void ldsm2(uint32_t r[2], uint32_t addr) {
    asm volatile("ldmatrix.sync.aligned.m8n8.x2.shared.b16 {%0,%1}, [%2];"
        : "=r"(r[0]), "=r"(r[1]) : "r"(addr));
}
#define CP_ASYNC16(dst, src) asm volatile("cp.async.cg.shared.global [%0], [%1], 16;" :: "r"(dst), "l"(src))
#define CP_COMMIT()          asm volatile("cp.async.commit_group;")
#define CP_WAIT1()           asm volatile("cp.async.wait_group 1;")
#define CP_WAIT0()           asm volatile("cp.async.wait_group 0;")

// pack two floats to fp16 pair
__device__ __forceinline__ uint32_t pack_h2(float f0, float f1) {
    __half2 h = __floats2half2_rn(f0, f1);
    return *(uint32_t*)&h;
}
// split two floats into fp16 hi pair (returned) and lo pair (out param)
__device__ __forceinline__ uint32_t pack_hilo16(float f0, float f1, uint32_t& lo) {
    __half h0 = __float2half_rn(f0), h1 = __float2half_rn(f1);
    float l0f = f0 - __half2float(h0);
    float l1f = f1 - __half2float(h1);
    __half l0 = __float2half_rn(l0f), l1 = __float2half_rn(l1f);
    lo = (uint32_t)__half_as_ushort(l0) | ((uint32_t)__half_as_ushort(l1) << 16);
    return (uint32_t)__half_as_ushort(h0) | ((uint32_t)__half_as_ushort(h1) << 16);
}

// ---------------- weight prep ----------------
__global__ void prep_kernel(const float* __restrict__ Wq, const float* __restrict__ bq,
                            const float* __restrict__ Wk, const float* __restrict__ bk,
                            const float* __restrict__ Wv, const float* __restrict__ bv)
{
    int i = blockIdx.x * blockDim.x + threadIdx.x;
    if (i >= MROWS * CC) return;
    int m = i >> 8, c = i & 255;
    float w = 0.f, b = 0.f;
    if      (m < 32)  { w = Wq[m * CC + c];        b = bq[m];      }
    else if (m < 64)  { w = Wk[(m - 32) * CC + c]; b = bk[m - 32]; }
    else if (m < 320) { w = Wv[(m - 64) * CC + c]; b = bv[m - 64]; }
    __half hi = __float2half_rn(w);
    g_Whi[i] = hi;
    g_Wlo[i] = __float2half_rn(w - __half2float(hi));
    if (c == 0) g_ball[m] = b;
}

// ---------------- X pre-convert: fp32 -> fp16 hi/lo planar ----------------
__global__ __launch_bounds__(256)
void xconv_kernel(const float* __restrict__ X)
{
    size_t i = ((size_t)blockIdx.x * 256 + threadIdx.x) * 4;
    float4 v = *(const float4*)&X[i];
    uint32_t lo0, hi0 = pack_hilo16(v.x, v.y, lo0);
    uint32_t lo1, hi1 = pack_hilo16(v.z, v.w, lo1);
    *(uint2*)&g_Xhi[i] = make_uint2(hi0, hi1);
    *(uint2*)&g_Xlo[i] = make_uint2(lo0, lo1);
}

// ---------------- fused QKV projection: cp.async double-buffered HMMA ----------------
// m-tile 0 (q,k + v0..63): 3-product fp16 hi/lo. m-tiles 1,2 (v): single product.
#define OAH 0
#define OAL 10240
#define OBH 20480
#define OBL 29184
#define BUFSZ 37888
#define PROJ_SMEM (2*BUFSZ)   // 75776

__device__ __forceinline__ void store_proj(int b, int mg, int p, float v0, float v1) {
    if (mg >= 320) return;
    float bv = g_ball[mg];
    float f0 = v0 + bv, f1 = v1 + bv;
    if (mg < 64) {
        uint32_t lo;
        uint32_t hi = pack_hilo16(f0, f1, lo);
        size_t idx;
        __half *dh, *dl;
        if (mg < 32) { dh = g_qhi; dl = g_qlo; idx = (size_t)(b*CQ + mg) * HW + p; }
        else         { dh = g_khi; dl = g_klo; idx = (size_t)(b*CQ + mg - 32) * HW + p; }
        *(uint32_t*)&dh[idx] = hi;
        *(uint32_t*)&dl[idx] = lo;
    } else {
        size_t idx = (size_t)(b*CC + mg - 64) * HW + p;
        *(uint32_t*)&g_vhi[idx] = pack_h2(f0, f1);
    }
}

__global__ __launch_bounds__(256, 2)
void qkv_mma_kernel()
{
    extern __shared__ char smem[];
    uint32_t sbase = smem_u32(smem);

    int tid = threadIdx.x, lane = tid & 31, wid = tid >> 5;
    int wm = wid >> 2, wn = wid & 3;          // warp grid 2(m) x 4(n)
    int r = lane >> 2, tg = lane & 3;
    int m0 = blockIdx.x * 128, p0 = blockIdx.y * 128, bb = blockIdx.z;
    const bool full = (blockIdx.x == 0);      // hi/lo 3-product for q,k tile

    float acc[4][4][4];
#pragma unroll
    for (int mf=0; mf<4; mf++)
#pragma unroll
        for (int nf=0; nf<4; nf++)
#pragma unroll
            for (int j=0; j<4; j++) acc[mf][nf][j] = 0.f;

    auto load_chunk = [&](int ck, int buf) {
        uint32_t base = sbase + buf*BUFSZ;
#pragma unroll
        for (int t = 0; t < 4; t++) {            // A granules
            int item = t*256 + tid;
            int half = item >> 9, m = (item >> 2) & 127, g = item & 3;
            if (half && !full) continue;
            uint32_t dst = base + (half ? OAL : OAH) + m*80 + g*16;
            const __half* src = (half ? g_Wlo : g_Whi) + (size_t)(m0 + m)*CC + ck*32 + g*8;
            CP_ASYNC16(dst, src);
        }
#pragma unroll
        for (int t = 0; t < 4; t++) {            // B granules
            int item = t*256 + tid;
            int half = item >> 9, k = (item >> 4) & 31, g = item & 15;
            if (half && !full) continue;
            uint32_t dst = base + (half ? OBL : OBH) + k*272 + g*16;
            const __half* src = (half ? g_Xlo : g_Xhi)
                              + ((size_t)(bb*CC + ck*32 + k))*P + p0 + g*8;
            CP_ASYNC16(dst, src);
        }
    };

    load_chunk(0, 0);
    CP_COMMIT();

    for (int ck = 0; ck < 8; ck++) {
        if (ck < 7) load_chunk(ck + 1, (ck + 1) & 1);
        CP_COMMIT();
        CP_WAIT1();
        __syncthreads();

        uint32_t base = sbase + (ck & 1)*BUFSZ;
#pragma unroll
        for (int s = 0; s < 2; s++) {
            uint32_t bh[4][2], bl[4][2];
#pragma unroll
            for (int pr = 0; pr < 2; pr++) {
                uint32_t ab = base + OBH + (uint32_t)((s*16 + (lane & 15))*272
                             + (wn*32 + pr*16 + (lane >> 4)*8)*2);
                uint32_t t4h[4];
                ldsm4t(t4h, ab);
                bh[2*pr][0]=t4h[0]; bh[2*pr][1]=t4h[1]; bh[2*pr+1][0]=t4h[2]; bh[2*pr+1][1]=t4h[3];
                if (full) {
                    uint32_t t4l[4];
                    ldsm4t(t4l, ab + (OBL - OBH));
                    bl[2*pr][0]=t4l[0]; bl[2*pr][1]=t4l[1]; bl[2*pr+1][0]=t4l[2]; bl[2*pr+1][1]=t4l[3];
                }
            }
#pragma unroll
            for (int mf = 0; mf < 4; mf++) {
                uint32_t aa = base + OAH + (uint32_t)((wm*64 + mf*16 + (lane & 15))*80
                             + s*32 + (lane >> 4)*16);
                uint32_t ah[4], al[4];
                ldsm4(ah, aa);
                if (full) ldsm4(al, aa + (OAL - OAH));
#pragma unroll
                for (int nf = 0; nf < 4; nf++) {
                    mma_f16(acc[mf][nf], ah, bh[nf]);
                    if (full) {
                        mma_f16(acc[mf][nf], ah, bl[nf]);
                        mma_f16(acc[mf][nf], al, bh[nf]);
                    }
                }
            }
        }
        __syncthreads();
    }

#pragma unroll
    for (int mf = 0; mf < 4; mf++) {
        int mg = m0 + wm*64 + mf*16 + r;
#pragma unroll
        for (int nf = 0; nf < 4; nf++) {
            int col = p0 + wn*32 + nf*8 + 2*tg;
            store_proj(bb, mg,     col, acc[mf][nf][0], acc[mf][nf][1]);
            store_proj(bb, mg + 8, col, acc[mf][nf][2], acc[mf][nf][3]);
        }
    }
}

// ---------------- fp16 plane transpose: [plane][h][w] -> [plane][w][h] ----------------
__global__ __launch_bounds__(256)
void tranb_kernel(const __half* __restrict__ s0p, const __half* __restrict__ s1p,
                  __half* __restrict__ d0p, __half* __restrict__ d1p)
{
    __shared__ uint32_t t[128*67];
    const __half* src = (blockIdx.y ? s1p : s0p) + (size_t)blockIdx.z * HW;
    __half*       dst = (blockIdx.y ? d1p : d0p) + (size_t)blockIdx.z * HW;
    const uint32_t* s32 = (const uint32_t*)src;
    uint32_t*       d32 = (uint32_t*)dst;
    int tid = threadIdx.x;
#pragma unroll
    for (int i = tid; i < 8192; i += 256) {
        int h = i >> 6, wq = i & 63;
        t[h*67 + wq] = s32[i];
    }
    __syncthreads();
#pragma unroll
    for (int i = tid; i < 8192; i += 256) {
        int w = i >> 6, hq = i & 63;
        uint32_t a = t[(2*hq)*67 + (w >> 1)];
        uint32_t b = t[(2*hq+1)*67 + (w >> 1)];
        d32[i] = __byte_perm(a, b, (w & 1) ? 0x7632 : 0x5410);
    }
}

// ---------------- attention over one line ----------------
// smem (bytes): VH [64][272] 0..17408 | P [128][272] fp16 17408..52224 | ss 52224..52736
// q/k staging overlaid on P start (consumed in phase1 before P written):
//   QH 17408 | QL 21760 | KH 26112 | KL 30464, each [16][272B] rows 8..15 zero
#define ATT_SMEM 52736

__global__ __launch_bounds__(256, 3)
void attn_kernel(const __half* __restrict__ qhi, const __half* __restrict__ qlo,
                 const __half* __restrict__ khi, const __half* __restrict__ klo,
                 const __half* __restrict__ vhi,
                 const float* __restrict__ scr, const float* __restrict__ x,
                 const float* __restrict__ gamma, float* __restrict__ outp, int mode)
{
    extern __shared__ char smc[];
    const uint32_t OVH = 0, OP = 17408, OSS = 52224;
    const uint32_t OQK = 17408;                 // 4 mats x 4352B
    uint32_t sb = smem_u32(smc);
    uint32_t* PP = (uint32_t*)(smc + OP);
    float*    ss = (float*)(smc + OSS);

    int tid = threadIdx.x;
    int row = blockIdx.x;
    int bh  = blockIdx.y;
    int b   = bh >> 2, hd = bh & 3;
    int lane = tid & 31, wid = tid >> 5;

    size_t qoff = ((size_t)(b*CQ + hd*8 ))*HW + (size_t)row*WW;
    size_t voff = ((size_t)(b*CC + hd*64))*HW + (size_t)row*WW;

    // ---- group 0: q,k hi/lo (4 mats x 8 rows x 256B) ----
    {
        const __half* srcs[4] = {qhi, qlo, khi, klo};
#pragma unroll
        for (int i = tid; i < 512; i += 256) {
            int mat = i >> 7, rem = i & 127, c = rem >> 4, g = rem & 15;
            uint32_t dst = sb + OQK + mat*4352 + c*272 + g*16;
            CP_ASYNC16(dst, srcs[mat] + qoff + (size_t)c*HW + g*8);
        }
    }
    CP_COMMIT();
    // ---- group 1: v (64 rows x 256B) ----
#pragma unroll
    for (int i = tid; i < 1024; i += 256) {
        int c = i >> 4, g = i & 15;
        uint32_t dst = sb + OVH + c*272 + g*16;
        CP_ASYNC16(dst, vhi + voff + (size_t)c*HW + g*8);
    }
    CP_COMMIT();
    // ---- zero rows 8..15 of the 4 q/k mats (K padded 8 -> 16) ----
#pragma unroll
    for (int i = tid; i < 2048; i += 256) {
        int mat = i >> 9, rem = i & 511, r8 = rem >> 6, u = rem & 63;
        *(uint32_t*)(smc + OQK + mat*4352 + (8 + r8)*272 + u*4) = 0;
    }
    CP_WAIT1();          // q,k landed (v may still be in flight)
    __syncthreads();

    // ---- phase 1: E[w][kv] = q^T k via HMMA 3-product, frags via ldmatrix.trans ----
    int w0 = wid * 16;
    float e[16][4];
#pragma unroll
    for (int nf=0; nf<16; nf++)
#pragma unroll
        for (int j=0; j<4; j++) e[nf][j] = 0.f;
    {
        int l7 = lane & 7, g = lane >> 3;
        uint32_t aa = sb + OQK + (uint32_t)(((g >> 1)*8 + l7)*272 + (w0 + (g & 1)*8)*2);
        uint32_t aqh[4], aql[4];
        ldsm4t(aqh, aa);
        ldsm4t(aql, aa + 4352);
#pragma unroll
        for (int t = 0; t < 8; t++) {
            uint32_t ba = sb + OQK + 2*4352
                        + (uint32_t)(((g & 1)*8 + l7)*272 + (t*16 + (g >> 1)*8)*2);
            uint32_t bh4[4], bl4[4];
            ldsm4t(bh4, ba);
            ldsm4t(bl4, ba + 4352);
            uint32_t B0h[2] = {bh4[0], bh4[1]}, B1h[2] = {bh4[2], bh4[3]};
            uint32_t B0l[2] = {bl4[0], bl4[1]}, B1l[2] = {bl4[2], bl4[3]};
            mma_f16(e[2*t],   aqh, B0h);
            mma_f16(e[2*t],   aqh, B0l);
            mma_f16(e[2*t],   aql, B0h);
            mma_f16(e[2*t+1], aqh, B1h);
            mma_f16(e[2*t+1], aqh, B1l);
            mma_f16(e[2*t+1], aql, B1h);
        }
    }
    __syncthreads();   // staging reads complete before P region overwritten

    // ---- phase 2: softmax in registers; pack single fp16 to P ----
    {
        int r = lane >> 2, tg = lane & 3;
        float mx0 = -1e30f, mx1 = -1e30f;
#pragma unroll
        for (int nf = 0; nf < 16; nf++) {
            mx0 = fmaxf(mx0, fmaxf(e[nf][0], e[nf][1]));
            mx1 = fmaxf(mx1, fmaxf(e[nf][2], e[nf][3]));
        }
        mx0 = fmaxf(mx0, __shfl_xor_sync(0xFFFFFFFF, mx0, 1));
        mx0 = fmaxf(mx0, __shfl_xor_sync(0xFFFFFFFF, mx0, 2));
        mx1 = fmaxf(mx1, __shfl_xor_sync(0xFFFFFFFF, mx1, 1));
        mx1 = fmaxf(mx1, __shfl_xor_sync(0xFFFFFFFF, mx1, 2));
        float s0 = 0.f, s1 = 0.f;
#pragma unroll
        for (int nf = 0; nf < 16; nf++) {
            e[nf][0] = __expf(e[nf][0] - mx0);
            e[nf][1] = __expf(e[nf][1] - mx0);
            e[nf][2] = __expf(e[nf][2] - mx1);
            e[nf][3] = __expf(e[nf][3] - mx1);
            s0 += e[nf][0] + e[nf][1];
            s1 += e[nf][2] + e[nf][3];
        }
        s0 += __shfl_xor_sync(0xFFFFFFFF, s0, 1);
        s0 += __shfl_xor_sync(0xFFFFFFFF, s0, 2);
        s1 += __shfl_xor_sync(0xFFFFFFFF, s1, 1);
        s1 += __shfl_xor_sync(0xFFFFFFFF, s1, 2);
        if (tg == 0) {
            ss[w0 + r]     = 1.0f / s0;
            ss[w0 + r + 8] = 1.0f / s1;
        }
#pragma unroll
        for (int nf = 0; nf < 16; nf++) {
            PP[(w0 + r)*68     + nf*4 + tg] = pack_h2(e[nf][0], e[nf][1]);
            PP[(w0 + r + 8)*68 + nf*4 + tg] = pack_h2(e[nf][2], e[nf][3]);
        }
    }
    CP_WAIT0();          // v landed
    __syncthreads();

    // ---- phase 3: O[c][w] = (V P^T) * ss[w] single-product HMMA ----
    {
        int wm = wid >> 2, wn = wid & 3;      // 2(m=c) x 4(n=w)
        int r = lane >> 2, tg = lane & 3;
        int lr = lane & 7, grp = lane >> 3;

        float acc[2][4][4];
#pragma unroll
        for (int mf=0; mf<2; mf++)
#pragma unroll
            for (int nf=0; nf<4; nf++)
#pragma unroll
                for (int j=0; j<4; j++) acc[mf][nf][j] = 0.f;

#pragma unroll
        for (int s = 0; s < 8; s++) {
            uint32_t bp[4][2];
#pragma unroll
            for (int nf = 0; nf < 4; nf++) {
                uint32_t ab = sb + OP + (uint32_t)(((wn*32 + nf*8) + lr)*68 + s*8 + ((lane>>3)&1)*4)*4;
                ldsm2(bp[nf], ab);
            }
#pragma unroll
            for (int mf = 0; mf < 2; mf++) {
                uint32_t aa = sb + OVH + (uint32_t)((wm*32 + mf*16 + lr + (grp&1)*8)*68 + s*8 + (grp>>1)*4)*4;
                uint32_t ah[4];
                ldsm4(ah, aa);
#pragma unroll
                for (int nf=0; nf<4; nf++)
                    mma_f16(acc[mf][nf], ah, bp[nf]);
            }
        }

        float g = gamma[0];
#pragma unroll
        for (int mf = 0; mf < 2; mf++) {
            int ch = wm*32 + mf*16 + r;
#pragma unroll
            for (int nf = 0; nf < 4; nf++) {
                int wcol = wn*32 + nf*8 + 2*tg;
                float s0 = ss[wcol], s1 = ss[wcol+1];
                const float* a = acc[mf][nf];
                size_t base0 = ((size_t)(b*CC + hd*64 + ch    )*HH + row)*WW + wcol;
                size_t base1 = ((size_t)(b*CC + hd*64 + ch + 8)*HH + row)*WW + wcol;
                if (mode == 0) {
                    *(float2*)&outp[base0] = make_float2(a[0]*s0, a[1]*s1);
                    *(float2*)&outp[base1] = make_float2(a[2]*s0, a[3]*s1);
                } else {
                    float2 sc0 = *(const float2*)&scr[base0];
                    float2 x0  = *(const float2*)&x[base0];
                    float2 sc1 = *(const float2*)&scr[base1];
                    float2 x1  = *(const float2*)&x[base1];
                    *(float2*)&outp[base0] = make_float2(g*(a[0]*s0 + sc0.x) + x0.x,
                                                         g*(a[1]*s1 + sc0.y) + x0.y);
                    *(float2*)&outp[base1] = make_float2(g*(a[2]*s0 + sc1.x) + x1.x,
                                                         g*(a[3]*s1 + sc1.y) + x1.y);
                }
            }
        }
    }
}

// ---------------- host ----------------
extern "C" void kernel_launch(void* const* d_in, const int* in_sizes, int n_in,
                              void* d_out, int out_size)
{
    const float* x     = (const float*)d_in[0];
    const float* Wq    = (const float*)d_in[1];
    const float* bq    = (const float*)d_in[2];
    const float* Wk    = (const float*)d_in[3];
    const float* bk    = (const float*)d_in[4];
    const float* Wv    = (const float*)d_in[5];
    const float* bv    = (const float*)d_in[6];
    const float* gamma = (const float*)d_in[7];
    float* out = (float*)d_out;

    float* poh;
    cudaGetSymbolAddress((void**)&poh, g_oh);
    __half *pqh,*pql,*pkh,*pkl,*pvh,*pqTh,*pqTl,*pkTh,*pkTl,*pvTh;
    cudaGetSymbolAddress((void**)&pqh,  g_qhi);  cudaGetSymbolAddress((void**)&pql,  g_qlo);
    cudaGetSymbolAddress((void**)&pkh,  g_khi);  cudaGetSymbolAddress((void**)&pkl,  g_klo);
    cudaGetSymbolAddress((void**)&pvh,  g_vhi);
    cudaGetSymbolAddress((void**)&pqTh, g_qThi); cudaGetSymbolAddress((void**)&pqTl, g_qTlo);
    cudaGetSymbolAddress((void**)&pkTh, g_kThi); cudaGetSymbolAddress((void**)&pkTl, g_kTlo);
    cudaGetSymbolAddress((void**)&pvTh, g_vThi);

    prep_kernel<<<(MROWS*CC + 255)/256, 256>>>(Wq, bq, Wk, bk, Wv, bv);
    xconv_kernel<<<(BB*CC*HW)/(256*4), 256>>>(x);

    cudaFuncSetAttribute(qkv_mma_kernel, cudaFuncAttributeMaxDynamicSharedMemorySize, PROJ_SMEM);
    qkv_mma_kernel<<<dim3(MROWS/128, P/128, BB), 256, PROJ_SMEM>>>();

    tranb_kernel<<<dim3(1, 2, BB*CQ), 256>>>(pqh, pql, pqTh, pqTl);
    tranb_kernel<<<dim3(1, 2, BB*CQ), 256>>>(pkh, pkl, pkTh, pkTl);
    tranb_kernel<<<dim3(1, 1, BB*CC), 256>>>(pvh, pvh, pvTh, pvTh);

    cudaFuncSetAttribute(attn_kernel, cudaFuncAttributeMaxDynamicSharedMemorySize, ATT_SMEM);
    attn_kernel<<<dim3(HH, BB*NH), 256, ATT_SMEM>>>(pqh, pql, pkh, pkl, pvh,
                                                    nullptr, nullptr, gamma, poh, 0);
    attn_kernel<<<dim3(WW, BB*NH), 256, ATT_SMEM>>>(pqTh, pqTl, pkTh, pkTl, pvTh,
                                                    poh, x, gamma, out, 1);
}

// round 10
// speedup vs baseline: 6.7981x; 1.4199x over previous
#include <cuda_runtime.h>
#include <cuda_fp16.h>
#include <cstdint>

// Problem constants
#define BB   4
#define CC   256
#define CQ   32
#define HH   128
#define WW   128
#define NH   4
#define HW   (HH*WW)          // 16384
#define P    HW
#define MROWS 384             // fused rows: 32 q + 32 k + 256 v + 64 pad

// ---------------- scratch (device globals; no allocation) ----------------
__device__ __align__(16) __half g_ohh[BB*CC*HW];               // o_h scratch (fp16)
__device__ __align__(16) __half g_Whi[MROWS*CC];
__device__ __align__(16) __half g_Xhi[BB*CC*HW];
__device__ __align__(16) __half g_qhi [BB*CQ*HW];
__device__ __align__(16) __half g_khi [BB*CQ*HW];
__device__ __align__(16) __half g_vhi [BB*CC*HW];
__device__ __align__(16) __half g_qThi[BB*CQ*HW];
__device__ __align__(16) __half g_kThi[BB*CQ*HW];
__device__ __align__(16) __half g_vThi[BB*CC*HW];
__device__ float g_ball[MROWS];

// ---------------- PTX helpers (baseline PTX, compute_103-safe) ----------------
__device__ __forceinline__ uint32_t smem_u32(const void* p) {
    uint32_t a;
    asm("{ .reg .u64 t; cvta.to.shared.u64 t, %1; cvt.u32.u64 %0, t; }" : "=r"(a) : "l"(p));
    return a;
}
__device__ __forceinline__ void mma_f16(float d[4], const uint32_t a[4], const uint32_t b[2]) {
    asm volatile(
        "mma.sync.aligned.m16n8k16.row.col.f32.f16.f16.f32 "
        "{%0,%1,%2,%3}, {%4,%5,%6,%7}, {%8,%9}, {%0,%1,%2,%3};"
        : "+f"(d[0]), "+f"(d[1]), "+f"(d[2]), "+f"(d[3])
        : "r"(a[0]), "r"(a[1]), "r"(a[2]), "r"(a[3]), "r"(b[0]), "r"(b[1]));
}
__device__ __forceinline__ void ldsm4(uint32_t r[4], uint32_t addr) {
    asm volatile("ldmatrix.sync.aligned.m8n8.x4.shared.b16 {%0,%1,%2,%3}, [%4];"
        : "=r"(r[0]), "=r"(r[1]), "=r"(r[2]), "=r"(r[3]) : "r"(addr));
}
__device__ __forceinline__ void ldsm4t(uint32_t r[4], uint32_t addr) {
    asm volatile("ldmatrix.sync.aligned.m8n8.x4.trans.shared.b16 {%0,%1,%2,%3}, [%4];"
        : "=r"(r[0]), "=r"(r[1]), "=r"(r[2]), "=r"(r[3]) : "r"(addr));
}
__device__ __forceinline__ void ldsm2(uint32_t r[2], uint32_t addr) {
    asm volatile("ldmatrix.sync.aligned.m8n8.x2.shared.b16 {%0,%1}, [%2];"
        : "=r"(r[0]), "=r"(r[1]) : "r"(addr));
}
#define CP_ASYNC16(dst, src) asm volatile("cp.async.cg.shared.global [%0], [%1], 16;" :: "r"(dst), "l"(src))
#define CP_COMMIT()          asm volatile("cp.async.commit_group;")
#define CP_WAIT1()           asm volatile("cp.async.wait_group 1;")
#define CP_WAIT0()           asm volatile("cp.async.wait_group 0;")

// pack two floats to fp16 pair
__device__ __forceinline__ uint32_t pack_h2(float f0, float f1) {
    __half2 h = __floats2half2_rn(f0, f1);
    return *(uint32_t*)&h;
}

// ---------------- weight prep ----------------
__global__ void prep_kernel(const float* __restrict__ Wq, const float* __restrict__ bq,
                            const float* __restrict__ Wk, const float* __restrict__ bk,
                            const float* __restrict__ Wv, const float* __restrict__ bv)
{
    int i = blockIdx.x * blockDim.x + threadIdx.x;
    if (i >= MROWS * CC) return;
    int m = i >> 8, c = i & 255;
    float w = 0.f, b = 0.f;
    if      (m < 32)  { w = Wq[m * CC + c];        b = bq[m];      }
    else if (m < 64)  { w = Wk[(m - 32) * CC + c]; b = bk[m - 32]; }
    else if (m < 320) { w = Wv[(m - 64) * CC + c]; b = bv[m - 64]; }
    g_Whi[i] = __float2half_rn(w);
    if (c == 0) g_ball[m] = b;
}

// ---------------- X pre-convert: fp32 -> fp16 planar ----------------
__global__ __launch_bounds__(256)
void xconv_kernel(const float* __restrict__ X)
{
    size_t i = ((size_t)blockIdx.x * 256 + threadIdx.x) * 4;
    float4 v = *(const float4*)&X[i];
    *(uint2*)&g_Xhi[i] = make_uint2(pack_h2(v.x, v.y), pack_h2(v.z, v.w));
}

// ---------------- fused QKV projection: cp.async double-buffered HMMA ----------------
#define OAH 0
#define OBH 10240
#define BUFSZ 18944
#define PROJ_SMEM (2*BUFSZ)   // 37888

__device__ __forceinline__ void store_proj(int b, int mg, int p, float v0, float v1) {
    if (mg >= 320) return;
    float bv = g_ball[mg];
    uint32_t hv = pack_h2(v0 + bv, v1 + bv);
    __half* dh;
    size_t idx;
    if (mg < 32)      { dh = g_qhi; idx = (size_t)(b*CQ + mg) * HW + p; }
    else if (mg < 64) { dh = g_khi; idx = (size_t)(b*CQ + mg - 32) * HW + p; }
    else              { dh = g_vhi; idx = (size_t)(b*CC + mg - 64) * HW + p; }
    *(uint32_t*)&dh[idx] = hv;
}

__global__ __launch_bounds__(256, 2)
void qkv_mma_kernel()
{
    extern __shared__ char smem[];
    uint32_t sbase = smem_u32(smem);

    int tid = threadIdx.x, lane = tid & 31, wid = tid >> 5;
    int wm = wid >> 2, wn = wid & 3;          // warp grid 2(m) x 4(n)
    int r = lane >> 2, tg = lane & 3;
    int m0 = blockIdx.x * 128, p0 = blockIdx.y * 128, bb = blockIdx.z;

    float acc[4][4][4];
#pragma unroll
    for (int mf=0; mf<4; mf++)
#pragma unroll
        for (int nf=0; nf<4; nf++)
#pragma unroll
            for (int j=0; j<4; j++) acc[mf][nf][j] = 0.f;

    auto load_chunk = [&](int ck, int buf) {
        uint32_t base = sbase + buf*BUFSZ;
#pragma unroll
        for (int t = 0; t < 2; t++) {            // A: 512 granules
            int item = t*256 + tid;
            int m = item >> 2, g = item & 3;
            uint32_t dst = base + OAH + m*80 + g*16;
            CP_ASYNC16(dst, g_Whi + (size_t)(m0 + m)*CC + ck*32 + g*8);
        }
#pragma unroll
        for (int t = 0; t < 2; t++) {            // B: 512 granules
            int item = t*256 + tid;
            int k = item >> 4, g = item & 15;
            uint32_t dst = base + OBH + k*272 + g*16;
            CP_ASYNC16(dst, g_Xhi + ((size_t)(bb*CC + ck*32 + k))*P + p0 + g*8);
        }
    };

    load_chunk(0, 0);
    CP_COMMIT();

    for (int ck = 0; ck < 8; ck++) {
        if (ck < 7) load_chunk(ck + 1, (ck + 1) & 1);
        CP_COMMIT();
        CP_WAIT1();
        __syncthreads();

        uint32_t base = sbase + (ck & 1)*BUFSZ;
#pragma unroll
        for (int s = 0; s < 2; s++) {
            uint32_t bh[4][2];
#pragma unroll
            for (int pr = 0; pr < 2; pr++) {
                uint32_t ab = base + OBH + (uint32_t)((s*16 + (lane & 15))*272
                             + (wn*32 + pr*16 + (lane >> 4)*8)*2);
                uint32_t t4h[4];
                ldsm4t(t4h, ab);
                bh[2*pr][0]=t4h[0]; bh[2*pr][1]=t4h[1]; bh[2*pr+1][0]=t4h[2]; bh[2*pr+1][1]=t4h[3];
            }
#pragma unroll
            for (int mf = 0; mf < 4; mf++) {
                uint32_t aa = base + OAH + (uint32_t)((wm*64 + mf*16 + (lane & 15))*80
                             + s*32 + (lane >> 4)*16);
                uint32_t ah[4];
                ldsm4(ah, aa);
#pragma unroll
                for (int nf = 0; nf < 4; nf++)
                    mma_f16(acc[mf][nf], ah, bh[nf]);
            }
        }
        __syncthreads();
    }

#pragma unroll
    for (int mf = 0; mf < 4; mf++) {
        int mg = m0 + wm*64 + mf*16 + r;
#pragma unroll
        for (int nf = 0; nf < 4; nf++) {
            int col = p0 + wn*32 + nf*8 + 2*tg;
            store_proj(bb, mg,     col, acc[mf][nf][0], acc[mf][nf][1]);
            store_proj(bb, mg + 8, col, acc[mf][nf][2], acc[mf][nf][3]);
        }
    }
}

// ---------------- fused fp16 plane transpose: q|k|v in one launch ----------------
// blockIdx.x: 0..127 q planes, 128..255 k planes, 256..1279 v planes
__global__ __launch_bounds__(256)
void tranb_kernel()
{
    __shared__ uint32_t t[128*67];
    int pz = blockIdx.x;
    const __half* src;
    __half* dst;
    if (pz < 128)      { src = g_qhi + (size_t)pz * HW;         dst = g_qThi + (size_t)pz * HW; }
    else if (pz < 256) { src = g_khi + (size_t)(pz-128) * HW;   dst = g_kThi + (size_t)(pz-128) * HW; }
    else               { src = g_vhi + (size_t)(pz-256) * HW;   dst = g_vThi + (size_t)(pz-256) * HW; }
    const uint32_t* s32 = (const uint32_t*)src;
    uint32_t*       d32 = (uint32_t*)dst;
    int tid = threadIdx.x;
#pragma unroll
    for (int i = tid; i < 8192; i += 256) {
        int h = i >> 6, wq = i & 63;
        t[h*67 + wq] = s32[i];
    }
    __syncthreads();
#pragma unroll
    for (int i = tid; i < 8192; i += 256) {
        int w = i >> 6, hq = i & 63;
        uint32_t a = t[(2*hq)*67 + (w >> 1)];
        uint32_t b = t[(2*hq+1)*67 + (w >> 1)];
        d32[i] = __byte_perm(a, b, (w & 1) ? 0x7632 : 0x5410);
    }
}

// ---------------- attention over one line ----------------
// smem (bytes): VH [64][272] 0..17408 | P [128][272] fp16 17408..52224 | ss 52224..52736
// q/k staging overlaid on P start (consumed in phase1 before P written):
//   Q 17408, K 21760, each [16][272B] rows 8..15 zero
#define ATT_SMEM 52736

__global__ __launch_bounds__(256, 3)
void attn_kernel(const __half* __restrict__ qh, const __half* __restrict__ kh,
                 const __half* __restrict__ vh,
                 const __half* __restrict__ scrH, const float* __restrict__ x,
                 const float* __restrict__ gamma,
                 float* __restrict__ outF, __half* __restrict__ outH, int mode)
{
    extern __shared__ char smc[];
    const uint32_t OVH = 0, OP = 17408, OSS = 52224;
    const uint32_t OQ = 17408, OK = 21760;
    uint32_t sb = smem_u32(smc);
    uint32_t* PP = (uint32_t*)(smc + OP);
    float*    ss = (float*)(smc + OSS);

    int tid = threadIdx.x;
    int row = blockIdx.x;
    int bh  = blockIdx.y;
    int b   = bh >> 2, hd = bh & 3;
    int lane = tid & 31, wid = tid >> 5;

    size_t qoff = ((size_t)(b*CQ + hd*8 ))*HW + (size_t)row*WW;
    size_t voff = ((size_t)(b*CC + hd*64))*HW + (size_t)row*WW;

    // ---- group 0: q,k (2 mats x 8 rows x 256B) ----
#pragma unroll
    for (int i = tid; i < 256; i += 256) {
        int mat = i >> 7, rem = i & 127, c = rem >> 4, g = rem & 15;
        uint32_t dst = sb + OQ + mat*4352 + c*272 + g*16;
        const __half* src = mat ? kh : qh;
        CP_ASYNC16(dst, src + qoff + (size_t)c*HW + g*8);
    }
    CP_COMMIT();
    // ---- group 1: v (64 rows x 256B) ----
#pragma unroll
    for (int i = tid; i < 1024; i += 256) {
        int c = i >> 4, g = i & 15;
        uint32_t dst = sb + OVH + c*272 + g*16;
        CP_ASYNC16(dst, vh + voff + (size_t)c*HW + g*8);
    }
    CP_COMMIT();
    // ---- zero rows 8..15 of the 2 q/k mats (K padded 8 -> 16) ----
#pragma unroll
    for (int i = tid; i < 1024; i += 256) {
        int mat = i >> 9, rem = i & 511, r8 = rem >> 6, u = rem & 63;
        *(uint32_t*)(smc + OQ + mat*4352 + (8 + r8)*272 + u*4) = 0;
    }
    CP_WAIT1();          // q,k landed (v may still be in flight)
    __syncthreads();

    // ---- phase 1: E[w][kv] = q^T k via single-product HMMA (ldmatrix.trans) ----
    int w0 = wid * 16;
    float e[16][4];
#pragma unroll
    for (int nf=0; nf<16; nf++)
#pragma unroll
        for (int j=0; j<4; j++) e[nf][j] = 0.f;
    {
        int l7 = lane & 7, g = lane >> 3;
        uint32_t aa = sb + OQ + (uint32_t)(((g >> 1)*8 + l7)*272 + (w0 + (g & 1)*8)*2);
        uint32_t aq[4];
        ldsm4t(aq, aa);
#pragma unroll
        for (int t = 0; t < 8; t++) {
            uint32_t ba = sb + OK + (uint32_t)(((g & 1)*8 + l7)*272 + (t*16 + (g >> 1)*8)*2);
            uint32_t b4[4];
            ldsm4t(b4, ba);
            uint32_t B0[2] = {b4[0], b4[1]}, B1[2] = {b4[2], b4[3]};
            mma_f16(e[2*t],   aq, B0);
            mma_f16(e[2*t+1], aq, B1);
        }
    }
    __syncthreads();   // staging reads complete before P region overwritten

    // ---- phase 2: softmax in registers; pack fp16 to P ----
    {
        int r = lane >> 2, tg = lane & 3;
        float mx0 = -1e30f, mx1 = -1e30f;
#pragma unroll
        for (int nf = 0; nf < 16; nf++) {
            mx0 = fmaxf(mx0, fmaxf(e[nf][0], e[nf][1]));
            mx1 = fmaxf(mx1, fmaxf(e[nf][2], e[nf][3]));
        }
        mx0 = fmaxf(mx0, __shfl_xor_sync(0xFFFFFFFF, mx0, 1));
        mx0 = fmaxf(mx0, __shfl_xor_sync(0xFFFFFFFF, mx0, 2));
        mx1 = fmaxf(mx1, __shfl_xor_sync(0xFFFFFFFF, mx1, 1));
        mx1 = fmaxf(mx1, __shfl_xor_sync(0xFFFFFFFF, mx1, 2));
        float s0 = 0.f, s1 = 0.f;
#pragma unroll
        for (int nf = 0; nf < 16; nf++) {
            e[nf][0] = __expf(e[nf][0] - mx0);
            e[nf][1] = __expf(e[nf][1] - mx0);
            e[nf][2] = __expf(e[nf][2] - mx1);
            e[nf][3] = __expf(e[nf][3] - mx1);
            s0 += e[nf][0] + e[nf][1];
            s1 += e[nf][2] + e[nf][3];
        }
        s0 += __shfl_xor_sync(0xFFFFFFFF, s0, 1);
        s0 += __shfl_xor_sync(0xFFFFFFFF, s0, 2);
        s1 += __shfl_xor_sync(0xFFFFFFFF, s1, 1);
        s1 += __shfl_xor_sync(0xFFFFFFFF, s1, 2);
        if (tg == 0) {
            ss[w0 + r]     = 1.0f / s0;
            ss[w0 + r + 8] = 1.0f / s1;
        }
#pragma unroll
        for (int nf = 0; nf < 16; nf++) {
            PP[(w0 + r)*68     + nf*4 + tg] = pack_h2(e[nf][0], e[nf][1]);
            PP[(w0 + r + 8)*68 + nf*4 + tg] = pack_h2(e[nf][2], e[nf][3]);
        }
    }
    CP_WAIT0();          // v landed
    __syncthreads();

    // ---- phase 3: O[c][w] = (V P^T) * ss[w] single-product HMMA ----
    {
        int wm = wid >> 2, wn = wid & 3;      // 2(m=c) x 4(n=w)
        int r = lane >> 2, tg = lane & 3;
        int lr = lane & 7, grp = lane >> 3;

        float acc[2][4][4];
#pragma unroll
        for (int mf=0; mf<2; mf++)
#pragma unroll
            for (int nf=0; nf<4; nf++)
#pragma unroll
                for (int j=0; j<4; j++) acc[mf][nf][j] = 0.f;

#pragma unroll
        for (int s = 0; s < 8; s++) {
            uint32_t bp[4][2];
#pragma unroll
            for (int nf = 0; nf < 4; nf++) {
                uint32_t ab = sb + OP + (uint32_t)(((wn*32 + nf*8) + lr)*68 + s*8 + ((lane>>3)&1)*4)*4;
                ldsm2(bp[nf], ab);
            }
#pragma unroll
            for (int mf = 0; mf < 2; mf++) {
                uint32_t aa = sb + OVH + (uint32_t)((wm*32 + mf*16 + lr + (grp&1)*8)*68 + s*8 + (grp>>1)*4)*4;
                uint32_t ah[4];
                ldsm4(ah, aa);
#pragma unroll
                for (int nf=0; nf<4; nf++)
                    mma_f16(acc[mf][nf], ah, bp[nf]);
            }
        }

        float g = gamma[0];
#pragma unroll
        for (int mf = 0; mf < 2; mf++) {
            int ch = wm*32 + mf*16 + r;
#pragma unroll
            for (int nf = 0; nf < 4; nf++) {
                int wcol = wn*32 + nf*8 + 2*tg;
                float s0 = ss[wcol], s1 = ss[wcol+1];
                const float* a = acc[mf][nf];
                size_t base0 = ((size_t)(b*CC + hd*64 + ch    )*HH + row)*WW + wcol;
                size_t base1 = ((size_t)(b*CC + hd*64 + ch + 8)*HH + row)*WW + wcol;
                if (mode == 0) {
                    *(uint32_t*)&outH[base0] = pack_h2(a[0]*s0, a[1]*s1);
                    *(uint32_t*)&outH[base1] = pack_h2(a[2]*s0, a[3]*s1);
                } else {
                    uint32_t su0 = *(const uint32_t*)&scrH[base0];
                    uint32_t su1 = *(const uint32_t*)&scrH[base1];
                    float2 sc0 = __half22float2(*(const __half2*)&su0);
                    float2 sc1 = __half22float2(*(const __half2*)&su1);
                    float2 x0  = *(const float2*)&x[base0];
                    float2 x1  = *(const float2*)&x[base1];
                    *(float2*)&outF[base0] = make_float2(g*(a[0]*s0 + sc0.x) + x0.x,
                                                         g*(a[1]*s1 + sc0.y) + x0.y);
                    *(float2*)&outF[base1] = make_float2(g*(a[2]*s0 + sc1.x) + x1.x,
                                                         g*(a[3]*s1 + sc1.y) + x1.y);
                }
            }
        }
    }
}

// ---------------- host ----------------
extern "C" void kernel_launch(void* const* d_in, const int* in_sizes, int n_in,
                              void* d_out, int out_size)
{
    const float* x     = (const float*)d_in[0];
    const float* Wq    = (const float*)d_in[1];
    const float* bq    = (const float*)d_in[2];
    const float* Wk    = (const float*)d_in[3];
    const float* bk    = (const float*)d_in[4];
    const float* Wv    = (const float*)d_in[5];
    const float* bv    = (const float*)d_in[6];
    const float* gamma = (const float*)d_in[7];
    float* out = (float*)d_out;

    __half *poh, *pqh, *pkh, *pvh, *pqTh, *pkTh, *pvTh;
    cudaGetSymbolAddress((void**)&poh,  g_ohh);
    cudaGetSymbolAddress((void**)&pqh,  g_qhi);
    cudaGetSymbolAddress((void**)&pkh,  g_khi);
    cudaGetSymbolAddress((void**)&pvh,  g_vhi);
    cudaGetSymbolAddress((void**)&pqTh, g_qThi);
    cudaGetSymbolAddress((void**)&pkTh, g_kThi);
    cudaGetSymbolAddress((void**)&pvTh, g_vThi);

    prep_kernel<<<(MROWS*CC + 255)/256, 256>>>(Wq, bq, Wk, bk, Wv, bv);
    xconv_kernel<<<(BB*CC*HW)/(256*4), 256>>>(x);

    cudaFuncSetAttribute(qkv_mma_kernel, cudaFuncAttributeMaxDynamicSharedMemorySize, PROJ_SMEM);
    qkv_mma_kernel<<<dim3(MROWS/128, P/128, BB), 256, PROJ_SMEM>>>();

    tranb_kernel<<<BB*CQ*2 + BB*CC, 256>>>();   // 1280 blocks: q|k|v planes

    cudaFuncSetAttribute(attn_kernel, cudaFuncAttributeMaxDynamicSharedMemorySize, ATT_SMEM);
    attn_kernel<<<dim3(HH, BB*NH), 256, ATT_SMEM>>>(pqh, pkh, pvh,
                                                    nullptr, nullptr, gamma, nullptr, poh, 0);
    attn_kernel<<<dim3(WW, BB*NH), 256, ATT_SMEM>>>(pqTh, pkTh, pvTh,
                                                    poh, x, gamma, out, nullptr, 1);
}

// round 11
// speedup vs baseline: 6.9396x; 1.0208x over previous
#include <cuda_runtime.h>
#include <cuda_fp16.h>
#include <cstdint>

// Problem constants
#define BB   4
#define CC   256
#define CQ   32
#define HH   128
#define WW   128
#define NH   4
#define HW   (HH*WW)          // 16384
#define P    HW
#define MROWS 384             // fused rows: 32 q + 32 k + 256 v + 64 pad

// ---------------- scratch (device globals; no allocation) ----------------
__device__ __align__(16) __half g_ohh[BB*CC*HW];               // o_h scratch (fp16)
__device__ __align__(16) __half g_Whi[MROWS*CC];
__device__ __align__(16) __half g_Xhi[BB*CC*HW];
__device__ __align__(16) __half g_qhi [BB*CQ*HW];
__device__ __align__(16) __half g_khi [BB*CQ*HW];
__device__ __align__(16) __half g_vhi [BB*CC*HW];
__device__ __align__(16) __half g_qThi[BB*CQ*HW];
__device__ __align__(16) __half g_kThi[BB*CQ*HW];
__device__ __align__(16) __half g_vThi[BB*CC*HW];
__device__ float g_ball[MROWS];

// ---------------- PTX helpers (baseline PTX, compute_103-safe) ----------------
__device__ __forceinline__ uint32_t smem_u32(const void* p) {
    uint32_t a;
    asm("{ .reg .u64 t; cvta.to.shared.u64 t, %1; cvt.u32.u64 %0, t; }" : "=r"(a) : "l"(p));
    return a;
}
__device__ __forceinline__ void mma_f16(float d[4], const uint32_t a[4], const uint32_t b[2]) {
    asm volatile(
        "mma.sync.aligned.m16n8k16.row.col.f32.f16.f16.f32 "
        "{%0,%1,%2,%3}, {%4,%5,%6,%7}, {%8,%9}, {%0,%1,%2,%3};"
        : "+f"(d[0]), "+f"(d[1]), "+f"(d[2]), "+f"(d[3])
        : "r"(a[0]), "r"(a[1]), "r"(a[2]), "r"(a[3]), "r"(b[0]), "r"(b[1]));
}
__device__ __forceinline__ void ldsm4(uint32_t r[4], uint32_t addr) {
    asm volatile("ldmatrix.sync.aligned.m8n8.x4.shared.b16 {%0,%1,%2,%3}, [%4];"
        : "=r"(r[0]), "=r"(r[1]), "=r"(r[2]), "=r"(r[3]) : "r"(addr));
}
__device__ __forceinline__ void ldsm4t(uint32_t r[4], uint32_t addr) {
    asm volatile("ldmatrix.sync.aligned.m8n8.x4.trans.shared.b16 {%0,%1,%2,%3}, [%4];"
        : "=r"(r[0]), "=r"(r[1]), "=r"(r[2]), "=r"(r[3]) : "r"(addr));
}
__device__ __forceinline__ void ldsm2(uint32_t r[2], uint32_t addr) {
    asm volatile("ldmatrix.sync.aligned.m8n8.x2.shared.b16 {%0,%1}, [%2];"
        : "=r"(r[0]), "=r"(r[1]) : "r"(addr));
}
#define CP_ASYNC16(dst, src) asm volatile("cp.async.cg.shared.global [%0], [%1], 16;" :: "r"(dst), "l"(src))
#define CP_COMMIT()          asm volatile("cp.async.commit_group;")
#define CP_WAIT2()           asm volatile("cp.async.wait_group 2;")
#define CP_WAIT1()           asm volatile("cp.async.wait_group 1;")
#define CP_WAIT0()           asm volatile("cp.async.wait_group 0;")

// pack two floats to fp16 pair
__device__ __forceinline__ uint32_t pack_h2(float f0, float f1) {
    __half2 h = __floats2half2_rn(f0, f1);
    return *(uint32_t*)&h;
}

// ---------------- weight prep ----------------
__global__ void prep_kernel(const float* __restrict__ Wq, const float* __restrict__ bq,
                            const float* __restrict__ Wk, const float* __restrict__ bk,
                            const float* __restrict__ Wv, const float* __restrict__ bv)
{
    int i = blockIdx.x * blockDim.x + threadIdx.x;
    if (i >= MROWS * CC) return;
    int m = i >> 8, c = i & 255;
    float w = 0.f, b = 0.f;
    if      (m < 32)  { w = Wq[m * CC + c];        b = bq[m];      }
    else if (m < 64)  { w = Wk[(m - 32) * CC + c]; b = bk[m - 32]; }
    else if (m < 320) { w = Wv[(m - 64) * CC + c]; b = bv[m - 64]; }
    g_Whi[i] = __float2half_rn(w);
    if (c == 0) g_ball[m] = b;
}

// ---------------- X pre-convert: fp32 -> fp16 planar (8 elems/thread) ----------------
__global__ __launch_bounds__(256)
void xconv_kernel(const float* __restrict__ X)
{
    size_t i = ((size_t)blockIdx.x * 256 + threadIdx.x) * 8;
    float4 v0 = *(const float4*)&X[i];
    float4 v1 = *(const float4*)&X[i + 4];
    *(uint4*)&g_Xhi[i] = make_uint4(pack_h2(v0.x, v0.y), pack_h2(v0.z, v0.w),
                                    pack_h2(v1.x, v1.y), pack_h2(v1.z, v1.w));
}

// ---------------- fused QKV projection: cp.async triple-buffered HMMA ----------------
#define OAH 0
#define OBH 10240
#define BUFSZ 18944
#define PROJ_SMEM (3*BUFSZ)   // 56832

__device__ __forceinline__ void store_proj(int b, int mg, int p, float v0, float v1) {
    if (mg >= 320) return;
    float bv = g_ball[mg];
    uint32_t hv = pack_h2(v0 + bv, v1 + bv);
    __half* dh;
    size_t idx;
    if (mg < 32)      { dh = g_qhi; idx = (size_t)(b*CQ + mg) * HW + p; }
    else if (mg < 64) { dh = g_khi; idx = (size_t)(b*CQ + mg - 32) * HW + p; }
    else              { dh = g_vhi; idx = (size_t)(b*CC + mg - 64) * HW + p; }
    *(uint32_t*)&dh[idx] = hv;
}

__global__ __launch_bounds__(256, 2)
void qkv_mma_kernel()
{
    extern __shared__ char smem[];
    uint32_t sbase = smem_u32(smem);

    int tid = threadIdx.x, lane = tid & 31, wid = tid >> 5;
    int wm = wid >> 2, wn = wid & 3;          // warp grid 2(m) x 4(n)
    int r = lane >> 2, tg = lane & 3;
    int m0 = blockIdx.x * 128, p0 = blockIdx.y * 128, bb = blockIdx.z;

    float acc[4][4][4];
#pragma unroll
    for (int mf=0; mf<4; mf++)
#pragma unroll
        for (int nf=0; nf<4; nf++)
#pragma unroll
            for (int j=0; j<4; j++) acc[mf][nf][j] = 0.f;

    auto load_chunk = [&](int ck, int buf) {
        uint32_t base = sbase + buf*BUFSZ;
#pragma unroll
        for (int t = 0; t < 2; t++) {            // A: 512 granules
            int item = t*256 + tid;
            int m = item >> 2, g = item & 3;
            uint32_t dst = base + OAH + m*80 + g*16;
            CP_ASYNC16(dst, g_Whi + (size_t)(m0 + m)*CC + ck*32 + g*8);
        }
#pragma unroll
        for (int t = 0; t < 2; t++) {            // B: 512 granules
            int item = t*256 + tid;
            int k = item >> 4, g = item & 15;
            uint32_t dst = base + OBH + k*272 + g*16;
            CP_ASYNC16(dst, g_Xhi + ((size_t)(bb*CC + ck*32 + k))*P + p0 + g*8);
        }
    };

    load_chunk(0, 0);
    CP_COMMIT();
    load_chunk(1, 1);
    CP_COMMIT();

    for (int ck = 0; ck < 8; ck++) {
        if (ck < 6) {
            load_chunk(ck + 2, (ck + 2) % 3);
            CP_COMMIT();
        }
        // complete group ck: pending after commit step is {ck..min(ck+2,7)}
        if (ck < 6)      CP_WAIT2();
        else if (ck == 6) CP_WAIT1();
        else              CP_WAIT0();
        __syncthreads();

        uint32_t base = sbase + (ck % 3)*BUFSZ;
#pragma unroll
        for (int s = 0; s < 2; s++) {
            uint32_t bh[4][2];
#pragma unroll
            for (int pr = 0; pr < 2; pr++) {
                uint32_t ab = base + OBH + (uint32_t)((s*16 + (lane & 15))*272
                             + (wn*32 + pr*16 + (lane >> 4)*8)*2);
                uint32_t t4h[4];
                ldsm4t(t4h, ab);
                bh[2*pr][0]=t4h[0]; bh[2*pr][1]=t4h[1]; bh[2*pr+1][0]=t4h[2]; bh[2*pr+1][1]=t4h[3];
            }
#pragma unroll
            for (int mf = 0; mf < 4; mf++) {
                uint32_t aa = base + OAH + (uint32_t)((wm*64 + mf*16 + (lane & 15))*80
                             + s*32 + (lane >> 4)*16);
                uint32_t ah[4];
                ldsm4(ah, aa);
#pragma unroll
                for (int nf = 0; nf < 4; nf++)
                    mma_f16(acc[mf][nf], ah, bh[nf]);
            }
        }
        __syncthreads();   // buffer (ck%3) free for reload at iteration ck+1
    }

#pragma unroll
    for (int mf = 0; mf < 4; mf++) {
        int mg = m0 + wm*64 + mf*16 + r;
#pragma unroll
        for (int nf = 0; nf < 4; nf++) {
            int col = p0 + wn*32 + nf*8 + 2*tg;
            store_proj(bb, mg,     col, acc[mf][nf][0], acc[mf][nf][1]);
            store_proj(bb, mg + 8, col, acc[mf][nf][2], acc[mf][nf][3]);
        }
    }
}

// ---------------- transpose one fp16 plane (device fn, runs in attn launch) ----------------
__device__ __forceinline__ void transpose_plane(char* smc, int pz)
{
    uint32_t* t = (uint32_t*)smc;            // 128*67 u32 = 34336B of dynamic smem
    const __half* src;
    __half* dst;
    if (pz < 128)      { src = g_qhi + (size_t)pz * HW;       dst = g_qThi + (size_t)pz * HW; }
    else if (pz < 256) { src = g_khi + (size_t)(pz-128) * HW; dst = g_kThi + (size_t)(pz-128) * HW; }
    else               { src = g_vhi + (size_t)(pz-256) * HW; dst = g_vThi + (size_t)(pz-256) * HW; }
    const uint32_t* s32 = (const uint32_t*)src;
    uint32_t*       d32 = (uint32_t*)dst;
    int tid = threadIdx.x;
#pragma unroll
    for (int i = tid; i < 8192; i += 256) {
        int h = i >> 6, wq = i & 63;
        t[h*67 + wq] = s32[i];
    }
    __syncthreads();
#pragma unroll
    for (int i = tid; i < 8192; i += 256) {
        int w = i >> 6, hq = i & 63;
        uint32_t a = t[(2*hq)*67 + (w >> 1)];
        uint32_t b = t[(2*hq+1)*67 + (w >> 1)];
        d32[i] = __byte_perm(a, b, (w & 1) ? 0x7632 : 0x5410);
    }
}

// ---------------- attention over one line ----------------
// 1D grid. mode 0: blocks [0,2048) attention rows -> o_h fp16; blocks [2048,3328)
// transpose q|k|v planes (independent work co-scheduled in the same launch).
// mode 1: 2048 blocks, fused epilogue to fp32 out.
// smem (bytes): VH [64][272] 0..17408 | P [128][272] fp16 17408..52224 | ss 52224..52736
// q/k staging overlaid on P start: Q 17408, K 21760, each [16][272B] rows 8..15 zero
#define ATT_SMEM 52736

__global__ __launch_bounds__(256, 3)
void attn_kernel(const __half* __restrict__ qh, const __half* __restrict__ kh,
                 const __half* __restrict__ vh,
                 const __half* __restrict__ scrH, const float* __restrict__ x,
                 const float* __restrict__ gamma,
                 float* __restrict__ outF, __half* __restrict__ outH, int mode)
{
    extern __shared__ char smc[];
    if (blockIdx.x >= 2048) {                 // mode-0 extra blocks: transpose
        transpose_plane(smc, blockIdx.x - 2048);
        return;
    }
    const uint32_t OVH = 0, OP = 17408, OSS = 52224;
    const uint32_t OQ = 17408, OK = 21760;
    uint32_t sb = smem_u32(smc);
    uint32_t* PP = (uint32_t*)(smc + OP);
    float*    ss = (float*)(smc + OSS);

    int tid = threadIdx.x;
    int row = blockIdx.x & 127;
    int bh  = blockIdx.x >> 7;
    int b   = bh >> 2, hd = bh & 3;
    int lane = tid & 31, wid = tid >> 5;

    size_t qoff = ((size_t)(b*CQ + hd*8 ))*HW + (size_t)row*WW;
    size_t voff = ((size_t)(b*CC + hd*64))*HW + (size_t)row*WW;

    // ---- group 0: q,k (2 mats x 8 rows x 256B) ----
#pragma unroll
    for (int i = tid; i < 256; i += 256) {
        int mat = i >> 7, rem = i & 127, c = rem >> 4, g = rem & 15;
        uint32_t dst = sb + OQ + mat*4352 + c*272 + g*16;
        const __half* src = mat ? kh : qh;
        CP_ASYNC16(dst, src + qoff + (size_t)c*HW + g*8);
    }
    CP_COMMIT();
    // ---- group 1: v (64 rows x 256B) ----
#pragma unroll
    for (int i = tid; i < 1024; i += 256) {
        int c = i >> 4, g = i & 15;
        uint32_t dst = sb + OVH + c*272 + g*16;
        CP_ASYNC16(dst, vh + voff + (size_t)c*HW + g*8);
    }
    CP_COMMIT();
    // ---- zero rows 8..15 of the 2 q/k mats (K padded 8 -> 16) ----
#pragma unroll
    for (int i = tid; i < 1024; i += 256) {
        int mat = i >> 9, rem = i & 511, r8 = rem >> 6, u = rem & 63;
        *(uint32_t*)(smc + OQ + mat*4352 + (8 + r8)*272 + u*4) = 0;
    }
    CP_WAIT1();          // q,k landed (v may still be in flight)
    __syncthreads();

    // ---- phase 1: E[w][kv] = q^T k via single-product HMMA (ldmatrix.trans) ----
    int w0 = wid * 16;
    float e[16][4];
#pragma unroll
    for (int nf=0; nf<16; nf++)
#pragma unroll
        for (int j=0; j<4; j++) e[nf][j] = 0.f;
    {
        int l7 = lane & 7, g = lane >> 3;
        uint32_t aa = sb + OQ + (uint32_t)(((g >> 1)*8 + l7)*272 + (w0 + (g & 1)*8)*2);
        uint32_t aq[4];
        ldsm4t(aq, aa);
#pragma unroll
        for (int t = 0; t < 8; t++) {
            uint32_t ba = sb + OK + (uint32_t)(((g & 1)*8 + l7)*272 + (t*16 + (g >> 1)*8)*2);
            uint32_t b4[4];
            ldsm4t(b4, ba);
            uint32_t B0[2] = {b4[0], b4[1]}, B1[2] = {b4[2], b4[3]};
            mma_f16(e[2*t],   aq, B0);
            mma_f16(e[2*t+1], aq, B1);
        }
    }
    __syncthreads();   // staging reads complete before P region overwritten

    // ---- phase 2: softmax in registers; pack fp16 to P ----
    {
        int r = lane >> 2, tg = lane & 3;
        float mx0 = -1e30f, mx1 = -1e30f;
#pragma unroll
        for (int nf = 0; nf < 16; nf++) {
            mx0 = fmaxf(mx0, fmaxf(e[nf][0], e[nf][1]));
            mx1 = fmaxf(mx1, fmaxf(e[nf][2], e[nf][3]));
        }
        mx0 = fmaxf(mx0, __shfl_xor_sync(0xFFFFFFFF, mx0, 1));
        mx0 = fmaxf(mx0, __shfl_xor_sync(0xFFFFFFFF, mx0, 2));
        mx1 = fmaxf(mx1, __shfl_xor_sync(0xFFFFFFFF, mx1, 1));
        mx1 = fmaxf(mx1, __shfl_xor_sync(0xFFFFFFFF, mx1, 2));
        float s0 = 0.f, s1 = 0.f;
#pragma unroll
        for (int nf = 0; nf < 16; nf++) {
            e[nf][0] = __expf(e[nf][0] - mx0);
            e[nf][1] = __expf(e[nf][1] - mx0);
            e[nf][2] = __expf(e[nf][2] - mx1);
            e[nf][3] = __expf(e[nf][3] - mx1);
            s0 += e[nf][0] + e[nf][1];
            s1 += e[nf][2] + e[nf][3];
        }
        s0 += __shfl_xor_sync(0xFFFFFFFF, s0, 1);
        s0 += __shfl_xor_sync(0xFFFFFFFF, s0, 2);
        s1 += __shfl_xor_sync(0xFFFFFFFF, s1, 1);
        s1 += __shfl_xor_sync(0xFFFFFFFF, s1, 2);
        if (tg == 0) {
            ss[w0 + r]     = 1.0f / s0;
            ss[w0 + r + 8] = 1.0f / s1;
        }
#pragma unroll
        for (int nf = 0; nf < 16; nf++) {
            PP[(w0 + r)*68     + nf*4 + tg] = pack_h2(e[nf][0], e[nf][1]);
            PP[(w0 + r + 8)*68 + nf*4 + tg] = pack_h2(e[nf][2], e[nf][3]);
        }
    }
    CP_WAIT0();          // v landed
    __syncthreads();

    // ---- phase 3: O[c][w] = (V P^T) * ss[w] single-product HMMA ----
    {
        int wm = wid >> 2, wn = wid & 3;      // 2(m=c) x 4(n=w)
        int r = lane >> 2, tg = lane & 3;
        int lr = lane & 7, grp = lane >> 3;

        float acc[2][4][4];
#pragma unroll
        for (int mf=0; mf<2; mf++)
#pragma unroll
            for (int nf=0; nf<4; nf++)
#pragma unroll
                for (int j=0; j<4; j++) acc[mf][nf][j] = 0.f;

#pragma unroll
        for (int s = 0; s < 8; s++) {
            uint32_t bp[4][2];
#pragma unroll
            for (int nf = 0; nf < 4; nf++) {
                uint32_t ab = sb + OP + (uint32_t)(((wn*32 + nf*8) + lr)*68 + s*8 + ((lane>>3)&1)*4)*4;
                ldsm2(bp[nf], ab);
            }
#pragma unroll
            for (int mf = 0; mf < 2; mf++) {
                uint32_t aa = sb + OVH + (uint32_t)((wm*32 + mf*16 + lr + (grp&1)*8)*68 + s*8 + (grp>>1)*4)*4;
                uint32_t ah[4];
                ldsm4(ah, aa);
#pragma unroll
                for (int nf=0; nf<4; nf++)
                    mma_f16(acc[mf][nf], ah, bp[nf]);
            }
        }

        float g = gamma[0];
#pragma unroll
        for (int mf = 0; mf < 2; mf++) {
            int ch = wm*32 + mf*16 + r;
#pragma unroll
            for (int nf = 0; nf < 4; nf++) {
                int wcol = wn*32 + nf*8 + 2*tg;
                float s0 = ss[wcol], s1 = ss[wcol+1];
                const float* a = acc[mf][nf];
                size_t base0 = ((size_t)(b*CC + hd*64 + ch    )*HH + row)*WW + wcol;
                size_t base1 = ((size_t)(b*CC + hd*64 + ch + 8)*HH + row)*WW + wcol;
                if (mode == 0) {
                    *(uint32_t*)&outH[base0] = pack_h2(a[0]*s0, a[1]*s1);
                    *(uint32_t*)&outH[base1] = pack_h2(a[2]*s0, a[3]*s1);
                } else {
                    uint32_t su0 = *(const uint32_t*)&scrH[base0];
                    uint32_t su1 = *(const uint32_t*)&scrH[base1];
                    float2 sc0 = __half22float2(*(const __half2*)&su0);
                    float2 sc1 = __half22float2(*(const __half2*)&su1);
                    float2 x0  = *(const float2*)&x[base0];
                    float2 x1  = *(const float2*)&x[base1];
                    *(float2*)&outF[base0] = make_float2(g*(a[0]*s0 + sc0.x) + x0.x,
                                                         g*(a[1]*s1 + sc0.y) + x0.y);
                    *(float2*)&outF[base1] = make_float2(g*(a[2]*s0 + sc1.x) + x1.x,
                                                         g*(a[3]*s1 + sc1.y) + x1.y);
                }
            }
        }
    }
}

// ---------------- host ----------------
extern "C" void kernel_launch(void* const* d_in, const int* in_sizes, int n_in,
                              void* d_out, int out_size)
{
    const float* x     = (const float*)d_in[0];
    const float* Wq    = (const float*)d_in[1];
    const float* bq    = (const float*)d_in[2];
    const float* Wk    = (const float*)d_in[3];
    const float* bk    = (const float*)d_in[4];
    const float* Wv    = (const float*)d_in[5];
    const float* bv    = (const float*)d_in[6];
    const float* gamma = (const float*)d_in[7];
    float* out = (float*)d_out;

    __half *poh, *pqh, *pkh, *pvh, *pqTh, *pkTh, *pvTh;
    cudaGetSymbolAddress((void**)&poh,  g_ohh);
    cudaGetSymbolAddress((void**)&pqh,  g_qhi);
    cudaGetSymbolAddress((void**)&pkh,  g_khi);
    cudaGetSymbolAddress((void**)&pvh,  g_vhi);
    cudaGetSymbolAddress((void**)&pqTh, g_qThi);
    cudaGetSymbolAddress((void**)&pkTh, g_kThi);
    cudaGetSymbolAddress((void**)&pvTh, g_vThi);

    prep_kernel<<<(MROWS*CC + 255)/256, 256>>>(Wq, bq, Wk, bk, Wv, bv);
    xconv_kernel<<<(BB*CC*HW)/(256*8), 256>>>(x);

    cudaFuncSetAttribute(qkv_mma_kernel, cudaFuncAttributeMaxDynamicSharedMemorySize, PROJ_SMEM);
    qkv_mma_kernel<<<dim3(MROWS/128, P/128, BB), 256, PROJ_SMEM>>>();

    cudaFuncSetAttribute(attn_kernel, cudaFuncAttributeMaxDynamicSharedMemorySize, ATT_SMEM);
    // mode 0: 2048 attention blocks + 1280 transpose blocks co-scheduled
    attn_kernel<<<2048 + BB*CQ*2 + BB*CC, 256, ATT_SMEM>>>(pqh, pkh, pvh,
                                                    nullptr, nullptr, gamma, nullptr, poh, 0);
    // mode 1: vertical pass on transposed arrays + fused epilogue
    attn_kernel<<<2048, 256, ATT_SMEM>>>(pqTh, pkTh, pvTh,
                                                    poh, x, gamma, out, nullptr, 1);
}

// round 12
// speedup vs baseline: 7.2954x; 1.0513x over previous
#include <cuda_runtime.h>
#include <cuda_fp16.h>
#include <cstdint>

// Problem constants
#define BB   4
#define CC   256
#define CQ   32
#define HH   128
#define WW   128
#define NH   4
#define HW   (HH*WW)          // 16384
#define P    HW
#define MROWS 384             // fused rows: 32 q + 32 k + 256 v + 64 pad

// ---------------- scratch (device globals; no allocation) ----------------
__device__ __align__(16) __half g_ohh[BB*CC*HW];               // o_h scratch (fp16)
__device__ __align__(16) __half g_Whi[MROWS*CC];
__device__ __align__(16) __half g_Xhi[BB*CC*HW];
__device__ __align__(16) __half g_qhi [BB*CQ*HW];
__device__ __align__(16) __half g_khi [BB*CQ*HW];
__device__ __align__(16) __half g_vhi [BB*CC*HW];
__device__ __align__(16) __half g_qThi[BB*CQ*HW];
__device__ __align__(16) __half g_kThi[BB*CQ*HW];
__device__ __align__(16) __half g_vThi[BB*CC*HW];
__device__ float g_ball[MROWS];

// ---------------- PTX helpers (baseline PTX, compute_103-safe) ----------------
__device__ __forceinline__ uint32_t smem_u32(const void* p) {
    uint32_t a;
    asm("{ .reg .u64 t; cvta.to.shared.u64 t, %1; cvt.u32.u64 %0, t; }" : "=r"(a) : "l"(p));
    return a;
}
__device__ __forceinline__ void mma_f16(float d[4], const uint32_t a[4], const uint32_t b[2]) {
    asm volatile(
        "mma.sync.aligned.m16n8k16.row.col.f32.f16.f16.f32 "
        "{%0,%1,%2,%3}, {%4,%5,%6,%7}, {%8,%9}, {%0,%1,%2,%3};"
        : "+f"(d[0]), "+f"(d[1]), "+f"(d[2]), "+f"(d[3])
        : "r"(a[0]), "r"(a[1]), "r"(a[2]), "r"(a[3]), "r"(b[0]), "r"(b[1]));
}
__device__ __forceinline__ void ldsm4(uint32_t r[4], uint32_t addr) {
    asm volatile("ldmatrix.sync.aligned.m8n8.x4.shared.b16 {%0,%1,%2,%3}, [%4];"
        : "=r"(r[0]), "=r"(r[1]), "=r"(r[2]), "=r"(r[3]) : "r"(addr));
}
__device__ __forceinline__ void ldsm4t(uint32_t r[4], uint32_t addr) {
    asm volatile("ldmatrix.sync.aligned.m8n8.x4.trans.shared.b16 {%0,%1,%2,%3}, [%4];"
        : "=r"(r[0]), "=r"(r[1]), "=r"(r[2]), "=r"(r[3]) : "r"(addr));
}
__device__ __forceinline__ void stsm4(uint32_t addr, uint32_t r0, uint32_t r1,
                                      uint32_t r2, uint32_t r3) {
    asm volatile("stmatrix.sync.aligned.m8n8.x4.shared.b16 [%0], {%1,%2,%3,%4};"
        :: "r"(addr), "r"(r0), "r"(r1), "r"(r2), "r"(r3) : "memory");
}
#define CP_ASYNC16(dst, src) asm volatile("cp.async.cg.shared.global [%0], [%1], 16;" :: "r"(dst), "l"(src))
#define CP_COMMIT()          asm volatile("cp.async.commit_group;")
#define CP_WAIT2()           asm volatile("cp.async.wait_group 2;")
#define CP_WAIT1()           asm volatile("cp.async.wait_group 1;")
#define CP_WAIT0()           asm volatile("cp.async.wait_group 0;")

// pack two floats to fp16 pair
__device__ __forceinline__ uint32_t pack_h2(float f0, float f1) {
    __half2 h = __floats2half2_rn(f0, f1);
    return *(uint32_t*)&h;
}

// ---------------- fused X pre-convert + weight prep (heterogeneous blocks) ----------------
// blocks [0,8192): xconv (8 elems/thread); blocks [8192,8576): weight prep
__global__ __launch_bounds__(256)
void xconv_prep_kernel(const float* __restrict__ X,
                       const float* __restrict__ Wq, const float* __restrict__ bq,
                       const float* __restrict__ Wk, const float* __restrict__ bk,
                       const float* __restrict__ Wv, const float* __restrict__ bv)
{
    int bx = blockIdx.x;
    if (bx < 8192) {
        size_t i = ((size_t)bx * 256 + threadIdx.x) * 8;
        float4 v0 = *(const float4*)&X[i];
        float4 v1 = *(const float4*)&X[i + 4];
        *(uint4*)&g_Xhi[i] = make_uint4(pack_h2(v0.x, v0.y), pack_h2(v0.z, v0.w),
                                        pack_h2(v1.x, v1.y), pack_h2(v1.z, v1.w));
        return;
    }
    int i = (bx - 8192) * 256 + threadIdx.x;
    if (i >= MROWS * CC) return;
    int m = i >> 8, c = i & 255;
    float w = 0.f, b = 0.f;
    if      (m < 32)  { w = Wq[m * CC + c];        b = bq[m];      }
    else if (m < 64)  { w = Wk[(m - 32) * CC + c]; b = bk[m - 32]; }
    else if (m < 320) { w = Wv[(m - 64) * CC + c]; b = bv[m - 64]; }
    g_Whi[i] = __float2half_rn(w);
    if (c == 0) g_ball[m] = b;
}

// ---------------- fused QKV projection: cp.async triple-buffered HMMA ----------------
#define OAH 0
#define OBH 10240
#define BUFSZ 18944
#define PROJ_SMEM (3*BUFSZ)   // 56832

__device__ __forceinline__ void store_proj(int b, int mg, int p, float v0, float v1) {
    if (mg >= 320) return;
    float bv = g_ball[mg];
    uint32_t hv = pack_h2(v0 + bv, v1 + bv);
    __half* dh;
    size_t idx;
    if (mg < 32)      { dh = g_qhi; idx = (size_t)(b*CQ + mg) * HW + p; }
    else if (mg < 64) { dh = g_khi; idx = (size_t)(b*CQ + mg - 32) * HW + p; }
    else              { dh = g_vhi; idx = (size_t)(b*CC + mg - 64) * HW + p; }
    *(uint32_t*)&dh[idx] = hv;
}

__global__ __launch_bounds__(256, 2)
void qkv_mma_kernel()
{
    extern __shared__ char smem[];
    uint32_t sbase = smem_u32(smem);

    int tid = threadIdx.x, lane = tid & 31, wid = tid >> 5;
    int wm = wid >> 2, wn = wid & 3;          // warp grid 2(m) x 4(n)
    int r = lane >> 2, tg = lane & 3;
    int m0 = blockIdx.x * 128, p0 = blockIdx.y * 128, bb = blockIdx.z;

    float acc[4][4][4];
#pragma unroll
    for (int mf=0; mf<4; mf++)
#pragma unroll
        for (int nf=0; nf<4; nf++)
#pragma unroll
            for (int j=0; j<4; j++) acc[mf][nf][j] = 0.f;

    auto load_chunk = [&](int ck, int buf) {
        uint32_t base = sbase + buf*BUFSZ;
#pragma unroll
        for (int t = 0; t < 2; t++) {            // A: 512 granules
            int item = t*256 + tid;
            int m = item >> 2, g = item & 3;
            uint32_t dst = base + OAH + m*80 + g*16;
            CP_ASYNC16(dst, g_Whi + (size_t)(m0 + m)*CC + ck*32 + g*8);
        }
#pragma unroll
        for (int t = 0; t < 2; t++) {            // B: 512 granules
            int item = t*256 + tid;
            int k = item >> 4, g = item & 15;
            uint32_t dst = base + OBH + k*272 + g*16;
            CP_ASYNC16(dst, g_Xhi + ((size_t)(bb*CC + ck*32 + k))*P + p0 + g*8);
        }
    };

    load_chunk(0, 0);
    CP_COMMIT();
    load_chunk(1, 1);
    CP_COMMIT();

    for (int ck = 0; ck < 8; ck++) {
        if (ck < 6) {
            load_chunk(ck + 2, (ck + 2) % 3);
            CP_COMMIT();
        }
        if (ck < 6)       CP_WAIT2();
        else if (ck == 6) CP_WAIT1();
        else              CP_WAIT0();
        __syncthreads();

        uint32_t base = sbase + (ck % 3)*BUFSZ;
#pragma unroll
        for (int s = 0; s < 2; s++) {
            uint32_t bh[4][2];
#pragma unroll
            for (int pr = 0; pr < 2; pr++) {
                uint32_t ab = base + OBH + (uint32_t)((s*16 + (lane & 15))*272
                             + (wn*32 + pr*16 + (lane >> 4)*8)*2);
                uint32_t t4h[4];
                ldsm4t(t4h, ab);
                bh[2*pr][0]=t4h[0]; bh[2*pr][1]=t4h[1]; bh[2*pr+1][0]=t4h[2]; bh[2*pr+1][1]=t4h[3];
            }
#pragma unroll
            for (int mf = 0; mf < 4; mf++) {
                uint32_t aa = base + OAH + (uint32_t)((wm*64 + mf*16 + (lane & 15))*80
                             + s*32 + (lane >> 4)*16);
                uint32_t ah[4];
                ldsm4(ah, aa);
#pragma unroll
                for (int nf = 0; nf < 4; nf++)
                    mma_f16(acc[mf][nf], ah, bh[nf]);
            }
        }
        __syncthreads();
    }

#pragma unroll
    for (int mf = 0; mf < 4; mf++) {
        int mg = m0 + wm*64 + mf*16 + r;
#pragma unroll
        for (int nf = 0; nf < 4; nf++) {
            int col = p0 + wn*32 + nf*8 + 2*tg;
            store_proj(bb, mg,     col, acc[mf][nf][0], acc[mf][nf][1]);
            store_proj(bb, mg + 8, col, acc[mf][nf][2], acc[mf][nf][3]);
        }
    }
}

// ---------------- transpose one fp16 plane (device fn, runs in attn launch) ----------------
__device__ __forceinline__ void transpose_plane(char* smc, int pz)
{
    uint32_t* t = (uint32_t*)smc;
    const __half* src;
    __half* dst;
    if (pz < 128)      { src = g_qhi + (size_t)pz * HW;       dst = g_qThi + (size_t)pz * HW; }
    else if (pz < 256) { src = g_khi + (size_t)(pz-128) * HW; dst = g_kThi + (size_t)(pz-128) * HW; }
    else               { src = g_vhi + (size_t)(pz-256) * HW; dst = g_vThi + (size_t)(pz-256) * HW; }
    const uint32_t* s32 = (const uint32_t*)src;
    uint32_t*       d32 = (uint32_t*)dst;
    int tid = threadIdx.x;
#pragma unroll
    for (int i = tid; i < 8192; i += 256) {
        int h = i >> 6, wq = i & 63;
        t[h*67 + wq] = s32[i];
    }
    __syncthreads();
#pragma unroll
    for (int i = tid; i < 8192; i += 256) {
        int w = i >> 6, hq = i & 63;
        uint32_t a = t[(2*hq)*67 + (w >> 1)];
        uint32_t b = t[(2*hq+1)*67 + (w >> 1)];
        d32[i] = __byte_perm(a, b, (w & 1) ? 0x7632 : 0x5410);
    }
}

// ---------------- attention over one line ----------------
// 1D grid. mode 0: blocks [0,2048) attention rows -> o_h fp16; blocks [2048,3328)
// transpose q|k|v planes. mode 1: 2048 blocks, fused epilogue to fp32 out.
// smem (bytes): VH [64][272] 0..17408 | P [128][272] fp16 17408..52224 | ss 52224..52736
// q/k staging overlaid on P start: Q 17408, K 21760, each [16][272B] rows 8..15 zero
#define ATT_SMEM 52736

__global__ __launch_bounds__(256, 3)
void attn_kernel(const __half* __restrict__ qh, const __half* __restrict__ kh,
                 const __half* __restrict__ vh,
                 const __half* __restrict__ scrH, const float* __restrict__ x,
                 const float* __restrict__ gamma,
                 float* __restrict__ outF, __half* __restrict__ outH, int mode)
{
    extern __shared__ char smc[];
    if (blockIdx.x >= 2048) {                 // mode-0 extra blocks: transpose
        transpose_plane(smc, blockIdx.x - 2048);
        return;
    }
    const uint32_t OVH = 0, OP = 17408, OSS = 52224;
    const uint32_t OQ = 17408, OK = 21760;
    uint32_t sb = smem_u32(smc);
    float*    ss = (float*)(smc + OSS);

    int tid = threadIdx.x;
    int row = blockIdx.x & 127;
    int bh  = blockIdx.x >> 7;
    int b   = bh >> 2, hd = bh & 3;
    int lane = tid & 31, wid = tid >> 5;
    int l7 = lane & 7, msel = lane >> 3;

    size_t qoff = ((size_t)(b*CQ + hd*8 ))*HW + (size_t)row*WW;
    size_t voff = ((size_t)(b*CC + hd*64))*HW + (size_t)row*WW;

    // ---- group 0: q,k (2 mats x 8 rows x 256B) ----
#pragma unroll
    for (int i = tid; i < 256; i += 256) {
        int mat = i >> 7, rem = i & 127, c = rem >> 4, g = rem & 15;
        uint32_t dst = sb + OQ + mat*4352 + c*272 + g*16;
        const __half* src = mat ? kh : qh;
        CP_ASYNC16(dst, src + qoff + (size_t)c*HW + g*8);
    }
    CP_COMMIT();
    // ---- group 1: v (64 rows x 256B) ----
#pragma unroll
    for (int i = tid; i < 1024; i += 256) {
        int c = i >> 4, g = i & 15;
        uint32_t dst = sb + OVH + c*272 + g*16;
        CP_ASYNC16(dst, vh + voff + (size_t)c*HW + g*8);
    }
    CP_COMMIT();
    // ---- zero rows 8..15 of the 2 q/k mats (K padded 8 -> 16) ----
#pragma unroll
    for (int i = tid; i < 1024; i += 256) {
        int mat = i >> 9, rem = i & 511, r8 = rem >> 6, u = rem & 63;
        *(uint32_t*)(smc + OQ + mat*4352 + (8 + r8)*272 + u*4) = 0;
    }
    CP_WAIT1();          // q,k landed (v may still be in flight)
    __syncthreads();

    // ---- phase 1: E[w][kv] = q^T k via single-product HMMA (ldmatrix.trans) ----
    int w0 = wid * 16;
    float e[16][4];
#pragma unroll
    for (int nf=0; nf<16; nf++)
#pragma unroll
        for (int j=0; j<4; j++) e[nf][j] = 0.f;
    {
        int g = lane >> 3;
        uint32_t aa = sb + OQ + (uint32_t)(((g >> 1)*8 + l7)*272 + (w0 + (g & 1)*8)*2);
        uint32_t aq[4];
        ldsm4t(aq, aa);
#pragma unroll
        for (int t = 0; t < 8; t++) {
            uint32_t ba = sb + OK + (uint32_t)(((g & 1)*8 + l7)*272 + (t*16 + (g >> 1)*8)*2);
            uint32_t b4[4];
            ldsm4t(b4, ba);
            uint32_t B0[2] = {b4[0], b4[1]}, B1[2] = {b4[2], b4[3]};
            mma_f16(e[2*t],   aq, B0);
            mma_f16(e[2*t+1], aq, B1);
        }
    }
    __syncthreads();   // staging reads complete before P region overwritten

    // ---- phase 2: softmax in registers; emit P via stmatrix ----
    {
        int r = lane >> 2, tg = lane & 3;
        float mx0 = -1e30f, mx1 = -1e30f;
#pragma unroll
        for (int nf = 0; nf < 16; nf++) {
            mx0 = fmaxf(mx0, fmaxf(e[nf][0], e[nf][1]));
            mx1 = fmaxf(mx1, fmaxf(e[nf][2], e[nf][3]));
        }
        mx0 = fmaxf(mx0, __shfl_xor_sync(0xFFFFFFFF, mx0, 1));
        mx0 = fmaxf(mx0, __shfl_xor_sync(0xFFFFFFFF, mx0, 2));
        mx1 = fmaxf(mx1, __shfl_xor_sync(0xFFFFFFFF, mx1, 1));
        mx1 = fmaxf(mx1, __shfl_xor_sync(0xFFFFFFFF, mx1, 2));
        float s0 = 0.f, s1 = 0.f;
#pragma unroll
        for (int nf = 0; nf < 16; nf++) {
            e[nf][0] = __expf(e[nf][0] - mx0);
            e[nf][1] = __expf(e[nf][1] - mx0);
            e[nf][2] = __expf(e[nf][2] - mx1);
            e[nf][3] = __expf(e[nf][3] - mx1);
            s0 += e[nf][0] + e[nf][1];
            s1 += e[nf][2] + e[nf][3];
        }
        s0 += __shfl_xor_sync(0xFFFFFFFF, s0, 1);
        s0 += __shfl_xor_sync(0xFFFFFFFF, s0, 2);
        s1 += __shfl_xor_sync(0xFFFFFFFF, s1, 1);
        s1 += __shfl_xor_sync(0xFFFFFFFF, s1, 2);
        if (tg == 0) {
            ss[w0 + r]     = 1.0f / s0;
            ss[w0 + r + 8] = 1.0f / s1;
        }
        // stmatrix.x4: mats = (nf, rows w0..+7), (nf, rows w0+8..+15), (nf+1, ..), (nf+1, ..)
#pragma unroll
        for (int nf = 0; nf < 16; nf += 2) {
            uint32_t addr = sb + OP + (uint32_t)((w0 + (msel & 1)*8 + l7)*272
                          + (nf + (msel >> 1))*16);
            stsm4(addr,
                  pack_h2(e[nf][0],   e[nf][1]),
                  pack_h2(e[nf][2],   e[nf][3]),
                  pack_h2(e[nf+1][0], e[nf+1][1]),
                  pack_h2(e[nf+1][2], e[nf+1][3]));
        }
    }
    CP_WAIT0();          // v landed
    __syncthreads();

    // ---- phase 3: O[c][w] = (V P^T) * ss[w] single-product HMMA ----
    {
        int wm = wid >> 2, wn = wid & 3;      // 2(m=c) x 4(n=w)
        int r = lane >> 2, tg = lane & 3;
        int lr = lane & 7, grp = lane >> 3;

        float acc[2][4][4];
#pragma unroll
        for (int mf=0; mf<2; mf++)
#pragma unroll
            for (int nf=0; nf<4; nf++)
#pragma unroll
                for (int j=0; j<4; j++) acc[mf][nf][j] = 0.f;

#pragma unroll
        for (int s = 0; s < 8; s++) {
            uint32_t bp[4][2];
#pragma unroll
            for (int nf = 0; nf < 4; nf += 2) {
                // ldsm4: mats = (nf,k0-7),(nf,k8-15),(nf+1,k0-7),(nf+1,k8-15)
                uint32_t ab = sb + OP + (uint32_t)((wn*32 + nf*8 + (msel >> 1)*8 + l7)*272
                             + (s*8 + (msel & 1)*4)*4);
                uint32_t t4[4];
                ldsm4(t4, ab);
                bp[nf][0]=t4[0]; bp[nf][1]=t4[1]; bp[nf+1][0]=t4[2]; bp[nf+1][1]=t4[3];
            }
#pragma unroll
            for (int mf = 0; mf < 2; mf++) {
                uint32_t aa = sb + OVH + (uint32_t)((wm*32 + mf*16 + lr + (grp&1)*8)*68 + s*8 + (grp>>1)*4)*4;
                uint32_t ah[4];
                ldsm4(ah, aa);
#pragma unroll
                for (int nf=0; nf<4; nf++)
                    mma_f16(acc[mf][nf], ah, bp[nf]);
            }
        }

        float g = gamma[0];
#pragma unroll
        for (int mf = 0; mf < 2; mf++) {
            int ch = wm*32 + mf*16 + r;
#pragma unroll
            for (int nf = 0; nf < 4; nf++) {
                int wcol = wn*32 + nf*8 + 2*tg;
                float s0 = ss[wcol], s1 = ss[wcol+1];
                const float* a = acc[mf][nf];
                size_t base0 = ((size_t)(b*CC + hd*64 + ch    )*HH + row)*WW + wcol;
                size_t base1 = ((size_t)(b*CC + hd*64 + ch + 8)*HH + row)*WW + wcol;
                if (mode == 0) {
                    *(uint32_t*)&outH[base0] = pack_h2(a[0]*s0, a[1]*s1);
                    *(uint32_t*)&outH[base1] = pack_h2(a[2]*s0, a[3]*s1);
                } else {
                    uint32_t su0 = *(const uint32_t*)&scrH[base0];
                    uint32_t su1 = *(const uint32_t*)&scrH[base1];
                    float2 sc0 = __half22float2(*(const __half2*)&su0);
                    float2 sc1 = __half22float2(*(const __half2*)&su1);
                    float2 x0  = *(const float2*)&x[base0];
                    float2 x1  = *(const float2*)&x[base1];
                    *(float2*)&outF[base0] = make_float2(g*(a[0]*s0 + sc0.x) + x0.x,
                                                         g*(a[1]*s1 + sc0.y) + x0.y);
                    *(float2*)&outF[base1] = make_float2(g*(a[2]*s0 + sc1.x) + x1.x,
                                                         g*(a[3]*s1 + sc1.y) + x1.y);
                }
            }
        }
    }
}

// ---------------- host ----------------
extern "C" void kernel_launch(void* const* d_in, const int* in_sizes, int n_in,
                              void* d_out, int out_size)
{
    const float* x     = (const float*)d_in[0];
    const float* Wq    = (const float*)d_in[1];
    const float* bq    = (const float*)d_in[2];
    const float* Wk    = (const float*)d_in[3];
    const float* bk    = (const float*)d_in[4];
    const float* Wv    = (const float*)d_in[5];
    const float* bv    = (const float*)d_in[6];
    const float* gamma = (const float*)d_in[7];
    float* out = (float*)d_out;

    __half *poh, *pqh, *pkh, *pvh, *pqTh, *pkTh, *pvTh;
    cudaGetSymbolAddress((void**)&poh,  g_ohh);
    cudaGetSymbolAddress((void**)&pqh,  g_qhi);
    cudaGetSymbolAddress((void**)&pkh,  g_khi);
    cudaGetSymbolAddress((void**)&pvh,  g_vhi);
    cudaGetSymbolAddress((void**)&pqTh, g_qThi);
    cudaGetSymbolAddress((void**)&pkTh, g_kThi);
    cudaGetSymbolAddress((void**)&pvTh, g_vThi);

    // fused xconv (8192 blocks) + weight prep (384 blocks)
    xconv_prep_kernel<<<8192 + 384, 256>>>(x, Wq, bq, Wk, bk, Wv, bv);

    cudaFuncSetAttribute(qkv_mma_kernel, cudaFuncAttributeMaxDynamicSharedMemorySize, PROJ_SMEM);
    qkv_mma_kernel<<<dim3(MROWS/128, P/128, BB), 256, PROJ_SMEM>>>();

    cudaFuncSetAttribute(attn_kernel, cudaFuncAttributeMaxDynamicSharedMemorySize, ATT_SMEM);
    // mode 0: 2048 attention blocks + 1280 transpose blocks co-scheduled
    attn_kernel<<<2048 + BB*CQ*2 + BB*CC, 256, ATT_SMEM>>>(pqh, pkh, pvh,
                                                    nullptr, nullptr, gamma, nullptr, poh, 0);
    // mode 1: vertical pass on transposed arrays + fused epilogue
    attn_kernel<<<2048, 256, ATT_SMEM>>>(pqTh, pkTh, pvTh,
                                                    poh, x, gamma, out, nullptr, 1);
}

// round 15
// speedup vs baseline: 7.6961x; 1.0549x over previous
#include <cuda_runtime.h>
#include <cuda_fp16.h>
#include <cstdint>

// Problem constants
#define BB   4
#define CC   256
#define CQ   32
#define HH   128
#define WW   128
#define NH   4
#define HW   (HH*WW)          // 16384
#define P    HW
#define MROWS 384             // fused rows: 32 q + 32 k + 256 v + 64 pad

// ---------------- scratch (device globals; no allocation) ----------------
__device__ __align__(16) __half g_ohh[BB*CC*HW];               // o_h scratch (fp16)
__device__ __align__(16) __half g_Whi[MROWS*CC];
__device__ __align__(16) __half g_Xhi[BB*CC*HW];
__device__ __align__(16) __half g_qhi [BB*CQ*HW];
__device__ __align__(16) __half g_khi [BB*CQ*HW];
__device__ __align__(16) __half g_vhi [BB*CC*HW];
__device__ __align__(16) __half g_qThi[BB*CQ*HW];
__device__ __align__(16) __half g_kThi[BB*CQ*HW];
__device__ __align__(16) __half g_vThi[BB*CC*HW];
__device__ float g_ball[MROWS];

// ---------------- PTX helpers (baseline PTX, compute_103-safe) ----------------
__device__ __forceinline__ uint32_t smem_u32(const void* p) {
    uint32_t a;
    asm("{ .reg .u64 t; cvta.to.shared.u64 t, %1; cvt.u32.u64 %0, t; }" : "=r"(a) : "l"(p));
    return a;
}
__device__ __forceinline__ void mma_f16(float d[4], const uint32_t a[4], const uint32_t b[2]) {
    asm volatile(
        "mma.sync.aligned.m16n8k16.row.col.f32.f16.f16.f32 "
        "{%0,%1,%2,%3}, {%4,%5,%6,%7}, {%8,%9}, {%0,%1,%2,%3};"
        : "+f"(d[0]), "+f"(d[1]), "+f"(d[2]), "+f"(d[3])
        : "r"(a[0]), "r"(a[1]), "r"(a[2]), "r"(a[3]), "r"(b[0]), "r"(b[1]));
}
__device__ __forceinline__ void ldsm4(uint32_t r[4], uint32_t addr) {
    asm volatile("ldmatrix.sync.aligned.m8n8.x4.shared.b16 {%0,%1,%2,%3}, [%4];"
        : "=r"(r[0]), "=r"(r[1]), "=r"(r[2]), "=r"(r[3]) : "r"(addr));
}
__device__ __forceinline__ void ldsm4t(uint32_t r[4], uint32_t addr) {
    asm volatile("ldmatrix.sync.aligned.m8n8.x4.trans.shared.b16 {%0,%1,%2,%3}, [%4];"
        : "=r"(r[0]), "=r"(r[1]), "=r"(r[2]), "=r"(r[3]) : "r"(addr));
}
__device__ __forceinline__ void stsm4(uint32_t addr, uint32_t r0, uint32_t r1,
                                      uint32_t r2, uint32_t r3) {
    asm volatile("stmatrix.sync.aligned.m8n8.x4.shared.b16 [%0], {%1,%2,%3,%4};"
        :: "r"(addr), "r"(r0), "r"(r1), "r"(r2), "r"(r3) : "memory");
}
#define CP_ASYNC16(dst, src) asm volatile("cp.async.cg.shared.global [%0], [%1], 16;" :: "r"(dst), "l"(src))
#define CP_COMMIT()          asm volatile("cp.async.commit_group;")
#define CP_WAIT2()           asm volatile("cp.async.wait_group 2;")
#define CP_WAIT1()           asm volatile("cp.async.wait_group 1;")
#define CP_WAIT0()           asm volatile("cp.async.wait_group 0;")

// pack two floats to fp16 pair
__device__ __forceinline__ uint32_t pack_h2(float f0, float f1) {
    __half2 h = __floats2half2_rn(f0, f1);
    return *(uint32_t*)&h;
}

// ---------------- fused X pre-convert + weight prep (heterogeneous blocks) ----------------
__global__ __launch_bounds__(256)
void xconv_prep_kernel(const float* __restrict__ X,
                       const float* __restrict__ Wq, const float* __restrict__ bq,
                       const float* __restrict__ Wk, const float* __restrict__ bk,
                       const float* __restrict__ Wv, const float* __restrict__ bv)
{
    int bx = blockIdx.x;
    if (bx < 8192) {
        size_t i = ((size_t)bx * 256 + threadIdx.x) * 8;
        float4 v0 = *(const float4*)&X[i];
        float4 v1 = *(const float4*)&X[i + 4];
        *(uint4*)&g_Xhi[i] = make_uint4(pack_h2(v0.x, v0.y), pack_h2(v0.z, v0.w),
                                        pack_h2(v1.x, v1.y), pack_h2(v1.z, v1.w));
        return;
    }
    int i = (bx - 8192) * 256 + threadIdx.x;
    if (i >= MROWS * CC) return;
    int m = i >> 8, c = i & 255;
    float w = 0.f, b = 0.f;
    if      (m < 32)  { w = Wq[m * CC + c];        b = bq[m];      }
    else if (m < 64)  { w = Wk[(m - 32) * CC + c]; b = bk[m - 32]; }
    else if (m < 320) { w = Wv[(m - 64) * CC + c]; b = bv[m - 64]; }
    g_Whi[i] = __float2half_rn(w);
    if (c == 0) g_ball[m] = b;
}

// ---------------- fused QKV projection: cp.async triple-buffered HMMA ----------------
#define OAH 0
#define OBH 10240
#define BUFSZ 18944
#define PROJ_SMEM (3*BUFSZ)   // 56832

__device__ __forceinline__ void store_proj(int b, int mg, int p, float v0, float v1) {
    if (mg >= 320) return;
    float bv = g_ball[mg];
    uint32_t hv = pack_h2(v0 + bv, v1 + bv);
    __half* dh;
    size_t idx;
    if (mg < 32)      { dh = g_qhi; idx = (size_t)(b*CQ + mg) * HW + p; }
    else if (mg < 64) { dh = g_khi; idx = (size_t)(b*CQ + mg - 32) * HW + p; }
    else              { dh = g_vhi; idx = (size_t)(b*CC + mg - 64) * HW + p; }
    *(uint32_t*)&dh[idx] = hv;
}

__global__ __launch_bounds__(256, 2)
void qkv_mma_kernel()
{
    extern __shared__ char smem[];
    uint32_t sbase = smem_u32(smem);

    int tid = threadIdx.x, lane = tid & 31, wid = tid >> 5;
    int wm = wid >> 2, wn = wid & 3;          // warp grid 2(m) x 4(n)
    int r = lane >> 2, tg = lane & 3;
    int m0 = blockIdx.x * 128, p0 = blockIdx.y * 128, bb = blockIdx.z;

    float acc[4][4][4];
#pragma unroll
    for (int mf=0; mf<4; mf++)
#pragma unroll
        for (int nf=0; nf<4; nf++)
#pragma unroll
            for (int j=0; j<4; j++) acc[mf][nf][j] = 0.f;

    auto load_chunk = [&](int ck, int buf) {
        uint32_t base = sbase + buf*BUFSZ;
#pragma unroll
        for (int t = 0; t < 2; t++) {            // A: 512 granules
            int item = t*256 + tid;
            int m = item >> 2, g = item & 3;
            uint32_t dst = base + OAH + m*80 + g*16;
            CP_ASYNC16(dst, g_Whi + (size_t)(m0 + m)*CC + ck*32 + g*8);
        }
#pragma unroll
        for (int t = 0; t < 2; t++) {            // B: 512 granules
            int item = t*256 + tid;
            int k = item >> 4, g = item & 15;
            uint32_t dst = base + OBH + k*272 + g*16;
            CP_ASYNC16(dst, g_Xhi + ((size_t)(bb*CC + ck*32 + k))*P + p0 + g*8);
        }
    };

    load_chunk(0, 0);
    CP_COMMIT();
    load_chunk(1, 1);
    CP_COMMIT();

    for (int ck = 0; ck < 8; ck++) {
        if (ck < 6) {
            load_chunk(ck + 2, (ck + 2) % 3);
            CP_COMMIT();
        }
        if (ck < 6)       CP_WAIT2();
        else if (ck == 6) CP_WAIT1();
        else              CP_WAIT0();
        __syncthreads();

        uint32_t base = sbase + (ck % 3)*BUFSZ;
#pragma unroll
        for (int s = 0; s < 2; s++) {
            uint32_t bh[4][2];
#pragma unroll
            for (int pr = 0; pr < 2; pr++) {
                uint32_t ab = base + OBH + (uint32_t)((s*16 + (lane & 15))*272
                             + (wn*32 + pr*16 + (lane >> 4)*8)*2);
                uint32_t t4h[4];
                ldsm4t(t4h, ab);
                bh[2*pr][0]=t4h[0]; bh[2*pr][1]=t4h[1]; bh[2*pr+1][0]=t4h[2]; bh[2*pr+1][1]=t4h[3];
            }
#pragma unroll
            for (int mf = 0; mf < 4; mf++) {
                uint32_t aa = base + OAH + (uint32_t)((wm*64 + mf*16 + (lane & 15))*80
                             + s*32 + (lane >> 4)*16);
                uint32_t ah[4];
                ldsm4(ah, aa);
#pragma unroll
                for (int nf = 0; nf < 4; nf++)
                    mma_f16(acc[mf][nf], ah, bh[nf]);
            }
        }
        __syncthreads();
    }

#pragma unroll
    for (int mf = 0; mf < 4; mf++) {
        int mg = m0 + wm*64 + mf*16 + r;
#pragma unroll
        for (int nf = 0; nf < 4; nf++) {
            int col = p0 + wn*32 + nf*8 + 2*tg;
            store_proj(bb, mg,     col, acc[mf][nf][0], acc[mf][nf][1]);
            store_proj(bb, mg + 8, col, acc[mf][nf][2], acc[mf][nf][3]);
        }
    }
}

// ---------------- transpose one fp16 plane (device fn, runs in attn launch) ----------------
__device__ __forceinline__ void transpose_plane(char* smc, int pz)
{
    uint32_t* t = (uint32_t*)smc;
    const __half* src;
    __half* dst;
    if (pz < 128)      { src = g_qhi + (size_t)pz * HW;       dst = g_qThi + (size_t)pz * HW; }
    else if (pz < 256) { src = g_khi + (size_t)(pz-128) * HW; dst = g_kThi + (size_t)(pz-128) * HW; }
    else               { src = g_vhi + (size_t)(pz-256) * HW; dst = g_vThi + (size_t)(pz-256) * HW; }
    const uint32_t* s32 = (const uint32_t*)src;
    uint32_t*       d32 = (uint32_t*)dst;
    int tid = threadIdx.x;
#pragma unroll
    for (int i = tid; i < 8192; i += 256) {
        int h = i >> 6, wq = i & 63;
        t[h*67 + wq] = s32[i];
    }
    __syncthreads();
#pragma unroll
    for (int i = tid; i < 8192; i += 256) {
        int w = i >> 6, hq = i & 63;
        uint32_t a = t[(2*hq)*67 + (w >> 1)];
        uint32_t b = t[(2*hq+1)*67 + (w >> 1)];
        d32[i] = __byte_perm(a, b, (w & 1) ? 0x7632 : 0x5410);
    }
}

// ---------------- attention over one line ----------------
// 1D grid. mode 0: blocks [0,2048) attention rows -> o_h fp16; blocks [2048,3328)
// transpose q|k|v planes. mode 1: 2048 blocks, fused epilogue to fp32 out.
// smem (bytes): VH [64][272] 0..17408 (reused as o-tile post-MMA)
//               P [128][272] fp16 17408..52224 | ss 52224..52736
// q/k staging overlaid on P start: Q 17408, K 21760, each [16][272B] rows 8..15 zero
#define ATT_SMEM 52736

__global__ __launch_bounds__(256, 3)
void attn_kernel(const __half* __restrict__ qh, const __half* __restrict__ kh,
                 const __half* __restrict__ vh,
                 const __half* __restrict__ scrH, const float* __restrict__ x,
                 const float* __restrict__ gamma,
                 float* __restrict__ outF, __half* __restrict__ outH, int mode)
{
    extern __shared__ char smc[];
    if (blockIdx.x >= 2048) {                 // mode-0 extra blocks: transpose
        transpose_plane(smc, blockIdx.x - 2048);
        return;
    }
    const uint32_t OVH = 0, OP = 17408, OSS = 52224;
    const uint32_t OQ = 17408, OK = 21760;
    uint32_t sb = smem_u32(smc);
    float*    ss = (float*)(smc + OSS);

    int tid = threadIdx.x;
    int row = blockIdx.x & 127;
    int bh  = blockIdx.x >> 7;
    int b   = bh >> 2, hd = bh & 3;
    int lane = tid & 31, wid = tid >> 5;
    int l7 = lane & 7, msel = lane >> 3;

    size_t qoff = ((size_t)(b*CQ + hd*8 ))*HW + (size_t)row*WW;
    size_t voff = ((size_t)(b*CC + hd*64))*HW + (size_t)row*WW;

    // ---- group 0: q,k (2 mats x 8 rows x 256B) ----
#pragma unroll
    for (int i = tid; i < 256; i += 256) {
        int mat = i >> 7, rem = i & 127, c = rem >> 4, g = rem & 15;
        uint32_t dst = sb + OQ + mat*4352 + c*272 + g*16;
        const __half* src = mat ? kh : qh;
        CP_ASYNC16(dst, src + qoff + (size_t)c*HW + g*8);
    }
    CP_COMMIT();
    // ---- group 1: v (64 rows x 256B) ----
#pragma unroll
    for (int i = tid; i < 1024; i += 256) {
        int c = i >> 4, g = i & 15;
        uint32_t dst = sb + OVH + c*272 + g*16;
        CP_ASYNC16(dst, vh + voff + (size_t)c*HW + g*8);
    }
    CP_COMMIT();
    // ---- zero rows 8..15 of the 2 q/k mats (K padded 8 -> 16) ----
#pragma unroll
    for (int i = tid; i < 1024; i += 256) {
        int mat = i >> 9, rem = i & 511, r8 = rem >> 6, u = rem & 63;
        *(uint32_t*)(smc + OQ + mat*4352 + (8 + r8)*272 + u*4) = 0;
    }
    CP_WAIT1();          // q,k landed (v may still be in flight)
    __syncthreads();

    // ---- phase 1: E[w][kv] = q^T k via single-product HMMA (ldmatrix.trans) ----
    int w0 = wid * 16;
    float e[16][4];
#pragma unroll
    for (int nf=0; nf<16; nf++)
#pragma unroll
        for (int j=0; j<4; j++) e[nf][j] = 0.f;
    {
        int g = lane >> 3;
        uint32_t aa = sb + OQ + (uint32_t)(((g >> 1)*8 + l7)*272 + (w0 + (g & 1)*8)*2);
        uint32_t aq[4];
        ldsm4t(aq, aa);
#pragma unroll
        for (int t = 0; t < 8; t++) {
            uint32_t ba = sb + OK + (uint32_t)(((g & 1)*8 + l7)*272 + (t*16 + (g >> 1)*8)*2);
            uint32_t b4[4];
            ldsm4t(b4, ba);
            uint32_t B0[2] = {b4[0], b4[1]}, B1[2] = {b4[2], b4[3]};
            mma_f16(e[2*t],   aq, B0);
            mma_f16(e[2*t+1], aq, B1);
        }
    }
    __syncthreads();   // staging reads complete before P region overwritten

    // ---- phase 2: softmax in registers; emit P via stmatrix ----
    {
        int r = lane >> 2, tg = lane & 3;
        float mx0 = -1e30f, mx1 = -1e30f;
#pragma unroll
        for (int nf = 0; nf < 16; nf++) {
            mx0 = fmaxf(mx0, fmaxf(e[nf][0], e[nf][1]));
            mx1 = fmaxf(mx1, fmaxf(e[nf][2], e[nf][3]));
        }
        mx0 = fmaxf(mx0, __shfl_xor_sync(0xFFFFFFFF, mx0, 1));
        mx0 = fmaxf(mx0, __shfl_xor_sync(0xFFFFFFFF, mx0, 2));
        mx1 = fmaxf(mx1, __shfl_xor_sync(0xFFFFFFFF, mx1, 1));
        mx1 = fmaxf(mx1, __shfl_xor_sync(0xFFFFFFFF, mx1, 2));
        float s0 = 0.f, s1 = 0.f;
#pragma unroll
        for (int nf = 0; nf < 16; nf++) {
            e[nf][0] = __expf(e[nf][0] - mx0);
            e[nf][1] = __expf(e[nf][1] - mx0);
            e[nf][2] = __expf(e[nf][2] - mx1);
            e[nf][3] = __expf(e[nf][3] - mx1);
            s0 += e[nf][0] + e[nf][1];
            s1 += e[nf][2] + e[nf][3];
        }
        s0 += __shfl_xor_sync(0xFFFFFFFF, s0, 1);
        s0 += __shfl_xor_sync(0xFFFFFFFF, s0, 2);
        s1 += __shfl_xor_sync(0xFFFFFFFF, s1, 1);
        s1 += __shfl_xor_sync(0xFFFFFFFF, s1, 2);
        if (tg == 0) {
            ss[w0 + r]     = 1.0f / s0;
            ss[w0 + r + 8] = 1.0f / s1;
        }
#pragma unroll
        for (int nf = 0; nf < 16; nf += 2) {
            uint32_t addr = sb + OP + (uint32_t)((w0 + (msel & 1)*8 + l7)*272
                          + (nf + (msel >> 1))*16);
            stsm4(addr,
                  pack_h2(e[nf][0],   e[nf][1]),
                  pack_h2(e[nf][2],   e[nf][3]),
                  pack_h2(e[nf+1][0], e[nf+1][1]),
                  pack_h2(e[nf+1][2], e[nf+1][3]));
        }
    }
    CP_WAIT0();          // v landed
    __syncthreads();

    // ---- phase 3: O[c][w] = (V P^T) * ss[w] single-product HMMA ----
    {
        int wm = wid >> 2, wn = wid & 3;      // 2(m=c) x 4(n=w)
        int r = lane >> 2, tg = lane & 3;
        int lr = lane & 7, grp = lane >> 3;

        float acc[2][4][4];
#pragma unroll
        for (int mf=0; mf<2; mf++)
#pragma unroll
            for (int nf=0; nf<4; nf++)
#pragma unroll
                for (int j=0; j<4; j++) acc[mf][nf][j] = 0.f;

#pragma unroll
        for (int s = 0; s < 8; s++) {
            uint32_t bp[4][2];
#pragma unroll
            for (int nf = 0; nf < 4; nf += 2) {
                uint32_t ab = sb + OP + (uint32_t)((wn*32 + nf*8 + (msel >> 1)*8 + l7)*272
                             + (s*8 + (msel & 1)*4)*4);
                uint32_t t4[4];
                ldsm4(t4, ab);
                bp[nf][0]=t4[0]; bp[nf][1]=t4[1]; bp[nf+1][0]=t4[2]; bp[nf+1][1]=t4[3];
            }
#pragma unroll
            for (int mf = 0; mf < 2; mf++) {
                uint32_t aa = sb + OVH + (uint32_t)((wm*32 + mf*16 + lr + (grp&1)*8)*68 + s*8 + (grp>>1)*4)*4;
                uint32_t ah[4];
                ldsm4(ah, aa);
#pragma unroll
                for (int nf=0; nf<4; nf++)
                    mma_f16(acc[mf][nf], ah, bp[nf]);
            }
        }

        // ---- scale + stage o-tile (64 ch x 128 w, fp16) into smem via stmatrix ----
        __syncthreads();   // all warps done reading VH region
#pragma unroll
        for (int mf = 0; mf < 2; mf++) {
#pragma unroll
            for (int nf = 0; nf < 4; nf += 2) {
                int wc0 = wn*32 + nf*8 + 2*tg;
                int wc1 = wc0 + 8;
                float s00 = ss[wc0], s01 = ss[wc0+1];
                float s10 = ss[wc1], s11 = ss[wc1+1];
                uint32_t r0 = pack_h2(acc[mf][nf][0]*s00,   acc[mf][nf][1]*s01);
                uint32_t r1 = pack_h2(acc[mf][nf][2]*s00,   acc[mf][nf][3]*s01);
                uint32_t r2 = pack_h2(acc[mf][nf+1][0]*s10, acc[mf][nf+1][1]*s11);
                uint32_t r3 = pack_h2(acc[mf][nf+1][2]*s10, acc[mf][nf+1][3]*s11);
                uint32_t addr = sb + (uint32_t)((wm*32 + mf*16 + (msel & 1)*8 + l7)*272
                              + (wn*32 + nf*8 + (msel >> 1)*8)*2);
                stsm4(addr, r0, r1, r2, r3);
            }
        }
        __syncthreads();
    }

    // ---- cooperative coalesced write-out ----
    {
        size_t obase = ((size_t)(b*CC + hd*64))*HW + (size_t)row*WW;
        if (mode == 0) {
#pragma unroll
            for (int it = 0; it < 4; it++) {
                int j = it*256 + tid;
                int ch = j >> 4, wg = j & 15;
                uint4 v = *(uint4*)(smc + ch*272 + wg*16);
                *(uint4*)&outH[obase + (size_t)ch*HW + wg*8] = v;
            }
        } else {
            float g = gamma[0];
#pragma unroll
            for (int it = 0; it < 4; it++) {
                int j = it*256 + tid;
                int ch = j >> 4, wg = j & 15;
                size_t gi = obase + (size_t)ch*HW + wg*8;
                uint4 ovu = *(uint4*)(smc + ch*272 + wg*16);
                uint4 ohu = *(const uint4*)&scrH[gi];
                float4 xa = *(const float4*)&x[gi];
                float4 xb = *(const float4*)&x[gi + 4];
                __half2* ov2 = (__half2*)&ovu;
                __half2* oh2 = (__half2*)&ohu;
                float2 v0 = __half22float2(ov2[0]), h0 = __half22float2(oh2[0]);
                float2 v1 = __half22float2(ov2[1]), h1 = __half22float2(oh2[1]);
                float2 v2 = __half22float2(ov2[2]), h2 = __half22float2(oh2[2]);
                float2 v3 = __half22float2(ov2[3]), h3 = __half22float2(oh2[3]);
                float4 oa, ob;
                oa.x = g*(v0.x + h0.x) + xa.x;
                oa.y = g*(v0.y + h0.y) + xa.y;
                oa.z = g*(v1.x + h1.x) + xa.z;
                oa.w = g*(v1.y + h1.y) + xa.w;
                ob.x = g*(v2.x + h2.x) + xb.x;
                ob.y = g*(v2.y + h2.y) + xb.y;
                ob.z = g*(v3.x + h3.x) + xb.z;
                ob.w = g*(v3.y + h3.y) + xb.w;
                *(float4*)&outF[gi]     = oa;
                *(float4*)&outF[gi + 4] = ob;
            }
        }
    }
}

// ---------------- host ----------------
extern "C" void kernel_launch(void* const* d_in, const int* in_sizes, int n_in,
                              void* d_out, int out_size)
{
    const float* x     = (const float*)d_in[0];
    const float* Wq    = (const float*)d_in[1];
    const float* bq    = (const float*)d_in[2];
    const float* Wk    = (const float*)d_in[3];
    const float* bk    = (const float*)d_in[4];
    const float* Wv    = (const float*)d_in[5];
    const float* bv    = (const float*)d_in[6];
    const float* gamma = (const float*)d_in[7];
    float* out = (float*)d_out;

    __half *poh, *pqh, *pkh, *pvh, *pqTh, *pkTh, *pvTh;
    cudaGetSymbolAddress((void**)&poh,  g_ohh);
    cudaGetSymbolAddress((void**)&pqh,  g_qhi);
    cudaGetSymbolAddress((void**)&pkh,  g_khi);
    cudaGetSymbolAddress((void**)&pvh,  g_vhi);
    cudaGetSymbolAddress((void**)&pqTh, g_qThi);
    cudaGetSymbolAddress((void**)&pkTh, g_kThi);
    cudaGetSymbolAddress((void**)&pvTh, g_vThi);

    // fused xconv (8192 blocks) + weight prep (384 blocks)
    xconv_prep_kernel<<<8192 + 384, 256>>>(x, Wq, bq, Wk, bk, Wv, bv);

    cudaFuncSetAttribute(qkv_mma_kernel, cudaFuncAttributeMaxDynamicSharedMemorySize, PROJ_SMEM);
    qkv_mma_kernel<<<dim3(MROWS/128, P/128, BB), 256, PROJ_SMEM>>>();

    cudaFuncSetAttribute(attn_kernel, cudaFuncAttributeMaxDynamicSharedMemorySize, ATT_SMEM);
    // mode 0: 2048 attention blocks + 1280 transpose blocks co-scheduled
    attn_kernel<<<2048 + BB*CQ*2 + BB*CC, 256, ATT_SMEM>>>(pqh, pkh, pvh,
                                                    nullptr, nullptr, gamma, nullptr, poh, 0);
    // mode 1: vertical pass on transposed arrays + fused epilogue
    attn_kernel<<<2048, 256, ATT_SMEM>>>(pqTh, pkTh, pvTh,
                                                    poh, x, gamma, out, nullptr, 1);
}